// round 1
// baseline (speedup 1.0000x reference)
#include <cuda_runtime.h>
#include <cuda_bf16.h>
#include <math.h>

// Problem constants
#define Bb 4
#define Ss 2048
#define Dd 1024
#define Hh 8
#define HD 128
#define BH (Bb*Hh)          // 32 head-slices
#define MROWS (Bb*Ss)       // 8192

// Scratch (device globals: allocation-free rule)
__device__ float g_Q[(size_t)MROWS * Dd];
__device__ float g_K[(size_t)MROWS * Dd];
__device__ float g_V[(size_t)MROWS * Dd];
__device__ float g_X[(size_t)MROWS * Dd];
__device__ float g_S[(size_t)BH * Ss * Ss];   // 512 MB scores

// ---------------------------------------------------------------------------
// Tiled SGEMM: C[M,N] = A[M,K] @ op(B) + bias, op = identity (NN) or
// B given as [N,K] row-major (NT). blockIdx.z batches with given strides.
// BM=BN=128, BK=16, 256 threads, 8x8 per-thread tile.
// ---------------------------------------------------------------------------
#define BM 128
#define BN 128
#define BK 16
#define TM 8
#define TN 8

template<bool TB>
__global__ __launch_bounds__(256)
void gemm_kernel(const float* __restrict__ A, const float* __restrict__ B,
                 const float* __restrict__ bias, float* __restrict__ C,
                 int M, int N, int K,
                 long sA, long sB, long sC)
{
    A += (long)blockIdx.z * sA;
    B += (long)blockIdx.z * sB;
    C += (long)blockIdx.z * sC;

    __shared__ float As[BK][BM];
    __shared__ float Bs[BK][BN + 4];

    const int tid = threadIdx.x;
    const int tr = tid >> 4;        // 0..15
    const int tc = tid & 15;        // 0..15
    const int rowBase = blockIdx.y * BM;
    const int colBase = blockIdx.x * BN;

    float acc[TM][TN];
    #pragma unroll
    for (int i = 0; i < TM; i++)
        #pragma unroll
        for (int j = 0; j < TN; j++)
            acc[i][j] = 0.0f;

    for (int k0 = 0; k0 < K; k0 += BK) {
        // Load A tile 128x16 (row-major A[M,K]); store transposed As[k][m]
        #pragma unroll
        for (int i = 0; i < 8; i++) {
            int idx = tid + i * 256;
            int r = idx >> 4;        // 0..127
            int c = idx & 15;        // 0..15
            As[c][r] = A[(long)(rowBase + r) * K + (k0 + c)];
        }
        // Load B tile 16x128
        #pragma unroll
        for (int i = 0; i < 8; i++) {
            int idx = tid + i * 256;
            if (!TB) {
                int r = idx >> 7;    // 0..15
                int c = idx & 127;   // 0..127
                Bs[r][c] = B[(long)(k0 + r) * N + (colBase + c)];
            } else {
                int n  = idx >> 4;   // 0..127
                int kk = idx & 15;   // 0..15
                Bs[kk][n] = B[(long)(colBase + n) * K + (k0 + kk)];
            }
        }
        __syncthreads();

        #pragma unroll
        for (int kk = 0; kk < BK; kk++) {
            float a[TM], b[TN];
            #pragma unroll
            for (int i = 0; i < TM; i++) a[i] = As[kk][tr * TM + i];
            #pragma unroll
            for (int j = 0; j < TN; j++) b[j] = Bs[kk][tc * TN + j];
            #pragma unroll
            for (int i = 0; i < TM; i++)
                #pragma unroll
                for (int j = 0; j < TN; j++)
                    acc[i][j] = fmaf(a[i], b[j], acc[i][j]);
        }
        __syncthreads();
    }

    #pragma unroll
    for (int i = 0; i < TM; i++) {
        int r = rowBase + tr * TM + i;
        #pragma unroll
        for (int j = 0; j < TN; j++) {
            int c = colBase + tc * TN + j;
            float v = acc[i][j];
            if (bias) v += bias[c];
            C[(long)r * N + c] = v;
        }
    }
}

// ---------------------------------------------------------------------------
// Column softmax over the QUERY axis: for each head [S,S] matrix, softmax
// along rows (axis 0) independently per column. One thread per column,
// consecutive threads -> consecutive columns (coalesced row reads).
// ---------------------------------------------------------------------------
__global__ __launch_bounds__(256)
void softmax_q_kernel(float* __restrict__ S)
{
    const long base = (long)blockIdx.z * Ss * Ss;
    const int col = blockIdx.x * blockDim.x + threadIdx.x;

    float m = -1e30f, s = 0.0f;
    for (int r = 0; r < Ss; r++) {
        float x = S[base + (long)r * Ss + col];
        float nm = fmaxf(m, x);
        s = s * __expf(m - nm) + __expf(x - nm);
        m = nm;
    }
    const float inv = 1.0f / s;
    for (int r = 0; r < Ss; r++) {
        long idx = base + (long)r * Ss + col;
        S[idx] = __expf(S[idx] - m) * inv;
    }
}

// ---------------------------------------------------------------------------
// Launch
// ---------------------------------------------------------------------------
extern "C" void kernel_launch(void* const* d_in, const int* in_sizes, int n_in,
                              void* d_out, int out_size)
{
    const float* query = (const float*)d_in[0];
    const float* key   = (const float*)d_in[1];
    const float* value = (const float*)d_in[2];
    const float* Wq    = (const float*)d_in[3];
    const float* bq    = (const float*)d_in[4];
    const float* Wk    = (const float*)d_in[5];
    const float* bk    = (const float*)d_in[6];
    const float* Wv    = (const float*)d_in[7];
    const float* bv    = (const float*)d_in[8];
    const float* Wo    = (const float*)d_in[9];
    const float* bo    = (const float*)d_in[10];
    float* out = (float*)d_out;

    float *Qp, *Kp, *Vp, *Xp, *Sp;
    cudaGetSymbolAddress((void**)&Qp, g_Q);
    cudaGetSymbolAddress((void**)&Kp, g_K);
    cudaGetSymbolAddress((void**)&Vp, g_V);
    cudaGetSymbolAddress((void**)&Xp, g_X);
    cudaGetSymbolAddress((void**)&Sp, g_S);

    dim3 blk(256);

    // 1) QKV projections: [8192,1024] @ [1024,1024] + bias
    {
        dim3 grid(Dd / BN, MROWS / BM, 1);
        gemm_kernel<false><<<grid, blk>>>(query, Wq, bq, Qp, MROWS, Dd, Dd, 0, 0, 0);
        gemm_kernel<false><<<grid, blk>>>(key,   Wk, bk, Kp, MROWS, Dd, Dd, 0, 0, 0);
        gemm_kernel<false><<<grid, blk>>>(value, Wv, bv, Vp, MROWS, Dd, Dd, 0, 0, 0);
    }

    // 2) Scores per head: S[q,k] = Q_h[q,:] . K_h[k,:]   (NT GEMM, 32 heads)
    {
        dim3 grid(Ss / BN, Ss / BM, BH);
        gemm_kernel<true><<<grid, blk>>>(Qp, Kp, nullptr, Sp,
                                         Ss, Ss, HD,
                                         (long)Ss * HD, (long)Ss * HD, (long)Ss * Ss);
    }

    // 3) Softmax over query axis (column-wise per head)
    {
        dim3 grid(Ss / 256, 1, BH);
        softmax_q_kernel<<<grid, blk>>>(Sp);
    }

    // 4) PV per head: X_h[2048,128] = P_h[2048,2048] @ V_h[2048,128]
    {
        dim3 grid(HD / BN, Ss / BM, BH);   // HD/BN = 1
        gemm_kernel<false><<<grid, blk>>>(Sp, Vp, nullptr, Xp,
                                          Ss, HD, Ss,
                                          (long)Ss * Ss, (long)Ss * HD, (long)Ss * HD);
    }

    // 5) Output projection: [8192,1024] @ Wo + bo -> out
    {
        dim3 grid(Dd / BN, MROWS / BM, 1);
        gemm_kernel<false><<<grid, blk>>>(Xp, Wo, bo, out, MROWS, Dd, Dd, 0, 0, 0);
    }
}

// round 3
// speedup vs baseline: 2.1182x; 2.1182x over previous
#include <cuda_runtime.h>
#include <cuda_bf16.h>
#include <cstdint>
#include <math.h>

// Problem constants
#define Bb 4
#define Ss 2048
#define Dd 1024
#define Hh 8
#define HD 128
#define BH (Bb*Hh)            // 32 head-slices
#define MROWS (Bb*Ss)         // 8192
#define NELEM ((size_t)MROWS * Dd)      // 8M
#define WELEM ((size_t)Dd * Dd)         // 1M
#define SELEM ((size_t)BH * Ss * Ss)    // 128M

typedef __nv_bfloat16 bf16;
typedef __nv_bfloat162 bf162;

// ---------------------------------------------------------------------------
// Device scratch (allocation-free rule: __device__ globals)
// ---------------------------------------------------------------------------
__device__ __align__(256) bf16 g_iq_h[NELEM], g_iq_l[NELEM];
__device__ __align__(256) bf16 g_ik_h[NELEM], g_ik_l[NELEM];
__device__ __align__(256) bf16 g_iv_h[NELEM], g_iv_l[NELEM];
__device__ __align__(256) bf16 g_wq_h[WELEM], g_wq_l[WELEM];
__device__ __align__(256) bf16 g_wk_h[WELEM], g_wk_l[WELEM];
__device__ __align__(256) bf16 g_wv_h[WELEM], g_wv_l[WELEM];
__device__ __align__(256) bf16 g_wo_h[WELEM], g_wo_l[WELEM];
__device__ __align__(256) bf16 g_Q_h[NELEM],  g_Q_l[NELEM];
__device__ __align__(256) bf16 g_K_h[NELEM],  g_K_l[NELEM];
__device__ __align__(256) bf16 g_V_h[NELEM],  g_V_l[NELEM];
__device__ __align__(256) bf16 g_Vo_h[NELEM], g_Vo_l[NELEM];
__device__ __align__(256) bf16 g_X_h[NELEM],  g_X_l[NELEM];
__device__ __align__(256) bf16 g_E_h[SELEM], g_E_l[SELEM];  // scores -> exp planes
__device__ __align__(256) float g_Mx[(size_t)BH * Ss];
__device__ __align__(256) float g_Z [(size_t)BH * Ss];

// ---------------------------------------------------------------------------
// PTX helpers
// ---------------------------------------------------------------------------
__device__ __forceinline__ void cpa(uint32_t dst, const void* src) {
    asm volatile("cp.async.cg.shared.global [%0], [%1], 16;\n" :: "r"(dst), "l"(src));
}
__device__ __forceinline__ void ldsm4(uint32_t& r0, uint32_t& r1, uint32_t& r2, uint32_t& r3, uint32_t a) {
    asm volatile("ldmatrix.sync.aligned.m8n8.x4.shared.b16 {%0,%1,%2,%3}, [%4];"
                 : "=r"(r0), "=r"(r1), "=r"(r2), "=r"(r3) : "r"(a));
}
__device__ __forceinline__ void ldsm4t(uint32_t& r0, uint32_t& r1, uint32_t& r2, uint32_t& r3, uint32_t a) {
    asm volatile("ldmatrix.sync.aligned.m8n8.x4.trans.shared.b16 {%0,%1,%2,%3}, [%4];"
                 : "=r"(r0), "=r"(r1), "=r"(r2), "=r"(r3) : "r"(a));
}
__device__ __forceinline__ void mma16816(float* c, const uint32_t* a, const uint32_t* b) {
    asm volatile("mma.sync.aligned.m16n8k16.row.col.f32.bf16.bf16.f32 "
                 "{%0,%1,%2,%3},{%4,%5,%6,%7},{%8,%9},{%0,%1,%2,%3};"
                 : "+f"(c[0]), "+f"(c[1]), "+f"(c[2]), "+f"(c[3])
                 : "r"(a[0]), "r"(a[1]), "r"(a[2]), "r"(a[3]), "r"(b[0]), "r"(b[1]));
}
__device__ __forceinline__ uint32_t pack2(bf16 a, bf16 b) {
    bf162 t(a, b);
    return *reinterpret_cast<uint32_t*>(&t);
}
__device__ __forceinline__ void split2(float v0, float v1, uint32_t& hi, uint32_t& lo) {
    bf16 h0 = __float2bfloat16_rn(v0);
    bf16 h1 = __float2bfloat16_rn(v1);
    bf16 l0 = __float2bfloat16_rn(v0 - __bfloat162float(h0));
    bf16 l1 = __float2bfloat16_rn(v1 - __bfloat162float(h1));
    hi = pack2(h0, h1);
    lo = pack2(l0, l1);
}

// ---------------------------------------------------------------------------
// Split fp32 -> bf16 hi/lo planes
// ---------------------------------------------------------------------------
__global__ __launch_bounds__(256) void split_f32(const float4* __restrict__ x,
                                                 uint2* __restrict__ hi, uint2* __restrict__ lo, int n4)
{
    int i = blockIdx.x * 256 + threadIdx.x;
    if (i >= n4) return;
    float4 v = x[i];
    uint32_t h01, l01, h23, l23;
    split2(v.x, v.y, h01, l01);
    split2(v.z, v.w, h23, l23);
    hi[i] = make_uint2(h01, h23);
    lo[i] = make_uint2(l01, l23);
}

// ---------------------------------------------------------------------------
// bf16x3 MMA GEMM.  BM=BN=128, BK=64, 256 threads (8 warps 2x4),
// warp tile 64x32.  BLAY: 0 = B global [k][n], 1 = B global [n][k].
// EPI: 0 = fp32 out, 1 = hi/lo bf16 plane out.
// ---------------------------------------------------------------------------
#define STAGE_BYTES 65536
#define SMEM_BYTES  131072

template<int BLAY, int EPI>
__global__ __launch_bounds__(256) void mma_gemm(
    const bf16* __restrict__ Ah, const bf16* __restrict__ Al,
    const bf16* __restrict__ Bh, const bf16* __restrict__ Bl,
    const float* __restrict__ bias,
    float* __restrict__ Cf, bf16* __restrict__ Ch, bf16* __restrict__ Cl,
    int K, int lda, int ldb, int ldc,
    size_t sA, size_t sB, size_t sC)
{
    extern __shared__ __align__(16) char smem[];
    const uint32_t sbase = (uint32_t)__cvta_generic_to_shared(smem);
    const int tid = threadIdx.x, lane = tid & 31, wid = tid >> 5;
    const int wm = wid >> 2, wn = wid & 3;
    const int rowBase = blockIdx.y * 128, colBase = blockIdx.x * 128;
    const bf16* Agh = Ah + (size_t)blockIdx.z * sA;
    const bf16* Agl = Al + (size_t)blockIdx.z * sA;
    const bf16* Bgh = Bh + (size_t)blockIdx.z * sB;
    const bf16* Bgl = Bl + (size_t)blockIdx.z * sB;
    const size_t zC = (size_t)blockIdx.z * sC;

    float acc[4][4][4] = {};

    auto copyStage = [&](int st, int k0) {
        uint32_t aOff = sbase + st * STAGE_BYTES;
        #pragma unroll
        for (int t = 0; t < 4; t++) {
            int idx = tid + t * 256;
            int r = idx >> 3, c = idx & 7;
            int sw = c ^ (r & 7);
            uint32_t d = aOff + r * 128 + sw * 16;
            size_t g = (size_t)(rowBase + r) * lda + (k0 + c * 8);
            cpa(d,         Agh + g);
            cpa(d + 16384, Agl + g);
        }
        uint32_t bOff = aOff + 32768;
        #pragma unroll
        for (int t = 0; t < 4; t++) {
            int idx = tid + t * 256;
            if (BLAY == 0) {
                int r = idx >> 4, c = idx & 15;
                int sw = c ^ (r & 7);
                uint32_t d = bOff + r * 256 + sw * 16;
                size_t g = (size_t)(k0 + r) * ldb + (colBase + c * 8);
                cpa(d,         Bgh + g);
                cpa(d + 16384, Bgl + g);
            } else {
                int r = idx >> 3, c = idx & 7;
                int sw = c ^ (r & 7);
                uint32_t d = bOff + r * 128 + sw * 16;
                size_t g = (size_t)(colBase + r) * ldb + (k0 + c * 8);
                cpa(d,         Bgh + g);
                cpa(d + 16384, Bgl + g);
            }
        }
    };

    auto computeStage = [&](int st) {
        uint32_t aHi = sbase + st * STAGE_BYTES;
        uint32_t aLo = aHi + 16384;
        uint32_t bHi = aHi + 32768;
        uint32_t bLo = bHi + 16384;
        #pragma unroll
        for (int ks = 0; ks < 4; ks++) {
            uint32_t af[2][4][4];
            uint32_t bfr[2][4][2];
            #pragma unroll
            for (int mt = 0; mt < 4; mt++) {
                int row = wm * 64 + mt * 16 + (lane & 15);
                int ch = ks * 2 + (lane >> 4);
                uint32_t ad = (uint32_t)(row * 128 + ((ch ^ (row & 7)) * 16));
                ldsm4(af[0][mt][0], af[0][mt][1], af[0][mt][2], af[0][mt][3], aHi + ad);
                ldsm4(af[1][mt][0], af[1][mt][1], af[1][mt][2], af[1][mt][3], aLo + ad);
            }
            #pragma unroll
            for (int i = 0; i < 2; i++) {
                if (BLAY == 0) {
                    int row = ks * 16 + ((lane >> 3) & 1) * 8 + (lane & 7);
                    int ch = wn * 4 + i * 2 + (lane >> 4);
                    uint32_t bd = (uint32_t)(row * 256 + ((ch ^ (row & 7)) * 16));
                    uint32_t r0, r1, r2, r3;
                    ldsm4t(r0, r1, r2, r3, bHi + bd);
                    bfr[0][2*i][0] = r0; bfr[0][2*i][1] = r1; bfr[0][2*i+1][0] = r2; bfr[0][2*i+1][1] = r3;
                    ldsm4t(r0, r1, r2, r3, bLo + bd);
                    bfr[1][2*i][0] = r0; bfr[1][2*i][1] = r1; bfr[1][2*i+1][0] = r2; bfr[1][2*i+1][1] = r3;
                } else {
                    int row = wn * 32 + i * 16 + ((lane >> 4) << 3) + (lane & 7);
                    int ch = ks * 2 + ((lane >> 3) & 1);
                    uint32_t bd = (uint32_t)(row * 128 + ((ch ^ (row & 7)) * 16));
                    uint32_t r0, r1, r2, r3;
                    ldsm4(r0, r1, r2, r3, bHi + bd);
                    bfr[0][2*i][0] = r0; bfr[0][2*i][1] = r1; bfr[0][2*i+1][0] = r2; bfr[0][2*i+1][1] = r3;
                    ldsm4(r0, r1, r2, r3, bLo + bd);
                    bfr[1][2*i][0] = r0; bfr[1][2*i][1] = r1; bfr[1][2*i+1][0] = r2; bfr[1][2*i+1][1] = r3;
                }
            }
            #pragma unroll
            for (int mt = 0; mt < 4; mt++)
                #pragma unroll
                for (int nt = 0; nt < 4; nt++) {
                    mma16816(acc[mt][nt], af[0][mt], bfr[0][nt]);
                    mma16816(acc[mt][nt], af[0][mt], bfr[1][nt]);
                    mma16816(acc[mt][nt], af[1][mt], bfr[0][nt]);
                }
        }
    };

    const int nk = K >> 6;
    copyStage(0, 0);
    asm volatile("cp.async.commit_group;" ::: "memory");
    for (int kt = 0; kt < nk; kt++) {
        if (kt + 1 < nk) {
            copyStage((kt + 1) & 1, (kt + 1) * 64);
            asm volatile("cp.async.commit_group;" ::: "memory");
            asm volatile("cp.async.wait_group 1;" ::: "memory");
        } else {
            asm volatile("cp.async.wait_group 0;" ::: "memory");
        }
        __syncthreads();
        computeStage(kt & 1);
        __syncthreads();
    }

    #pragma unroll
    for (int mt = 0; mt < 4; mt++) {
        #pragma unroll
        for (int nt = 0; nt < 4; nt++) {
            int r = rowBase + wm * 64 + mt * 16 + (lane >> 2);
            int c = colBase + wn * 32 + nt * 8 + (lane & 3) * 2;
            float b0 = 0.f, b1 = 0.f;
            if (bias) { b0 = bias[c]; b1 = bias[c + 1]; }
            float v00 = acc[mt][nt][0] + b0, v01 = acc[mt][nt][1] + b1;
            float v10 = acc[mt][nt][2] + b0, v11 = acc[mt][nt][3] + b1;
            if (EPI == 0) {
                *reinterpret_cast<float2*>(Cf + zC + (size_t)r * ldc + c)       = make_float2(v00, v01);
                *reinterpret_cast<float2*>(Cf + zC + (size_t)(r + 8) * ldc + c) = make_float2(v10, v11);
            } else {
                uint32_t h, l;
                split2(v00, v01, h, l);
                *reinterpret_cast<uint32_t*>(Ch + zC + (size_t)r * ldc + c) = h;
                *reinterpret_cast<uint32_t*>(Cl + zC + (size_t)r * ldc + c) = l;
                split2(v10, v11, h, l);
                *reinterpret_cast<uint32_t*>(Ch + zC + (size_t)(r + 8) * ldc + c) = h;
                *reinterpret_cast<uint32_t*>(Cl + zC + (size_t)(r + 8) * ldc + c) = l;
            }
        }
    }
}

// ---------------------------------------------------------------------------
// Softmax over query axis on bf16 hi/lo score planes:
//  colmax:  M[k] = max_q S_hi[q,k]   (hi plane only; softmax invariant to m)
//  expsum:  E = exp(S_hi+S_lo - M) in place (hi/lo planes), Z[k] = sum_q E
//  vscale:  V'[k,d] = V[k,d] / Z[k];  then X = E @ V'.
// ---------------------------------------------------------------------------
__global__ __launch_bounds__(256) void colmax_kernel(const bf16* __restrict__ Eh, float* __restrict__ Mx)
{
    const size_t base = (size_t)blockIdx.z * Ss * Ss;
    const int c2 = blockIdx.x * 256 + threadIdx.x;   // bf162 column index
    const bf162* col = reinterpret_cast<const bf162*>(Eh + base) + c2;
    float m0 = -1e30f, m1 = -1e30f;
    #pragma unroll 4
    for (int r = 0; r < Ss; r += 2) {
        bf162 a = col[(size_t)r * (Ss / 2)];
        bf162 b = col[(size_t)(r + 1) * (Ss / 2)];
        m0 = fmaxf(m0, fmaxf(__bfloat162float(a.x), __bfloat162float(b.x)));
        m1 = fmaxf(m1, fmaxf(__bfloat162float(a.y), __bfloat162float(b.y)));
    }
    reinterpret_cast<float2*>(Mx + (size_t)blockIdx.z * Ss)[c2] = make_float2(m0, m1);
}

__global__ __launch_bounds__(256) void expsum_kernel(bf16* __restrict__ Eh, bf16* __restrict__ El,
                                                     const float* __restrict__ Mx,
                                                     float* __restrict__ Z)
{
    const size_t base = (size_t)blockIdx.z * Ss * Ss;
    const int c2 = blockIdx.x * 256 + threadIdx.x;
    bf162* EH = reinterpret_cast<bf162*>(Eh + base) + c2;
    bf162* EL = reinterpret_cast<bf162*>(El + base) + c2;
    float2 m = reinterpret_cast<const float2*>(Mx + (size_t)blockIdx.z * Ss)[c2];
    float z0 = 0.f, z1 = 0.f;
    #pragma unroll 2
    for (int r = 0; r < Ss; r++) {
        size_t off = (size_t)r * (Ss / 2);
        bf162 h = EH[off];
        bf162 l = EL[off];
        float s0 = __bfloat162float(h.x) + __bfloat162float(l.x);
        float s1 = __bfloat162float(h.y) + __bfloat162float(l.y);
        float e0 = __expf(s0 - m.x);
        float e1 = __expf(s1 - m.y);
        z0 += e0; z1 += e1;
        uint32_t hh, ll;
        split2(e0, e1, hh, ll);
        *reinterpret_cast<uint32_t*>(&EH[off]) = hh;
        *reinterpret_cast<uint32_t*>(&EL[off]) = ll;
    }
    reinterpret_cast<float2*>(Z + (size_t)blockIdx.z * Ss)[c2] = make_float2(z0, z1);
}

__global__ __launch_bounds__(256) void vscale_kernel(const bf16* __restrict__ Vh, const bf16* __restrict__ Vl,
                                                     const float* __restrict__ Z,
                                                     bf16* __restrict__ Voh, bf16* __restrict__ Vol)
{
    size_t i = (size_t)blockIdx.x * 256 + threadIdx.x;   // over 8M elements
    size_t kz = i >> 7;                                   // z*Ss + k  (HD = 128)
    float inv = __fdividef(1.0f, Z[kz]);
    float v = (__bfloat162float(Vh[i]) + __bfloat162float(Vl[i])) * inv;
    bf16 h = __float2bfloat16_rn(v);
    bf16 l = __float2bfloat16_rn(v - __bfloat162float(h));
    Voh[i] = h;
    Vol[i] = l;
}

// ---------------------------------------------------------------------------
// Launch
// ---------------------------------------------------------------------------
extern "C" void kernel_launch(void* const* d_in, const int* in_sizes, int n_in,
                              void* d_out, int out_size)
{
    const float* query = (const float*)d_in[0];
    const float* key   = (const float*)d_in[1];
    const float* value = (const float*)d_in[2];
    const float* Wq    = (const float*)d_in[3];
    const float* bq    = (const float*)d_in[4];
    const float* Wk    = (const float*)d_in[5];
    const float* bk    = (const float*)d_in[6];
    const float* Wv    = (const float*)d_in[7];
    const float* bv    = (const float*)d_in[8];
    const float* Wo    = (const float*)d_in[9];
    const float* bo    = (const float*)d_in[10];
    float* out = (float*)d_out;

    #define SYM(p, s) do { void* tmp_; cudaGetSymbolAddress(&tmp_, s); p = (decltype(p))tmp_; } while (0)
    bf16 *iqh, *iql, *ikh, *ikl, *ivh, *ivl;
    bf16 *wqh, *wql, *wkh, *wkl, *wvh, *wvl, *woh, *wol;
    bf16 *Qh, *Ql, *Kh, *Kl, *Vh, *Vl, *Voh, *Vol, *Xh, *Xl, *Eh, *El;
    float *Mxp, *Zp;
    SYM(iqh, g_iq_h); SYM(iql, g_iq_l); SYM(ikh, g_ik_h); SYM(ikl, g_ik_l);
    SYM(ivh, g_iv_h); SYM(ivl, g_iv_l);
    SYM(wqh, g_wq_h); SYM(wql, g_wq_l); SYM(wkh, g_wk_h); SYM(wkl, g_wk_l);
    SYM(wvh, g_wv_h); SYM(wvl, g_wv_l); SYM(woh, g_wo_h); SYM(wol, g_wo_l);
    SYM(Qh, g_Q_h); SYM(Ql, g_Q_l); SYM(Kh, g_K_h); SYM(Kl, g_K_l);
    SYM(Vh, g_V_h); SYM(Vl, g_V_l); SYM(Voh, g_Vo_h); SYM(Vol, g_Vo_l);
    SYM(Xh, g_X_h); SYM(Xl, g_X_l); SYM(Eh, g_E_h); SYM(El, g_E_l);
    SYM(Mxp, g_Mx); SYM(Zp, g_Z);
    #undef SYM

    cudaFuncSetAttribute(mma_gemm<0, 0>, cudaFuncAttributeMaxDynamicSharedMemorySize, SMEM_BYTES);
    cudaFuncSetAttribute(mma_gemm<0, 1>, cudaFuncAttributeMaxDynamicSharedMemorySize, SMEM_BYTES);
    cudaFuncSetAttribute(mma_gemm<1, 1>, cudaFuncAttributeMaxDynamicSharedMemorySize, SMEM_BYTES);

    // 1) Split fp32 inputs/weights into bf16 hi/lo planes
    {
        int n4i = (int)(NELEM / 4), n4w = (int)(WELEM / 4);
        split_f32<<<n4i / 256, 256>>>((const float4*)query, (uint2*)iqh, (uint2*)iql, n4i);
        split_f32<<<n4i / 256, 256>>>((const float4*)key,   (uint2*)ikh, (uint2*)ikl, n4i);
        split_f32<<<n4i / 256, 256>>>((const float4*)value, (uint2*)ivh, (uint2*)ivl, n4i);
        split_f32<<<n4w / 256, 256>>>((const float4*)Wq, (uint2*)wqh, (uint2*)wql, n4w);
        split_f32<<<n4w / 256, 256>>>((const float4*)Wk, (uint2*)wkh, (uint2*)wkl, n4w);
        split_f32<<<n4w / 256, 256>>>((const float4*)Wv, (uint2*)wvh, (uint2*)wvl, n4w);
        split_f32<<<n4w / 256, 256>>>((const float4*)Wo, (uint2*)woh, (uint2*)wol, n4w);
    }

    // 2) QKV projections: [8192,1024] @ [1024,1024] + bias -> hi/lo planes
    {
        dim3 grid(Dd / 128, MROWS / 128, 1);
        mma_gemm<0, 1><<<grid, 256, SMEM_BYTES>>>(iqh, iql, wqh, wql, bq, nullptr, Qh, Ql,
                                                  Dd, Dd, Dd, Dd, 0, 0, 0);
        mma_gemm<0, 1><<<grid, 256, SMEM_BYTES>>>(ikh, ikl, wkh, wkl, bk, nullptr, Kh, Kl,
                                                  Dd, Dd, Dd, Dd, 0, 0, 0);
        mma_gemm<0, 1><<<grid, 256, SMEM_BYTES>>>(ivh, ivl, wvh, wvl, bv, nullptr, Vh, Vl,
                                                  Dd, Dd, Dd, Dd, 0, 0, 0);
    }

    // 3) Scores per head: S = Q_h @ K_h^T -> hi/lo bf16 planes in E buffers
    {
        dim3 grid(Ss / 128, Ss / 128, BH);
        mma_gemm<1, 1><<<grid, 256, SMEM_BYTES>>>(Qh, Ql, Kh, Kl, nullptr, nullptr, Eh, El,
                                                  HD, HD, HD, Ss,
                                                  (size_t)Ss * HD, (size_t)Ss * HD, (size_t)Ss * Ss);
    }

    // 4) Softmax over query axis (normalization folded into V)
    {
        dim3 grid(Ss / 2 / 256, 1, BH);
        colmax_kernel<<<grid, 256>>>(Eh, Mxp);
        expsum_kernel<<<grid, 256>>>(Eh, El, Mxp, Zp);
        vscale_kernel<<<(unsigned)(NELEM / 256), 256>>>(Vh, Vl, Zp, Voh, Vol);
    }

    // 5) PV per head: X_h = E_h[2048,2048] @ V'_h[2048,128]
    {
        dim3 grid(HD / 128, Ss / 128, BH);
        mma_gemm<0, 1><<<grid, 256, SMEM_BYTES>>>(Eh, El, Voh, Vol, nullptr, nullptr, Xh, Xl,
                                                  Ss, Ss, HD, HD,
                                                  (size_t)Ss * Ss, (size_t)Ss * HD, (size_t)Ss * HD);
    }

    // 6) Output projection: [8192,1024] @ Wo + bo -> fp32 out
    {
        dim3 grid(Dd / 128, MROWS / 128, 1);
        mma_gemm<0, 0><<<grid, 256, SMEM_BYTES>>>(Xh, Xl, woh, wol, bo, out, nullptr, nullptr,
                                                  Dd, Dd, Dd, Dd, 0, 0, 0);
    }
}

// round 4
// speedup vs baseline: 2.7638x; 1.3048x over previous
#include <cuda_runtime.h>
#include <cuda_bf16.h>
#include <cuda_fp16.h>
#include <cstdint>
#include <math.h>

// Problem constants
#define Bb 4
#define Ss 2048
#define Dd 1024
#define Hh 8
#define HD 128
#define BH (Bb*Hh)            // 32 head-slices
#define MROWS (Bb*Ss)         // 8192
#define NELEM ((size_t)MROWS * Dd)      // 8M
#define WELEM ((size_t)Dd * Dd)         // 1M
#define SELEM ((size_t)BH * Ss * Ss)    // 128M

typedef __nv_bfloat16 bf16;
typedef __nv_bfloat162 bf162;

// ---------------------------------------------------------------------------
// Device scratch (allocation-free rule: __device__ globals)
// ---------------------------------------------------------------------------
__device__ __align__(256) bf16 g_iq_h[NELEM], g_iq_l[NELEM];
__device__ __align__(256) bf16 g_ik_h[NELEM], g_ik_l[NELEM];
__device__ __align__(256) bf16 g_iv_h[NELEM], g_iv_l[NELEM];
__device__ __align__(256) bf16 g_wq_h[WELEM], g_wq_l[WELEM];
__device__ __align__(256) bf16 g_wk_h[WELEM], g_wk_l[WELEM];
__device__ __align__(256) bf16 g_wv_h[WELEM], g_wv_l[WELEM];
__device__ __align__(256) bf16 g_wo_h[WELEM], g_wo_l[WELEM];
__device__ __align__(256) bf16 g_Q_h[NELEM],  g_Q_l[NELEM];
__device__ __align__(256) bf16 g_K_h[NELEM],  g_K_l[NELEM];
__device__ __align__(256) bf16 g_V_h[NELEM],  g_V_l[NELEM];
__device__ __align__(256) __half g_Vo_h[NELEM], g_Vo_l[NELEM];   // V' fp16 hi/lo
__device__ __align__(256) bf16 g_X_h[NELEM],  g_X_l[NELEM];
__device__ __align__(256) bf16 g_E_h[SELEM], g_E_l[SELEM];  // scores hi/lo; E overwrites hi as fp16
__device__ __align__(256) float g_Mx[(size_t)BH * Ss];
__device__ __align__(256) float g_Z [(size_t)BH * Ss];

// ---------------------------------------------------------------------------
// PTX helpers
// ---------------------------------------------------------------------------
__device__ __forceinline__ void cpa(uint32_t dst, const void* src) {
    asm volatile("cp.async.cg.shared.global [%0], [%1], 16;\n" :: "r"(dst), "l"(src));
}
__device__ __forceinline__ void ldsm4(uint32_t& r0, uint32_t& r1, uint32_t& r2, uint32_t& r3, uint32_t a) {
    asm volatile("ldmatrix.sync.aligned.m8n8.x4.shared.b16 {%0,%1,%2,%3}, [%4];"
                 : "=r"(r0), "=r"(r1), "=r"(r2), "=r"(r3) : "r"(a));
}
__device__ __forceinline__ void ldsm4t(uint32_t& r0, uint32_t& r1, uint32_t& r2, uint32_t& r3, uint32_t a) {
    asm volatile("ldmatrix.sync.aligned.m8n8.x4.trans.shared.b16 {%0,%1,%2,%3}, [%4];"
                 : "=r"(r0), "=r"(r1), "=r"(r2), "=r"(r3) : "r"(a));
}
__device__ __forceinline__ void mma16816(float* c, const uint32_t* a, const uint32_t* b) {
    asm volatile("mma.sync.aligned.m16n8k16.row.col.f32.bf16.bf16.f32 "
                 "{%0,%1,%2,%3},{%4,%5,%6,%7},{%8,%9},{%0,%1,%2,%3};"
                 : "+f"(c[0]), "+f"(c[1]), "+f"(c[2]), "+f"(c[3])
                 : "r"(a[0]), "r"(a[1]), "r"(a[2]), "r"(a[3]), "r"(b[0]), "r"(b[1]));
}
__device__ __forceinline__ void mma16816h(float* c, const uint32_t* a, const uint32_t* b) {
    asm volatile("mma.sync.aligned.m16n8k16.row.col.f32.f16.f16.f32 "
                 "{%0,%1,%2,%3},{%4,%5,%6,%7},{%8,%9},{%0,%1,%2,%3};"
                 : "+f"(c[0]), "+f"(c[1]), "+f"(c[2]), "+f"(c[3])
                 : "r"(a[0]), "r"(a[1]), "r"(a[2]), "r"(a[3]), "r"(b[0]), "r"(b[1]));
}
__device__ __forceinline__ uint32_t pack2(bf16 a, bf16 b) {
    bf162 t(a, b);
    return *reinterpret_cast<uint32_t*>(&t);
}
__device__ __forceinline__ void split2(float v0, float v1, uint32_t& hi, uint32_t& lo) {
    bf16 h0 = __float2bfloat16_rn(v0);
    bf16 h1 = __float2bfloat16_rn(v1);
    bf16 l0 = __float2bfloat16_rn(v0 - __bfloat162float(h0));
    bf16 l1 = __float2bfloat16_rn(v1 - __bfloat162float(h1));
    hi = pack2(h0, h1);
    lo = pack2(l0, l1);
}

// ---------------------------------------------------------------------------
// Split fp32 -> bf16 hi/lo planes
// ---------------------------------------------------------------------------
__global__ __launch_bounds__(256) void split_f32(const float4* __restrict__ x,
                                                 uint2* __restrict__ hi, uint2* __restrict__ lo, int n4)
{
    int i = blockIdx.x * 256 + threadIdx.x;
    if (i >= n4) return;
    float4 v = x[i];
    uint32_t h01, l01, h23, l23;
    split2(v.x, v.y, h01, l01);
    split2(v.z, v.w, h23, l23);
    hi[i] = make_uint2(h01, h23);
    lo[i] = make_uint2(l01, l23);
}

// ---------------------------------------------------------------------------
// bf16x3 MMA GEMM, 3-stage cp.async pipeline.
// BM=BN=128, BK=64, 256 threads (8 warps 2x4), warp tile 64x32.
// BLAY: 0 = B global [k][n], 1 = B global [n][k].
// EPI: 0 = fp32 out, 1 = hi/lo bf16 plane out.
// ---------------------------------------------------------------------------
#define STAGE_BYTES 65536
#define SMEM_BYTES  196608   // 3 stages

template<int BLAY, int EPI>
__global__ __launch_bounds__(256) void mma_gemm(
    const bf16* __restrict__ Ah, const bf16* __restrict__ Al,
    const bf16* __restrict__ Bh, const bf16* __restrict__ Bl,
    const float* __restrict__ bias,
    float* __restrict__ Cf, bf16* __restrict__ Ch, bf16* __restrict__ Cl,
    int K, int lda, int ldb, int ldc,
    size_t sA, size_t sB, size_t sC)
{
    extern __shared__ __align__(16) char smem[];
    const uint32_t sbase = (uint32_t)__cvta_generic_to_shared(smem);
    const int tid = threadIdx.x, lane = tid & 31, wid = tid >> 5;
    const int wm = wid >> 2, wn = wid & 3;
    const int rowBase = blockIdx.y * 128, colBase = blockIdx.x * 128;
    const bf16* Agh = Ah + (size_t)blockIdx.z * sA;
    const bf16* Agl = Al + (size_t)blockIdx.z * sA;
    const bf16* Bgh = Bh + (size_t)blockIdx.z * sB;
    const bf16* Bgl = Bl + (size_t)blockIdx.z * sB;
    const size_t zC = (size_t)blockIdx.z * sC;

    float acc[4][4][4] = {};

    auto copyStage = [&](int st, int k0) {
        uint32_t aOff = sbase + st * STAGE_BYTES;
        #pragma unroll
        for (int t = 0; t < 4; t++) {
            int idx = tid + t * 256;
            int r = idx >> 3, c = idx & 7;
            int sw = c ^ (r & 7);
            uint32_t d = aOff + r * 128 + sw * 16;
            size_t g = (size_t)(rowBase + r) * lda + (k0 + c * 8);
            cpa(d,         Agh + g);
            cpa(d + 16384, Agl + g);
        }
        uint32_t bOff = aOff + 32768;
        #pragma unroll
        for (int t = 0; t < 4; t++) {
            int idx = tid + t * 256;
            if (BLAY == 0) {
                int r = idx >> 4, c = idx & 15;
                int sw = c ^ (r & 7);
                uint32_t d = bOff + r * 256 + sw * 16;
                size_t g = (size_t)(k0 + r) * ldb + (colBase + c * 8);
                cpa(d,         Bgh + g);
                cpa(d + 16384, Bgl + g);
            } else {
                int r = idx >> 3, c = idx & 7;
                int sw = c ^ (r & 7);
                uint32_t d = bOff + r * 128 + sw * 16;
                size_t g = (size_t)(colBase + r) * ldb + (k0 + c * 8);
                cpa(d,         Bgh + g);
                cpa(d + 16384, Bgl + g);
            }
        }
    };

    auto computeStage = [&](int st) {
        uint32_t aHi = sbase + st * STAGE_BYTES;
        uint32_t aLo = aHi + 16384;
        uint32_t bHi = aHi + 32768;
        uint32_t bLo = bHi + 16384;
        #pragma unroll
        for (int ks = 0; ks < 4; ks++) {
            uint32_t af[2][4][4];
            uint32_t bfr[2][4][2];
            #pragma unroll
            for (int mt = 0; mt < 4; mt++) {
                int row = wm * 64 + mt * 16 + (lane & 15);
                int ch = ks * 2 + (lane >> 4);
                uint32_t ad = (uint32_t)(row * 128 + ((ch ^ (row & 7)) * 16));
                ldsm4(af[0][mt][0], af[0][mt][1], af[0][mt][2], af[0][mt][3], aHi + ad);
                ldsm4(af[1][mt][0], af[1][mt][1], af[1][mt][2], af[1][mt][3], aLo + ad);
            }
            #pragma unroll
            for (int i = 0; i < 2; i++) {
                if (BLAY == 0) {
                    int row = ks * 16 + ((lane >> 3) & 1) * 8 + (lane & 7);
                    int ch = wn * 4 + i * 2 + (lane >> 4);
                    uint32_t bd = (uint32_t)(row * 256 + ((ch ^ (row & 7)) * 16));
                    uint32_t r0, r1, r2, r3;
                    ldsm4t(r0, r1, r2, r3, bHi + bd);
                    bfr[0][2*i][0] = r0; bfr[0][2*i][1] = r1; bfr[0][2*i+1][0] = r2; bfr[0][2*i+1][1] = r3;
                    ldsm4t(r0, r1, r2, r3, bLo + bd);
                    bfr[1][2*i][0] = r0; bfr[1][2*i][1] = r1; bfr[1][2*i+1][0] = r2; bfr[1][2*i+1][1] = r3;
                } else {
                    int row = wn * 32 + i * 16 + ((lane >> 4) << 3) + (lane & 7);
                    int ch = ks * 2 + ((lane >> 3) & 1);
                    uint32_t bd = (uint32_t)(row * 128 + ((ch ^ (row & 7)) * 16));
                    uint32_t r0, r1, r2, r3;
                    ldsm4(r0, r1, r2, r3, bHi + bd);
                    bfr[0][2*i][0] = r0; bfr[0][2*i][1] = r1; bfr[0][2*i+1][0] = r2; bfr[0][2*i+1][1] = r3;
                    ldsm4(r0, r1, r2, r3, bLo + bd);
                    bfr[1][2*i][0] = r0; bfr[1][2*i][1] = r1; bfr[1][2*i+1][0] = r2; bfr[1][2*i+1][1] = r3;
                }
            }
            #pragma unroll
            for (int mt = 0; mt < 4; mt++)
                #pragma unroll
                for (int nt = 0; nt < 4; nt++) {
                    mma16816(acc[mt][nt], af[0][mt], bfr[0][nt]);
                    mma16816(acc[mt][nt], af[0][mt], bfr[1][nt]);
                    mma16816(acc[mt][nt], af[1][mt], bfr[0][nt]);
                }
        }
    };

    const int nk = K >> 6;
    copyStage(0, 0);
    asm volatile("cp.async.commit_group;" ::: "memory");
    if (nk > 1) {
        copyStage(1, 64);
        asm volatile("cp.async.commit_group;" ::: "memory");
    }
    int st = 0;
    for (int kt = 0; kt < nk; kt++) {
        if (kt + 2 < nk) {
            int pst = st + 2; if (pst >= 3) pst -= 3;
            copyStage(pst, (kt + 2) * 64);
            asm volatile("cp.async.commit_group;" ::: "memory");
            asm volatile("cp.async.wait_group 2;" ::: "memory");
        } else if (kt + 1 < nk) {
            asm volatile("cp.async.wait_group 1;" ::: "memory");
        } else {
            asm volatile("cp.async.wait_group 0;" ::: "memory");
        }
        __syncthreads();
        computeStage(st);
        __syncthreads();
        if (++st == 3) st = 0;
    }

    #pragma unroll
    for (int mt = 0; mt < 4; mt++) {
        #pragma unroll
        for (int nt = 0; nt < 4; nt++) {
            int r = rowBase + wm * 64 + mt * 16 + (lane >> 2);
            int c = colBase + wn * 32 + nt * 8 + (lane & 3) * 2;
            float b0 = 0.f, b1 = 0.f;
            if (bias) { b0 = bias[c]; b1 = bias[c + 1]; }
            float v00 = acc[mt][nt][0] + b0, v01 = acc[mt][nt][1] + b1;
            float v10 = acc[mt][nt][2] + b0, v11 = acc[mt][nt][3] + b1;
            if (EPI == 0) {
                *reinterpret_cast<float2*>(Cf + zC + (size_t)r * ldc + c)       = make_float2(v00, v01);
                *reinterpret_cast<float2*>(Cf + zC + (size_t)(r + 8) * ldc + c) = make_float2(v10, v11);
            } else {
                uint32_t h, l;
                split2(v00, v01, h, l);
                *reinterpret_cast<uint32_t*>(Ch + zC + (size_t)r * ldc + c) = h;
                *reinterpret_cast<uint32_t*>(Cl + zC + (size_t)r * ldc + c) = l;
                split2(v10, v11, h, l);
                *reinterpret_cast<uint32_t*>(Ch + zC + (size_t)(r + 8) * ldc + c) = h;
                *reinterpret_cast<uint32_t*>(Cl + zC + (size_t)(r + 8) * ldc + c) = l;
            }
        }
    }
}

// ---------------------------------------------------------------------------
// PV GEMM in fp16: X_h = E (fp16 single plane) @ V' (fp16 hi/lo planes).
// Same tiling as mma_gemm BLAY=0, but A is one plane -> 2 MMA products.
// Stage: A 16KB + Bh 16KB + Bl 16KB = 48KB, 3 stages.
// ---------------------------------------------------------------------------
#define PV_STAGE 49152
#define PV_SMEM  147456

__global__ __launch_bounds__(256) void pv_gemm(
    const __half* __restrict__ Ag,    // [Ss,Ss] per head (strided z)
    const __half* __restrict__ Bhg,   // [Ss,HD] per head
    const __half* __restrict__ Blg,
    bf16* __restrict__ Ch, bf16* __restrict__ Cl)  // [Ss,HD] per head
{
    extern __shared__ __align__(16) char smem[];
    const uint32_t sbase = (uint32_t)__cvta_generic_to_shared(smem);
    const int tid = threadIdx.x, lane = tid & 31, wid = tid >> 5;
    const int wm = wid >> 2, wn = wid & 3;
    const int rowBase = blockIdx.y * 128;
    const __half* A = Ag + (size_t)blockIdx.z * Ss * Ss;
    const __half* Bh = Bhg + (size_t)blockIdx.z * Ss * HD;
    const __half* Bl = Blg + (size_t)blockIdx.z * Ss * HD;
    const size_t zC = (size_t)blockIdx.z * Ss * HD;

    float acc[4][4][4] = {};

    auto copyStage = [&](int st, int k0) {
        uint32_t aOff = sbase + st * PV_STAGE;
        #pragma unroll
        for (int t = 0; t < 4; t++) {
            int idx = tid + t * 256;
            int r = idx >> 3, c = idx & 7;
            int sw = c ^ (r & 7);
            cpa(aOff + r * 128 + sw * 16, A + (size_t)(rowBase + r) * Ss + (k0 + c * 8));
        }
        uint32_t bOff = aOff + 16384;
        #pragma unroll
        for (int t = 0; t < 4; t++) {
            int idx = tid + t * 256;
            int r = idx >> 4, c = idx & 15;
            int sw = c ^ (r & 7);
            uint32_t d = bOff + r * 256 + sw * 16;
            size_t g = (size_t)(k0 + r) * HD + c * 8;
            cpa(d,         Bh + g);
            cpa(d + 16384, Bl + g);
        }
    };

    auto computeStage = [&](int st) {
        uint32_t aP  = sbase + st * PV_STAGE;
        uint32_t bHi = aP + 16384;
        uint32_t bLo = bHi + 16384;
        #pragma unroll
        for (int ks = 0; ks < 4; ks++) {
            uint32_t af[4][4];
            uint32_t bfr[2][4][2];
            #pragma unroll
            for (int mt = 0; mt < 4; mt++) {
                int row = wm * 64 + mt * 16 + (lane & 15);
                int ch = ks * 2 + (lane >> 4);
                uint32_t ad = (uint32_t)(row * 128 + ((ch ^ (row & 7)) * 16));
                ldsm4(af[mt][0], af[mt][1], af[mt][2], af[mt][3], aP + ad);
            }
            #pragma unroll
            for (int i = 0; i < 2; i++) {
                int row = ks * 16 + ((lane >> 3) & 1) * 8 + (lane & 7);
                int ch = wn * 4 + i * 2 + (lane >> 4);
                uint32_t bd = (uint32_t)(row * 256 + ((ch ^ (row & 7)) * 16));
                uint32_t r0, r1, r2, r3;
                ldsm4t(r0, r1, r2, r3, bHi + bd);
                bfr[0][2*i][0] = r0; bfr[0][2*i][1] = r1; bfr[0][2*i+1][0] = r2; bfr[0][2*i+1][1] = r3;
                ldsm4t(r0, r1, r2, r3, bLo + bd);
                bfr[1][2*i][0] = r0; bfr[1][2*i][1] = r1; bfr[1][2*i+1][0] = r2; bfr[1][2*i+1][1] = r3;
            }
            #pragma unroll
            for (int mt = 0; mt < 4; mt++)
                #pragma unroll
                for (int nt = 0; nt < 4; nt++) {
                    mma16816h(acc[mt][nt], af[mt], bfr[0][nt]);
                    mma16816h(acc[mt][nt], af[mt], bfr[1][nt]);
                }
        }
    };

    const int nk = Ss >> 6;   // 32
    copyStage(0, 0);
    asm volatile("cp.async.commit_group;" ::: "memory");
    copyStage(1, 64);
    asm volatile("cp.async.commit_group;" ::: "memory");
    int st = 0;
    for (int kt = 0; kt < nk; kt++) {
        if (kt + 2 < nk) {
            int pst = st + 2; if (pst >= 3) pst -= 3;
            copyStage(pst, (kt + 2) * 64);
            asm volatile("cp.async.commit_group;" ::: "memory");
            asm volatile("cp.async.wait_group 2;" ::: "memory");
        } else if (kt + 1 < nk) {
            asm volatile("cp.async.wait_group 1;" ::: "memory");
        } else {
            asm volatile("cp.async.wait_group 0;" ::: "memory");
        }
        __syncthreads();
        computeStage(st);
        __syncthreads();
        if (++st == 3) st = 0;
    }

    #pragma unroll
    for (int mt = 0; mt < 4; mt++) {
        #pragma unroll
        for (int nt = 0; nt < 4; nt++) {
            int r = rowBase + wm * 64 + mt * 16 + (lane >> 2);
            int c = wn * 32 + nt * 8 + (lane & 3) * 2;
            uint32_t h, l;
            split2(acc[mt][nt][0], acc[mt][nt][1], h, l);
            *reinterpret_cast<uint32_t*>(Ch + zC + (size_t)r * HD + c) = h;
            *reinterpret_cast<uint32_t*>(Cl + zC + (size_t)r * HD + c) = l;
            split2(acc[mt][nt][2], acc[mt][nt][3], h, l);
            *reinterpret_cast<uint32_t*>(Ch + zC + (size_t)(r + 8) * HD + c) = h;
            *reinterpret_cast<uint32_t*>(Cl + zC + (size_t)(r + 8) * HD + c) = l;
        }
    }
}

// ---------------------------------------------------------------------------
// Softmax over query axis:
//  colmax:  M[k] = max_q S_hi[q,k]  (hi bf16 plane)
//  expsum:  E = exp(S_hi+S_lo - M) -> single fp16 plane (in place over S_hi),
//           Z[k] = sum_q E
//  vscale:  V'[k,d] = V[k,d]/Z[k] -> fp16 hi/lo;  then X = E @ V'.
// ---------------------------------------------------------------------------
__global__ __launch_bounds__(256) void colmax_kernel(const bf16* __restrict__ Eh, float* __restrict__ Mx)
{
    const size_t base = (size_t)blockIdx.z * Ss * Ss;
    const int c2 = blockIdx.x * 256 + threadIdx.x;   // bf162 column index
    const bf162* col = reinterpret_cast<const bf162*>(Eh + base) + c2;
    float m0 = -1e30f, m1 = -1e30f;
    #pragma unroll 4
    for (int r = 0; r < Ss; r += 2) {
        bf162 a = col[(size_t)r * (Ss / 2)];
        bf162 b = col[(size_t)(r + 1) * (Ss / 2)];
        m0 = fmaxf(m0, fmaxf(__bfloat162float(a.x), __bfloat162float(b.x)));
        m1 = fmaxf(m1, fmaxf(__bfloat162float(a.y), __bfloat162float(b.y)));
    }
    reinterpret_cast<float2*>(Mx + (size_t)blockIdx.z * Ss)[c2] = make_float2(m0, m1);
}

__global__ __launch_bounds__(256) void expsum_kernel(bf16* __restrict__ Eh, const bf16* __restrict__ El,
                                                     const float* __restrict__ Mx,
                                                     float* __restrict__ Z)
{
    const size_t base = (size_t)blockIdx.z * Ss * Ss;
    const int c2 = blockIdx.x * 256 + threadIdx.x;
    uint32_t* EH = reinterpret_cast<uint32_t*>(Eh + base) + c2;
    const uint32_t* EL = reinterpret_cast<const uint32_t*>(El + base) + c2;
    float2 m = reinterpret_cast<const float2*>(Mx + (size_t)blockIdx.z * Ss)[c2];
    float z0 = 0.f, z1 = 0.f;
    #pragma unroll 2
    for (int r = 0; r < Ss; r++) {
        size_t off = (size_t)r * (Ss / 2);
        uint32_t hbits = EH[off];
        uint32_t lbits = EL[off];
        bf162 h = *reinterpret_cast<bf162*>(&hbits);
        bf162 l = *reinterpret_cast<const bf162*>(&lbits);
        float s0 = __bfloat162float(h.x) + __bfloat162float(l.x);
        float s1 = __bfloat162float(h.y) + __bfloat162float(l.y);
        float e0 = __expf(s0 - m.x);
        float e1 = __expf(s1 - m.y);
        z0 += e0; z1 += e1;
        __half2 e2 = __floats2half2_rn(e0, e1);
        EH[off] = *reinterpret_cast<uint32_t*>(&e2);     // fp16 E plane in place
    }
    reinterpret_cast<float2*>(Z + (size_t)blockIdx.z * Ss)[c2] = make_float2(z0, z1);
}

__global__ __launch_bounds__(256) void vscale_kernel(const bf16* __restrict__ Vh, const bf16* __restrict__ Vl,
                                                     const float* __restrict__ Z,
                                                     __half* __restrict__ Voh, __half* __restrict__ Vol)
{
    size_t i = (size_t)blockIdx.x * 256 + threadIdx.x;   // over 8M elements
    size_t kz = i >> 7;                                   // z*Ss + k  (HD = 128)
    float inv = __fdividef(1.0f, Z[kz]);
    float v = (__bfloat162float(Vh[i]) + __bfloat162float(Vl[i])) * inv;
    __half h = __float2half_rn(v);
    __half l = __float2half_rn(v - __half2float(h));
    Voh[i] = h;
    Vol[i] = l;
}

// ---------------------------------------------------------------------------
// Launch
// ---------------------------------------------------------------------------
extern "C" void kernel_launch(void* const* d_in, const int* in_sizes, int n_in,
                              void* d_out, int out_size)
{
    const float* query = (const float*)d_in[0];
    const float* key   = (const float*)d_in[1];
    const float* value = (const float*)d_in[2];
    const float* Wq    = (const float*)d_in[3];
    const float* bq    = (const float*)d_in[4];
    const float* Wk    = (const float*)d_in[5];
    const float* bk    = (const float*)d_in[6];
    const float* Wv    = (const float*)d_in[7];
    const float* bv    = (const float*)d_in[8];
    const float* Wo    = (const float*)d_in[9];
    const float* bo    = (const float*)d_in[10];
    float* out = (float*)d_out;

    #define SYM(p, s) do { void* tmp_; cudaGetSymbolAddress(&tmp_, s); p = (decltype(p))tmp_; } while (0)
    bf16 *iqh, *iql, *ikh, *ikl, *ivh, *ivl;
    bf16 *wqh, *wql, *wkh, *wkl, *wvh, *wvl, *woh, *wol;
    bf16 *Qh, *Ql, *Kh, *Kl, *Vh, *Vl, *Xh, *Xl, *Eh, *El;
    __half *Voh, *Vol;
    float *Mxp, *Zp;
    SYM(iqh, g_iq_h); SYM(iql, g_iq_l); SYM(ikh, g_ik_h); SYM(ikl, g_ik_l);
    SYM(ivh, g_iv_h); SYM(ivl, g_iv_l);
    SYM(wqh, g_wq_h); SYM(wql, g_wq_l); SYM(wkh, g_wk_h); SYM(wkl, g_wk_l);
    SYM(wvh, g_wv_h); SYM(wvl, g_wv_l); SYM(woh, g_wo_h); SYM(wol, g_wo_l);
    SYM(Qh, g_Q_h); SYM(Ql, g_Q_l); SYM(Kh, g_K_h); SYM(Kl, g_K_l);
    SYM(Vh, g_V_h); SYM(Vl, g_V_l); SYM(Voh, g_Vo_h); SYM(Vol, g_Vo_l);
    SYM(Xh, g_X_h); SYM(Xl, g_X_l); SYM(Eh, g_E_h); SYM(El, g_E_l);
    SYM(Mxp, g_Mx); SYM(Zp, g_Z);
    #undef SYM

    cudaFuncSetAttribute(mma_gemm<0, 0>, cudaFuncAttributeMaxDynamicSharedMemorySize, SMEM_BYTES);
    cudaFuncSetAttribute(mma_gemm<0, 1>, cudaFuncAttributeMaxDynamicSharedMemorySize, SMEM_BYTES);
    cudaFuncSetAttribute(mma_gemm<1, 1>, cudaFuncAttributeMaxDynamicSharedMemorySize, SMEM_BYTES);
    cudaFuncSetAttribute(pv_gemm, cudaFuncAttributeMaxDynamicSharedMemorySize, PV_SMEM);

    // 1) Split fp32 inputs/weights into bf16 hi/lo planes
    {
        int n4i = (int)(NELEM / 4), n4w = (int)(WELEM / 4);
        split_f32<<<n4i / 256, 256>>>((const float4*)query, (uint2*)iqh, (uint2*)iql, n4i);
        split_f32<<<n4i / 256, 256>>>((const float4*)key,   (uint2*)ikh, (uint2*)ikl, n4i);
        split_f32<<<n4i / 256, 256>>>((const float4*)value, (uint2*)ivh, (uint2*)ivl, n4i);
        split_f32<<<n4w / 256, 256>>>((const float4*)Wq, (uint2*)wqh, (uint2*)wql, n4w);
        split_f32<<<n4w / 256, 256>>>((const float4*)Wk, (uint2*)wkh, (uint2*)wkl, n4w);
        split_f32<<<n4w / 256, 256>>>((const float4*)Wv, (uint2*)wvh, (uint2*)wvl, n4w);
        split_f32<<<n4w / 256, 256>>>((const float4*)Wo, (uint2*)woh, (uint2*)wol, n4w);
    }

    // 2) QKV projections: [8192,1024] @ [1024,1024] + bias -> hi/lo planes
    {
        dim3 grid(Dd / 128, MROWS / 128, 1);
        mma_gemm<0, 1><<<grid, 256, SMEM_BYTES>>>(iqh, iql, wqh, wql, bq, nullptr, Qh, Ql,
                                                  Dd, Dd, Dd, Dd, 0, 0, 0);
        mma_gemm<0, 1><<<grid, 256, SMEM_BYTES>>>(ikh, ikl, wkh, wkl, bk, nullptr, Kh, Kl,
                                                  Dd, Dd, Dd, Dd, 0, 0, 0);
        mma_gemm<0, 1><<<grid, 256, SMEM_BYTES>>>(ivh, ivl, wvh, wvl, bv, nullptr, Vh, Vl,
                                                  Dd, Dd, Dd, Dd, 0, 0, 0);
    }

    // 3) Scores per head: S = Q_h @ K_h^T -> hi/lo bf16 planes in E buffers
    {
        dim3 grid(Ss / 128, Ss / 128, BH);
        mma_gemm<1, 1><<<grid, 256, SMEM_BYTES>>>(Qh, Ql, Kh, Kl, nullptr, nullptr, Eh, El,
                                                  HD, HD, HD, Ss,
                                                  (size_t)Ss * HD, (size_t)Ss * HD, (size_t)Ss * Ss);
    }

    // 4) Softmax over query axis (normalization folded into V)
    {
        dim3 grid(Ss / 2 / 256, 1, BH);
        colmax_kernel<<<grid, 256>>>(Eh, Mxp);
        expsum_kernel<<<grid, 256>>>(Eh, El, Mxp, Zp);
        vscale_kernel<<<(unsigned)(NELEM / 256), 256>>>(Vh, Vl, Zp, Voh, Vol);
    }

    // 5) PV per head (fp16): X_h = E[2048,2048] @ V'[2048,128]
    {
        dim3 grid(1, Ss / 128, BH);
        pv_gemm<<<grid, 256, PV_SMEM>>>((const __half*)Eh, Voh, Vol, Xh, Xl);
    }

    // 6) Output projection: [8192,1024] @ Wo + bo -> fp32 out
    {
        dim3 grid(Dd / 128, MROWS / 128, 1);
        mma_gemm<0, 0><<<grid, 256, SMEM_BYTES>>>(Xh, Xl, woh, wol, bo, out, nullptr, nullptr,
                                                  Dd, Dd, Dd, Dd, 0, 0, 0);
    }
}

// round 6
// speedup vs baseline: 4.1694x; 1.5086x over previous
#include <cuda_runtime.h>
#include <cuda_bf16.h>
#include <cuda_fp16.h>
#include <cstdint>
#include <math.h>

// Problem constants
#define Bb 4
#define Ss 2048
#define Dd 1024
#define Hh 8
#define HD 128
#define BH (Bb*Hh)            // 32 head-slices
#define MROWS (Bb*Ss)         // 8192
#define NELEM ((size_t)MROWS * Dd)      // 8M
#define WELEM ((size_t)Dd * Dd)         // 1M
#define SELEM ((size_t)BH * Ss * Ss)    // 128M

typedef __nv_bfloat16 bf16;
typedef __nv_bfloat162 bf162;

// ---------------------------------------------------------------------------
// Device scratch (allocation-free rule: __device__ globals)
// ---------------------------------------------------------------------------
__device__ __align__(256) bf16 g_iq_h[NELEM], g_iq_l[NELEM];
__device__ __align__(256) bf16 g_ik_h[NELEM], g_ik_l[NELEM];
__device__ __align__(256) bf16 g_iv_h[NELEM], g_iv_l[NELEM];
__device__ __align__(256) bf16 g_wq_h[WELEM], g_wq_l[WELEM];
__device__ __align__(256) bf16 g_wk_h[WELEM], g_wk_l[WELEM];
__device__ __align__(256) bf16 g_wv_h[WELEM], g_wv_l[WELEM];
__device__ __align__(256) bf16 g_wo_h[WELEM], g_wo_l[WELEM];
__device__ __align__(256) bf16 g_Q_h[NELEM],  g_Q_l[NELEM];
__device__ __align__(256) bf16 g_K_h[NELEM],  g_K_l[NELEM];
__device__ __align__(256) bf16 g_V_h[NELEM],  g_V_l[NELEM];
__device__ __align__(256) __half g_Vo_h[NELEM], g_Vo_l[NELEM];   // V' fp16 hi/lo
__device__ __align__(256) bf16 g_X_h[NELEM],  g_X_l[NELEM];
__device__ __align__(256) bf16 g_E_h[SELEM], g_E_l[SELEM];  // scores hi/lo; hi becomes fp16 E
__device__ __align__(256) float g_Mx[(size_t)BH * Ss];
__device__ __align__(256) float g_Z [(size_t)BH * Ss];

// ---------------------------------------------------------------------------
// PTX helpers
// ---------------------------------------------------------------------------
__device__ __forceinline__ void cpa(uint32_t dst, const void* src) {
    asm volatile("cp.async.cg.shared.global [%0], [%1], 16;\n" :: "r"(dst), "l"(src));
}
__device__ __forceinline__ void ldsm4(uint32_t& r0, uint32_t& r1, uint32_t& r2, uint32_t& r3, uint32_t a) {
    asm volatile("ldmatrix.sync.aligned.m8n8.x4.shared.b16 {%0,%1,%2,%3}, [%4];"
                 : "=r"(r0), "=r"(r1), "=r"(r2), "=r"(r3) : "r"(a));
}
__device__ __forceinline__ void ldsm4t(uint32_t& r0, uint32_t& r1, uint32_t& r2, uint32_t& r3, uint32_t a) {
    asm volatile("ldmatrix.sync.aligned.m8n8.x4.trans.shared.b16 {%0,%1,%2,%3}, [%4];"
                 : "=r"(r0), "=r"(r1), "=r"(r2), "=r"(r3) : "r"(a));
}
__device__ __forceinline__ void mma16816(float* c, const uint32_t* a, const uint32_t* b) {
    asm volatile("mma.sync.aligned.m16n8k16.row.col.f32.bf16.bf16.f32 "
                 "{%0,%1,%2,%3},{%4,%5,%6,%7},{%8,%9},{%0,%1,%2,%3};"
                 : "+f"(c[0]), "+f"(c[1]), "+f"(c[2]), "+f"(c[3])
                 : "r"(a[0]), "r"(a[1]), "r"(a[2]), "r"(a[3]), "r"(b[0]), "r"(b[1]));
}
__device__ __forceinline__ void mma16816h(float* c, const uint32_t* a, const uint32_t* b) {
    asm volatile("mma.sync.aligned.m16n8k16.row.col.f32.f16.f16.f32 "
                 "{%0,%1,%2,%3},{%4,%5,%6,%7},{%8,%9},{%0,%1,%2,%3};"
                 : "+f"(c[0]), "+f"(c[1]), "+f"(c[2]), "+f"(c[3])
                 : "r"(a[0]), "r"(a[1]), "r"(a[2]), "r"(a[3]), "r"(b[0]), "r"(b[1]));
}
__device__ __forceinline__ uint32_t pack2(bf16 a, bf16 b) {
    bf162 t(a, b);
    return *reinterpret_cast<uint32_t*>(&t);
}
__device__ __forceinline__ void split2(float v0, float v1, uint32_t& hi, uint32_t& lo) {
    bf16 h0 = __float2bfloat16_rn(v0);
    bf16 h1 = __float2bfloat16_rn(v1);
    bf16 l0 = __float2bfloat16_rn(v0 - __bfloat162float(h0));
    bf16 l1 = __float2bfloat16_rn(v1 - __bfloat162float(h1));
    hi = pack2(h0, h1);
    lo = pack2(l0, l1);
}
// Sign-safe float atomic max (works for shared and global pointers)
__device__ __forceinline__ void atomicMaxF(float* addr, float v) {
    if (v >= 0.f) atomicMax((int*)addr, __float_as_int(v));
    else          atomicMin((unsigned int*)addr, (unsigned int)__float_as_int(v));
}

// ---------------------------------------------------------------------------
// Elementwise prep
// ---------------------------------------------------------------------------
__global__ __launch_bounds__(256) void split_f32(const float4* __restrict__ x,
                                                 uint2* __restrict__ hi, uint2* __restrict__ lo, int n4)
{
    int i = blockIdx.x * 256 + threadIdx.x;
    if (i >= n4) return;
    float4 v = x[i];
    uint32_t h01, l01, h23, l23;
    split2(v.x, v.y, h01, l01);
    split2(v.z, v.w, h23, l23);
    hi[i] = make_uint2(h01, h23);
    lo[i] = make_uint2(l01, l23);
}

__global__ __launch_bounds__(256) void init_mz(float* __restrict__ Mx, float* __restrict__ Z)
{
    int i = blockIdx.x * 256 + threadIdx.x;   // BH*Ss = 65536
    Mx[i] = -1e30f;
    Z[i] = 0.f;
}

// ---------------------------------------------------------------------------
// bf16x3 MMA GEMM, 3-stage cp.async pipeline.
// BM=BN=128, BK=64, 256 threads (8 warps 2x4), warp tile 64x32.
// BLAY: 0 = B global [k][n], 1 = B global [n][k].
// EPI: 0 = fp32 out, 1 = hi/lo bf16 plane out.
// CMAX: 1 = also compute per-column max into Mx[z*ldc + col] (scores).
// ---------------------------------------------------------------------------
#define STAGE_BYTES 65536
#define SMEM_BYTES  (1024 + 3 * STAGE_BYTES)   // 1KB colmax scratch + 3 stages

template<int BLAY, int EPI, int CMAX>
__global__ __launch_bounds__(256) void mma_gemm(
    const bf16* __restrict__ Ah, const bf16* __restrict__ Al,
    const bf16* __restrict__ Bh, const bf16* __restrict__ Bl,
    const float* __restrict__ bias,
    float* __restrict__ Cf, bf16* __restrict__ Ch, bf16* __restrict__ Cl,
    float* __restrict__ Mx,
    int K, int lda, int ldb, int ldc,
    size_t sA, size_t sB, size_t sC)
{
    extern __shared__ __align__(16) char smem[];
    float* sMax = reinterpret_cast<float*>(smem);
    const uint32_t sbase = (uint32_t)__cvta_generic_to_shared(smem) + 1024;
    const int tid = threadIdx.x, lane = tid & 31, wid = tid >> 5;
    const int wm = wid >> 2, wn = wid & 3;
    const int rowBase = blockIdx.y * 128, colBase = blockIdx.x * 128;
    const bf16* Agh = Ah + (size_t)blockIdx.z * sA;
    const bf16* Agl = Al + (size_t)blockIdx.z * sA;
    const bf16* Bgh = Bh + (size_t)blockIdx.z * sB;
    const bf16* Bgl = Bl + (size_t)blockIdx.z * sB;
    const size_t zC = (size_t)blockIdx.z * sC;

    float acc[4][4][4] = {};

    auto copyStage = [&](int st, int k0) {
        uint32_t aOff = sbase + st * STAGE_BYTES;
        #pragma unroll
        for (int t = 0; t < 4; t++) {
            int idx = tid + t * 256;
            int r = idx >> 3, c = idx & 7;
            int sw = c ^ (r & 7);
            uint32_t d = aOff + r * 128 + sw * 16;
            size_t g = (size_t)(rowBase + r) * lda + (k0 + c * 8);
            cpa(d,         Agh + g);
            cpa(d + 16384, Agl + g);
        }
        uint32_t bOff = aOff + 32768;
        #pragma unroll
        for (int t = 0; t < 4; t++) {
            int idx = tid + t * 256;
            if (BLAY == 0) {
                int r = idx >> 4, c = idx & 15;
                int sw = c ^ (r & 7);
                uint32_t d = bOff + r * 256 + sw * 16;
                size_t g = (size_t)(k0 + r) * ldb + (colBase + c * 8);
                cpa(d,         Bgh + g);
                cpa(d + 16384, Bgl + g);
            } else {
                int r = idx >> 3, c = idx & 7;
                int sw = c ^ (r & 7);
                uint32_t d = bOff + r * 128 + sw * 16;
                size_t g = (size_t)(colBase + r) * ldb + (k0 + c * 8);
                cpa(d,         Bgh + g);
                cpa(d + 16384, Bgl + g);
            }
        }
    };

    auto computeStage = [&](int st) {
        uint32_t aHi = sbase + st * STAGE_BYTES;
        uint32_t aLo = aHi + 16384;
        uint32_t bHi = aHi + 32768;
        uint32_t bLo = bHi + 16384;
        #pragma unroll
        for (int ks = 0; ks < 4; ks++) {
            uint32_t af[2][4][4];
            uint32_t bfr[2][4][2];
            #pragma unroll
            for (int mt = 0; mt < 4; mt++) {
                int row = wm * 64 + mt * 16 + (lane & 15);
                int ch = ks * 2 + (lane >> 4);
                uint32_t ad = (uint32_t)(row * 128 + ((ch ^ (row & 7)) * 16));
                ldsm4(af[0][mt][0], af[0][mt][1], af[0][mt][2], af[0][mt][3], aHi + ad);
                ldsm4(af[1][mt][0], af[1][mt][1], af[1][mt][2], af[1][mt][3], aLo + ad);
            }
            #pragma unroll
            for (int i = 0; i < 2; i++) {
                if (BLAY == 0) {
                    int row = ks * 16 + ((lane >> 3) & 1) * 8 + (lane & 7);
                    int ch = wn * 4 + i * 2 + (lane >> 4);
                    uint32_t bd = (uint32_t)(row * 256 + ((ch ^ (row & 7)) * 16));
                    uint32_t r0, r1, r2, r3;
                    ldsm4t(r0, r1, r2, r3, bHi + bd);
                    bfr[0][2*i][0] = r0; bfr[0][2*i][1] = r1; bfr[0][2*i+1][0] = r2; bfr[0][2*i+1][1] = r3;
                    ldsm4t(r0, r1, r2, r3, bLo + bd);
                    bfr[1][2*i][0] = r0; bfr[1][2*i][1] = r1; bfr[1][2*i+1][0] = r2; bfr[1][2*i+1][1] = r3;
                } else {
                    int row = wn * 32 + i * 16 + ((lane >> 4) << 3) + (lane & 7);
                    int ch = ks * 2 + ((lane >> 3) & 1);
                    uint32_t bd = (uint32_t)(row * 128 + ((ch ^ (row & 7)) * 16));
                    uint32_t r0, r1, r2, r3;
                    ldsm4(r0, r1, r2, r3, bHi + bd);
                    bfr[0][2*i][0] = r0; bfr[0][2*i][1] = r1; bfr[0][2*i+1][0] = r2; bfr[0][2*i+1][1] = r3;
                    ldsm4(r0, r1, r2, r3, bLo + bd);
                    bfr[1][2*i][0] = r0; bfr[1][2*i][1] = r1; bfr[1][2*i+1][0] = r2; bfr[1][2*i+1][1] = r3;
                }
            }
            #pragma unroll
            for (int mt = 0; mt < 4; mt++)
                #pragma unroll
                for (int nt = 0; nt < 4; nt++) {
                    mma16816(acc[mt][nt], af[0][mt], bfr[0][nt]);
                    mma16816(acc[mt][nt], af[0][mt], bfr[1][nt]);
                    mma16816(acc[mt][nt], af[1][mt], bfr[0][nt]);
                }
        }
    };

    const int nk = K >> 6;
    copyStage(0, 0);
    asm volatile("cp.async.commit_group;" ::: "memory");
    if (nk > 1) {
        copyStage(1, 64);
        asm volatile("cp.async.commit_group;" ::: "memory");
    }
    int st = 0;
    for (int kt = 0; kt < nk; kt++) {
        if (kt + 2 < nk) {
            int pst = st + 2; if (pst >= 3) pst -= 3;
            copyStage(pst, (kt + 2) * 64);
            asm volatile("cp.async.commit_group;" ::: "memory");
            asm volatile("cp.async.wait_group 2;" ::: "memory");
        } else if (kt + 1 < nk) {
            asm volatile("cp.async.wait_group 1;" ::: "memory");
        } else {
            asm volatile("cp.async.wait_group 0;" ::: "memory");
        }
        __syncthreads();
        computeStage(st);
        __syncthreads();
        if (++st == 3) st = 0;
    }

    if (CMAX) {
        if (tid < 128) sMax[tid] = -1e30f;
        __syncthreads();
    }

    #pragma unroll
    for (int nt = 0; nt < 4; nt++) {
        float cm0 = -1e30f, cm1 = -1e30f;
        #pragma unroll
        for (int mt = 0; mt < 4; mt++) {
            int r = rowBase + wm * 64 + mt * 16 + (lane >> 2);
            int c = colBase + wn * 32 + nt * 8 + (lane & 3) * 2;
            float b0 = 0.f, b1 = 0.f;
            if (bias) { b0 = bias[c]; b1 = bias[c + 1]; }
            float v00 = acc[mt][nt][0] + b0, v01 = acc[mt][nt][1] + b1;
            float v10 = acc[mt][nt][2] + b0, v11 = acc[mt][nt][3] + b1;
            if (CMAX) {
                cm0 = fmaxf(cm0, fmaxf(v00, v10));
                cm1 = fmaxf(cm1, fmaxf(v01, v11));
            }
            if (EPI == 0) {
                *reinterpret_cast<float2*>(Cf + zC + (size_t)r * ldc + c)       = make_float2(v00, v01);
                *reinterpret_cast<float2*>(Cf + zC + (size_t)(r + 8) * ldc + c) = make_float2(v10, v11);
            } else {
                uint32_t h, l;
                split2(v00, v01, h, l);
                *reinterpret_cast<uint32_t*>(Ch + zC + (size_t)r * ldc + c) = h;
                *reinterpret_cast<uint32_t*>(Cl + zC + (size_t)r * ldc + c) = l;
                split2(v10, v11, h, l);
                *reinterpret_cast<uint32_t*>(Ch + zC + (size_t)(r + 8) * ldc + c) = h;
                *reinterpret_cast<uint32_t*>(Cl + zC + (size_t)(r + 8) * ldc + c) = l;
            }
        }
        if (CMAX) {
            int ci = wn * 32 + nt * 8 + (lane & 3) * 2;
            atomicMaxF(&sMax[ci], cm0);
            atomicMaxF(&sMax[ci + 1], cm1);
        }
    }

    if (CMAX) {
        __syncthreads();
        if (tid < 128)
            atomicMaxF(Mx + (size_t)blockIdx.z * ldc + colBase + tid, sMax[tid]);
    }
}

// ---------------------------------------------------------------------------
// PV GEMM in fp16: X_h = E (fp16 single plane) @ V' (fp16 hi/lo planes).
// ---------------------------------------------------------------------------
#define PV_STAGE 49152
#define PV_SMEM  147456

__global__ __launch_bounds__(256) void pv_gemm(
    const __half* __restrict__ Ag,
    const __half* __restrict__ Bhg,
    const __half* __restrict__ Blg,
    bf16* __restrict__ Ch, bf16* __restrict__ Cl)
{
    extern __shared__ __align__(16) char smem[];
    const uint32_t sbase = (uint32_t)__cvta_generic_to_shared(smem);
    const int tid = threadIdx.x, lane = tid & 31, wid = tid >> 5;
    const int wm = wid >> 2, wn = wid & 3;
    const int rowBase = blockIdx.y * 128;
    const __half* A = Ag + (size_t)blockIdx.z * Ss * Ss;
    const __half* Bh = Bhg + (size_t)blockIdx.z * Ss * HD;
    const __half* Bl = Blg + (size_t)blockIdx.z * Ss * HD;
    const size_t zC = (size_t)blockIdx.z * Ss * HD;

    float acc[4][4][4] = {};

    auto copyStage = [&](int st, int k0) {
        uint32_t aOff = sbase + st * PV_STAGE;
        #pragma unroll
        for (int t = 0; t < 4; t++) {
            int idx = tid + t * 256;
            int r = idx >> 3, c = idx & 7;
            int sw = c ^ (r & 7);
            cpa(aOff + r * 128 + sw * 16, A + (size_t)(rowBase + r) * Ss + (k0 + c * 8));
        }
        uint32_t bOff = aOff + 16384;
        #pragma unroll
        for (int t = 0; t < 4; t++) {
            int idx = tid + t * 256;
            int r = idx >> 4, c = idx & 15;
            int sw = c ^ (r & 7);
            uint32_t d = bOff + r * 256 + sw * 16;
            size_t g = (size_t)(k0 + r) * HD + c * 8;
            cpa(d,         Bh + g);
            cpa(d + 16384, Bl + g);
        }
    };

    auto computeStage = [&](int st) {
        uint32_t aP  = sbase + st * PV_STAGE;
        uint32_t bHi = aP + 16384;
        uint32_t bLo = bHi + 16384;
        #pragma unroll
        for (int ks = 0; ks < 4; ks++) {
            uint32_t af[4][4];
            uint32_t bfr[2][4][2];
            #pragma unroll
            for (int mt = 0; mt < 4; mt++) {
                int row = wm * 64 + mt * 16 + (lane & 15);
                int ch = ks * 2 + (lane >> 4);
                uint32_t ad = (uint32_t)(row * 128 + ((ch ^ (row & 7)) * 16));
                ldsm4(af[mt][0], af[mt][1], af[mt][2], af[mt][3], aP + ad);
            }
            #pragma unroll
            for (int i = 0; i < 2; i++) {
                int row = ks * 16 + ((lane >> 3) & 1) * 8 + (lane & 7);
                int ch = wn * 4 + i * 2 + (lane >> 4);
                uint32_t bd = (uint32_t)(row * 256 + ((ch ^ (row & 7)) * 16));
                uint32_t r0, r1, r2, r3;
                ldsm4t(r0, r1, r2, r3, bHi + bd);
                bfr[0][2*i][0] = r0; bfr[0][2*i][1] = r1; bfr[0][2*i+1][0] = r2; bfr[0][2*i+1][1] = r3;
                ldsm4t(r0, r1, r2, r3, bLo + bd);
                bfr[1][2*i][0] = r0; bfr[1][2*i][1] = r1; bfr[1][2*i+1][0] = r2; bfr[1][2*i+1][1] = r3;
            }
            #pragma unroll
            for (int mt = 0; mt < 4; mt++)
                #pragma unroll
                for (int nt = 0; nt < 4; nt++) {
                    mma16816h(acc[mt][nt], af[mt], bfr[0][nt]);
                    mma16816h(acc[mt][nt], af[mt], bfr[1][nt]);
                }
        }
    };

    const int nk = Ss >> 6;   // 32
    copyStage(0, 0);
    asm volatile("cp.async.commit_group;" ::: "memory");
    copyStage(1, 64);
    asm volatile("cp.async.commit_group;" ::: "memory");
    int st = 0;
    for (int kt = 0; kt < nk; kt++) {
        if (kt + 2 < nk) {
            int pst = st + 2; if (pst >= 3) pst -= 3;
            copyStage(pst, (kt + 2) * 64);
            asm volatile("cp.async.commit_group;" ::: "memory");
            asm volatile("cp.async.wait_group 2;" ::: "memory");
        } else if (kt + 1 < nk) {
            asm volatile("cp.async.wait_group 1;" ::: "memory");
        } else {
            asm volatile("cp.async.wait_group 0;" ::: "memory");
        }
        __syncthreads();
        computeStage(st);
        __syncthreads();
        if (++st == 3) st = 0;
    }

    #pragma unroll
    for (int mt = 0; mt < 4; mt++) {
        #pragma unroll
        for (int nt = 0; nt < 4; nt++) {
            int r = rowBase + wm * 64 + mt * 16 + (lane >> 2);
            int c = wn * 32 + nt * 8 + (lane & 3) * 2;
            uint32_t h, l;
            split2(acc[mt][nt][0], acc[mt][nt][1], h, l);
            *reinterpret_cast<uint32_t*>(Ch + zC + (size_t)r * HD + c) = h;
            *reinterpret_cast<uint32_t*>(Cl + zC + (size_t)r * HD + c) = l;
            split2(acc[mt][nt][2], acc[mt][nt][3], h, l);
            *reinterpret_cast<uint32_t*>(Ch + zC + (size_t)(r + 8) * HD + c) = h;
            *reinterpret_cast<uint32_t*>(Cl + zC + (size_t)(r + 8) * HD + c) = l;
        }
    }
}

// ---------------------------------------------------------------------------
// Softmax over query axis.  Mx comes from the scores-GEMM epilogue atomics.
// expsum: E = exp(S_hi+S_lo - M) -> single fp16 plane in place over S_hi;
//         Z partial sums merged via atomicAdd (Z zero-initialized).
// ---------------------------------------------------------------------------
#define ERS 8   // row splits for expsum

__global__ __launch_bounds__(256) void expsum_kernel(bf16* __restrict__ Eh, const bf16* __restrict__ El,
                                                     const float* __restrict__ Mx,
                                                     float* __restrict__ Z)
{
    const size_t base = (size_t)blockIdx.z * Ss * Ss;
    const int c2 = blockIdx.x * 256 + threadIdx.x;     // 0..1023 column pairs
    const int r0 = blockIdx.y * (Ss / ERS);
    uint32_t* EH = reinterpret_cast<uint32_t*>(Eh + base) + c2;
    const uint32_t* EL = reinterpret_cast<const uint32_t*>(El + base) + c2;
    float2 m = reinterpret_cast<const float2*>(Mx + (size_t)blockIdx.z * Ss)[c2];
    float z0 = 0.f, z1 = 0.f;
    #pragma unroll 4
    for (int r = r0; r < r0 + Ss / ERS; r++) {
        size_t off = (size_t)r * (Ss / 2);
        uint32_t hbits = EH[off];
        uint32_t lbits = EL[off];
        bf162 h = *reinterpret_cast<bf162*>(&hbits);
        bf162 l = *reinterpret_cast<const bf162*>(&lbits);
        float s0 = __bfloat162float(h.x) + __bfloat162float(l.x);
        float s1 = __bfloat162float(h.y) + __bfloat162float(l.y);
        float e0 = __expf(s0 - m.x);
        float e1 = __expf(s1 - m.y);
        z0 += e0; z1 += e1;
        __half2 e2 = __floats2half2_rn(e0, e1);
        EH[off] = *reinterpret_cast<uint32_t*>(&e2);
    }
    float* zp = Z + (size_t)blockIdx.z * Ss + c2 * 2;
    atomicAdd(zp,     z0);
    atomicAdd(zp + 1, z1);
}

__global__ __launch_bounds__(256) void vscale_kernel(const bf16* __restrict__ Vh, const bf16* __restrict__ Vl,
                                                     const float* __restrict__ Z,
                                                     __half* __restrict__ Voh, __half* __restrict__ Vol)
{
    size_t i = (size_t)blockIdx.x * 256 + threadIdx.x;   // over 8M elements
    size_t kz = i >> 7;                                   // z*Ss + k  (HD = 128)
    float inv = __fdividef(1.0f, Z[kz]);
    float v = (__bfloat162float(Vh[i]) + __bfloat162float(Vl[i])) * inv;
    __half h = __float2half_rn(v);
    __half l = __float2half_rn(v - __half2float(h));
    Voh[i] = h;
    Vol[i] = l;
}

// ---------------------------------------------------------------------------
// Launch
// ---------------------------------------------------------------------------
extern "C" void kernel_launch(void* const* d_in, const int* in_sizes, int n_in,
                              void* d_out, int out_size)
{
    const float* query = (const float*)d_in[0];
    const float* key   = (const float*)d_in[1];
    const float* value = (const float*)d_in[2];
    const float* Wq    = (const float*)d_in[3];
    const float* bq    = (const float*)d_in[4];
    const float* Wk    = (const float*)d_in[5];
    const float* bk    = (const float*)d_in[6];
    const float* Wv    = (const float*)d_in[7];
    const float* bv    = (const float*)d_in[8];
    const float* Wo    = (const float*)d_in[9];
    const float* bo    = (const float*)d_in[10];
    float* out = (float*)d_out;

    #define SYM(p, s) do { void* tmp_; cudaGetSymbolAddress(&tmp_, s); p = (decltype(p))tmp_; } while (0)
    bf16 *iqh, *iql, *ikh, *ikl, *ivh, *ivl;
    bf16 *wqh, *wql, *wkh, *wkl, *wvh, *wvl, *woh, *wol;
    bf16 *Qh, *Ql, *Kh, *Kl, *Vh, *Vl, *Xh, *Xl, *Eh, *El;
    __half *Voh, *Vol;
    float *Mxp, *Zp;
    SYM(iqh, g_iq_h); SYM(iql, g_iq_l); SYM(ikh, g_ik_h); SYM(ikl, g_ik_l);
    SYM(ivh, g_iv_h); SYM(ivl, g_iv_l);
    SYM(wqh, g_wq_h); SYM(wql, g_wq_l); SYM(wkh, g_wk_h); SYM(wkl, g_wk_l);
    SYM(wvh, g_wv_h); SYM(wvl, g_wv_l); SYM(woh, g_wo_h); SYM(wol, g_wo_l);
    SYM(Qh, g_Q_h); SYM(Ql, g_Q_l); SYM(Kh, g_K_h); SYM(Kl, g_K_l);
    SYM(Vh, g_V_h); SYM(Vl, g_V_l); SYM(Voh, g_Vo_h); SYM(Vol, g_Vo_l);
    SYM(Xh, g_X_h); SYM(Xl, g_X_l); SYM(Eh, g_E_h); SYM(El, g_E_l);
    SYM(Mxp, g_Mx); SYM(Zp, g_Z);
    #undef SYM

    cudaFuncSetAttribute(mma_gemm<0, 0, 0>, cudaFuncAttributeMaxDynamicSharedMemorySize, SMEM_BYTES);
    cudaFuncSetAttribute(mma_gemm<0, 1, 0>, cudaFuncAttributeMaxDynamicSharedMemorySize, SMEM_BYTES);
    cudaFuncSetAttribute(mma_gemm<1, 1, 1>, cudaFuncAttributeMaxDynamicSharedMemorySize, SMEM_BYTES);
    cudaFuncSetAttribute(pv_gemm, cudaFuncAttributeMaxDynamicSharedMemorySize, PV_SMEM);

    // 0) Re-init Mx (-inf) and Z (0) — graph-replay safe
    init_mz<<<(BH * Ss) / 256, 256>>>(Mxp, Zp);

    // 1) Split fp32 inputs/weights into bf16 hi/lo planes
    {
        int n4i = (int)(NELEM / 4), n4w = (int)(WELEM / 4);
        split_f32<<<n4i / 256, 256>>>((const float4*)query, (uint2*)iqh, (uint2*)iql, n4i);
        split_f32<<<n4i / 256, 256>>>((const float4*)key,   (uint2*)ikh, (uint2*)ikl, n4i);
        split_f32<<<n4i / 256, 256>>>((const float4*)value, (uint2*)ivh, (uint2*)ivl, n4i);
        split_f32<<<n4w / 256, 256>>>((const float4*)Wq, (uint2*)wqh, (uint2*)wql, n4w);
        split_f32<<<n4w / 256, 256>>>((const float4*)Wk, (uint2*)wkh, (uint2*)wkl, n4w);
        split_f32<<<n4w / 256, 256>>>((const float4*)Wv, (uint2*)wvh, (uint2*)wvl, n4w);
        split_f32<<<n4w / 256, 256>>>((const float4*)Wo, (uint2*)woh, (uint2*)wol, n4w);
    }

    // 2) QKV projections: [8192,1024] @ [1024,1024] + bias -> hi/lo planes
    {
        dim3 grid(Dd / 128, MROWS / 128, 1);
        mma_gemm<0, 1, 0><<<grid, 256, SMEM_BYTES>>>(iqh, iql, wqh, wql, bq, nullptr, Qh, Ql, nullptr,
                                                     Dd, Dd, Dd, Dd, 0, 0, 0);
        mma_gemm<0, 1, 0><<<grid, 256, SMEM_BYTES>>>(ikh, ikl, wkh, wkl, bk, nullptr, Kh, Kl, nullptr,
                                                     Dd, Dd, Dd, Dd, 0, 0, 0);
        mma_gemm<0, 1, 0><<<grid, 256, SMEM_BYTES>>>(ivh, ivl, wvh, wvl, bv, nullptr, Vh, Vl, nullptr,
                                                     Dd, Dd, Dd, Dd, 0, 0, 0);
    }

    // 3) Scores per head + fused column max: S = Q_h @ K_h^T -> hi/lo planes, Mx atomics
    {
        dim3 grid(Ss / 128, Ss / 128, BH);
        mma_gemm<1, 1, 1><<<grid, 256, SMEM_BYTES>>>(Qh, Ql, Kh, Kl, nullptr, nullptr, Eh, El, Mxp,
                                                     HD, HD, HD, Ss,
                                                     (size_t)Ss * HD, (size_t)Ss * HD, (size_t)Ss * Ss);
    }

    // 4) exp + column sums (row-split, atomicAdd Z), then fold 1/Z into V' (fp16)
    {
        dim3 grid(Ss / 2 / 256, ERS, BH);
        expsum_kernel<<<grid, 256>>>(Eh, El, Mxp, Zp);
        vscale_kernel<<<(unsigned)(NELEM / 256), 256>>>(Vh, Vl, Zp, Voh, Vol);
    }

    // 5) PV per head (fp16): X_h = E[2048,2048] @ V'[2048,128]
    {
        dim3 grid(1, Ss / 128, BH);
        pv_gemm<<<grid, 256, PV_SMEM>>>((const __half*)Eh, Voh, Vol, Xh, Xl);
    }

    // 6) Output projection: [8192,1024] @ Wo + bo -> fp32 out
    {
        dim3 grid(Dd / 128, MROWS / 128, 1);
        mma_gemm<0, 0, 0><<<grid, 256, SMEM_BYTES>>>(Xh, Xl, woh, wol, bo, out, nullptr, nullptr, nullptr,
                                                     Dd, Dd, Dd, Dd, 0, 0, 0);
    }
}

// round 7
// speedup vs baseline: 4.3998x; 1.0553x over previous
#include <cuda_runtime.h>
#include <cuda_bf16.h>
#include <cuda_fp16.h>
#include <cstdint>
#include <math.h>

// Problem constants
#define Bb 4
#define Ss 2048
#define Dd 1024
#define Hh 8
#define HD 128
#define BH (Bb*Hh)            // 32 head-slices
#define MROWS (Bb*Ss)         // 8192
#define NELEM ((size_t)MROWS * Dd)      // 8M
#define WELEM ((size_t)Dd * Dd)         // 1M
#define SELEM ((size_t)BH * Ss * Ss)    // 128M

typedef __nv_bfloat16 bf16;
typedef __nv_bfloat162 bf162;

// ---------------------------------------------------------------------------
// Device scratch (allocation-free rule: __device__ globals)
// ---------------------------------------------------------------------------
__device__ __align__(256) bf16 g_iq_h[NELEM], g_iq_l[NELEM];
__device__ __align__(256) bf16 g_ik_h[NELEM], g_ik_l[NELEM];
__device__ __align__(256) bf16 g_iv_h[NELEM], g_iv_l[NELEM];
__device__ __align__(256) bf16 g_wq_h[WELEM], g_wq_l[WELEM];
__device__ __align__(256) bf16 g_wk_h[WELEM], g_wk_l[WELEM];
__device__ __align__(256) bf16 g_wv_h[WELEM], g_wv_l[WELEM];
__device__ __align__(256) bf16 g_wo_h[WELEM], g_wo_l[WELEM];
__device__ __align__(256) bf16 g_Q_h[NELEM],  g_Q_l[NELEM];
__device__ __align__(256) bf16 g_K_h[NELEM],  g_K_l[NELEM];
__device__ __align__(256) bf16 g_V_h[NELEM],  g_V_l[NELEM];
__device__ __align__(256) __half g_Vo_h[NELEM], g_Vo_l[NELEM];   // V' fp16 hi/lo
__device__ __align__(256) bf16 g_X_h[NELEM],  g_X_l[NELEM];
__device__ __align__(256) __half g_E[SELEM];                     // fp16 E plane
__device__ __align__(256) float g_Mx[(size_t)BH * Ss];
__device__ __align__(256) float g_Z [(size_t)BH * Ss];

// ---------------------------------------------------------------------------
// PTX helpers
// ---------------------------------------------------------------------------
__device__ __forceinline__ void cpa(uint32_t dst, const void* src) {
    asm volatile("cp.async.cg.shared.global [%0], [%1], 16;\n" :: "r"(dst), "l"(src));
}
__device__ __forceinline__ void ldsm4(uint32_t& r0, uint32_t& r1, uint32_t& r2, uint32_t& r3, uint32_t a) {
    asm volatile("ldmatrix.sync.aligned.m8n8.x4.shared.b16 {%0,%1,%2,%3}, [%4];"
                 : "=r"(r0), "=r"(r1), "=r"(r2), "=r"(r3) : "r"(a));
}
__device__ __forceinline__ void ldsm4t(uint32_t& r0, uint32_t& r1, uint32_t& r2, uint32_t& r3, uint32_t a) {
    asm volatile("ldmatrix.sync.aligned.m8n8.x4.trans.shared.b16 {%0,%1,%2,%3}, [%4];"
                 : "=r"(r0), "=r"(r1), "=r"(r2), "=r"(r3) : "r"(a));
}
__device__ __forceinline__ void mma16816(float* c, const uint32_t* a, const uint32_t* b) {
    asm volatile("mma.sync.aligned.m16n8k16.row.col.f32.bf16.bf16.f32 "
                 "{%0,%1,%2,%3},{%4,%5,%6,%7},{%8,%9},{%0,%1,%2,%3};"
                 : "+f"(c[0]), "+f"(c[1]), "+f"(c[2]), "+f"(c[3])
                 : "r"(a[0]), "r"(a[1]), "r"(a[2]), "r"(a[3]), "r"(b[0]), "r"(b[1]));
}
__device__ __forceinline__ void mma16816h(float* c, const uint32_t* a, const uint32_t* b) {
    asm volatile("mma.sync.aligned.m16n8k16.row.col.f32.f16.f16.f32 "
                 "{%0,%1,%2,%3},{%4,%5,%6,%7},{%8,%9},{%0,%1,%2,%3};"
                 : "+f"(c[0]), "+f"(c[1]), "+f"(c[2]), "+f"(c[3])
                 : "r"(a[0]), "r"(a[1]), "r"(a[2]), "r"(a[3]), "r"(b[0]), "r"(b[1]));
}
__device__ __forceinline__ uint32_t pack2(bf16 a, bf16 b) {
    bf162 t(a, b);
    return *reinterpret_cast<uint32_t*>(&t);
}
__device__ __forceinline__ void split2(float v0, float v1, uint32_t& hi, uint32_t& lo) {
    bf16 h0 = __float2bfloat16_rn(v0);
    bf16 h1 = __float2bfloat16_rn(v1);
    bf16 l0 = __float2bfloat16_rn(v0 - __bfloat162float(h0));
    bf16 l1 = __float2bfloat16_rn(v1 - __bfloat162float(h1));
    hi = pack2(h0, h1);
    lo = pack2(l0, l1);
}
__device__ __forceinline__ void atomicMaxF(float* addr, float v) {
    if (v >= 0.f) atomicMax((int*)addr, __float_as_int(v));
    else          atomicMin((unsigned int*)addr, (unsigned int)__float_as_int(v));
}

// ---------------------------------------------------------------------------
// Elementwise prep
// ---------------------------------------------------------------------------
__global__ __launch_bounds__(256) void split_f32(const float4* __restrict__ x,
                                                 uint2* __restrict__ hi, uint2* __restrict__ lo, int n4)
{
    int i = blockIdx.x * 256 + threadIdx.x;
    if (i >= n4) return;
    float4 v = x[i];
    uint32_t h01, l01, h23, l23;
    split2(v.x, v.y, h01, l01);
    split2(v.z, v.w, h23, l23);
    hi[i] = make_uint2(h01, h23);
    lo[i] = make_uint2(l01, l23);
}

__global__ __launch_bounds__(256) void init_mz(float* __restrict__ Mx, float* __restrict__ Z)
{
    int i = blockIdx.x * 256 + threadIdx.x;   // BH*Ss = 65536
    Mx[i] = -1e30f;
    Z[i] = 0.f;
}

// ---------------------------------------------------------------------------
// MMA GEMM, 3-stage cp.async pipeline.
// BM=BN=128, BK=64, 256 threads (8 warps 2x4), warp tile 64x32.
// BLAY: 0 = B global [k][n], 1 = B global [n][k].
// EPI:  0 = fp32 out, 1 = hi/lo bf16 planes out,
//       2 = no store, column max -> Mx (atomicMaxF),
//       3 = exp(s - Mx) -> fp16 E plane + column sums Z (atomicAdd).
// LITE: 1 = hi planes only, 1 MMA product (for the max pass).
// ---------------------------------------------------------------------------
template<int BLAY, int EPI, int LITE>
__global__ __launch_bounds__(256) void mma_gemm(
    const bf16* __restrict__ Ah, const bf16* __restrict__ Al,
    const bf16* __restrict__ Bh, const bf16* __restrict__ Bl,
    const float* __restrict__ bias,
    float* __restrict__ Cf, bf16* __restrict__ Ch, bf16* __restrict__ Cl,
    float* __restrict__ Mx, float* __restrict__ Zp,
    int K, int lda, int ldb, int ldc,
    size_t sA, size_t sB, size_t sC)
{
    constexpr int APL = LITE ? 1 : 2;
    constexpr int STG = APL * 16384 + (LITE ? 16384 : 32768);
    extern __shared__ __align__(16) char smem[];
    float* sRed = reinterpret_cast<float*>(smem);             // 128 floats scratch
    const uint32_t sbase = (uint32_t)__cvta_generic_to_shared(smem) + 1024;
    const int tid = threadIdx.x, lane = tid & 31, wid = tid >> 5;
    const int wm = wid >> 2, wn = wid & 3;
    const int rowBase = blockIdx.y * 128, colBase = blockIdx.x * 128;
    const bf16* Agh = Ah + (size_t)blockIdx.z * sA;
    const bf16* Agl = Al + (size_t)blockIdx.z * sA;
    const bf16* Bgh = Bh + (size_t)blockIdx.z * sB;
    const bf16* Bgl = Bl + (size_t)blockIdx.z * sB;
    const size_t zC = (size_t)blockIdx.z * sC;

    float acc[4][4][4] = {};

    auto copyStage = [&](int st, int k0) {
        uint32_t aOff = sbase + st * STG;
        #pragma unroll
        for (int t = 0; t < 4; t++) {
            int idx = tid + t * 256;
            int r = idx >> 3, c = idx & 7;
            int sw = c ^ (r & 7);
            uint32_t d = aOff + r * 128 + sw * 16;
            size_t g = (size_t)(rowBase + r) * lda + (k0 + c * 8);
            cpa(d, Agh + g);
            if (!LITE) cpa(d + 16384, Agl + g);
        }
        uint32_t bOff = aOff + APL * 16384;
        #pragma unroll
        for (int t = 0; t < 4; t++) {
            int idx = tid + t * 256;
            if (BLAY == 0) {
                int r = idx >> 4, c = idx & 15;
                int sw = c ^ (r & 7);
                uint32_t d = bOff + r * 256 + sw * 16;
                size_t g = (size_t)(k0 + r) * ldb + (colBase + c * 8);
                cpa(d, Bgh + g);
                if (!LITE) cpa(d + 16384, Bgl + g);
            } else {
                int r = idx >> 3, c = idx & 7;
                int sw = c ^ (r & 7);
                uint32_t d = bOff + r * 128 + sw * 16;
                size_t g = (size_t)(colBase + r) * ldb + (k0 + c * 8);
                cpa(d, Bgh + g);
                if (!LITE) cpa(d + 16384, Bgl + g);
            }
        }
    };

    auto computeStage = [&](int st) {
        uint32_t aHi = sbase + st * STG;
        uint32_t aLo = aHi + 16384;
        uint32_t bHi = aHi + APL * 16384;
        uint32_t bLo = bHi + 16384;
        #pragma unroll
        for (int ks = 0; ks < 4; ks++) {
            uint32_t af[2][4][4];
            uint32_t bfr[2][4][2];
            #pragma unroll
            for (int mt = 0; mt < 4; mt++) {
                int row = wm * 64 + mt * 16 + (lane & 15);
                int ch = ks * 2 + (lane >> 4);
                uint32_t ad = (uint32_t)(row * 128 + ((ch ^ (row & 7)) * 16));
                ldsm4(af[0][mt][0], af[0][mt][1], af[0][mt][2], af[0][mt][3], aHi + ad);
                if (!LITE)
                    ldsm4(af[1][mt][0], af[1][mt][1], af[1][mt][2], af[1][mt][3], aLo + ad);
            }
            #pragma unroll
            for (int i = 0; i < 2; i++) {
                if (BLAY == 0) {
                    int row = ks * 16 + ((lane >> 3) & 1) * 8 + (lane & 7);
                    int ch = wn * 4 + i * 2 + (lane >> 4);
                    uint32_t bd = (uint32_t)(row * 256 + ((ch ^ (row & 7)) * 16));
                    uint32_t r0, r1, r2, r3;
                    ldsm4t(r0, r1, r2, r3, bHi + bd);
                    bfr[0][2*i][0] = r0; bfr[0][2*i][1] = r1; bfr[0][2*i+1][0] = r2; bfr[0][2*i+1][1] = r3;
                    if (!LITE) {
                        ldsm4t(r0, r1, r2, r3, bLo + bd);
                        bfr[1][2*i][0] = r0; bfr[1][2*i][1] = r1; bfr[1][2*i+1][0] = r2; bfr[1][2*i+1][1] = r3;
                    }
                } else {
                    int row = wn * 32 + i * 16 + ((lane >> 4) << 3) + (lane & 7);
                    int ch = ks * 2 + ((lane >> 3) & 1);
                    uint32_t bd = (uint32_t)(row * 128 + ((ch ^ (row & 7)) * 16));
                    uint32_t r0, r1, r2, r3;
                    ldsm4(r0, r1, r2, r3, bHi + bd);
                    bfr[0][2*i][0] = r0; bfr[0][2*i][1] = r1; bfr[0][2*i+1][0] = r2; bfr[0][2*i+1][1] = r3;
                    if (!LITE) {
                        ldsm4(r0, r1, r2, r3, bLo + bd);
                        bfr[1][2*i][0] = r0; bfr[1][2*i][1] = r1; bfr[1][2*i+1][0] = r2; bfr[1][2*i+1][1] = r3;
                    }
                }
            }
            #pragma unroll
            for (int mt = 0; mt < 4; mt++)
                #pragma unroll
                for (int nt = 0; nt < 4; nt++) {
                    mma16816(acc[mt][nt], af[0][mt], bfr[0][nt]);
                    if (!LITE) {
                        mma16816(acc[mt][nt], af[0][mt], bfr[1][nt]);
                        mma16816(acc[mt][nt], af[1][mt], bfr[0][nt]);
                    }
                }
        }
    };

    const int nk = K >> 6;
    copyStage(0, 0);
    asm volatile("cp.async.commit_group;" ::: "memory");
    if (nk > 1) {
        copyStage(1, 64);
        asm volatile("cp.async.commit_group;" ::: "memory");
    }
    int st = 0;
    for (int kt = 0; kt < nk; kt++) {
        if (kt + 2 < nk) {
            int pst = st + 2; if (pst >= 3) pst -= 3;
            copyStage(pst, (kt + 2) * 64);
            asm volatile("cp.async.commit_group;" ::: "memory");
            asm volatile("cp.async.wait_group 2;" ::: "memory");
        } else if (kt + 1 < nk) {
            asm volatile("cp.async.wait_group 1;" ::: "memory");
        } else {
            asm volatile("cp.async.wait_group 0;" ::: "memory");
        }
        __syncthreads();
        computeStage(st);
        __syncthreads();
        if (++st == 3) st = 0;
    }

    if (EPI == 2) {
        // Column-max only (scores max pass)
        if (tid < 128) sRed[tid] = -1e30f;
        __syncthreads();
        #pragma unroll
        for (int nt = 0; nt < 4; nt++) {
            float cm0 = -1e30f, cm1 = -1e30f;
            #pragma unroll
            for (int mt = 0; mt < 4; mt++) {
                cm0 = fmaxf(cm0, fmaxf(acc[mt][nt][0], acc[mt][nt][2]));
                cm1 = fmaxf(cm1, fmaxf(acc[mt][nt][1], acc[mt][nt][3]));
            }
            int ci = wn * 32 + nt * 8 + (lane & 3) * 2;
            atomicMaxF(&sRed[ci], cm0);
            atomicMaxF(&sRed[ci + 1], cm1);
        }
        __syncthreads();
        if (tid < 128)
            atomicMaxF(Mx + (size_t)blockIdx.z * ldc + colBase + tid, sRed[tid]);
    } else if (EPI == 3) {
        // exp(s - M) -> fp16 E plane, column sums -> Z
        if (tid < 128) sRed[tid] = 0.f;
        __syncthreads();
        const float* Mrow = Mx + (size_t)blockIdx.z * ldc + colBase;
        __half* Eo = reinterpret_cast<__half*>(Ch) + zC;
        #pragma unroll
        for (int nt = 0; nt < 4; nt++) {
            int ci = wn * 32 + nt * 8 + (lane & 3) * 2;
            float m0 = Mrow[ci], m1 = Mrow[ci + 1];
            float z0 = 0.f, z1 = 0.f;
            #pragma unroll
            for (int mt = 0; mt < 4; mt++) {
                int r = rowBase + wm * 64 + mt * 16 + (lane >> 2);
                float e00 = __expf(acc[mt][nt][0] - m0);
                float e01 = __expf(acc[mt][nt][1] - m1);
                float e10 = __expf(acc[mt][nt][2] - m0);
                float e11 = __expf(acc[mt][nt][3] - m1);
                z0 += e00 + e10;
                z1 += e01 + e11;
                __half2 p0 = __floats2half2_rn(e00, e01);
                __half2 p1 = __floats2half2_rn(e10, e11);
                *reinterpret_cast<__half2*>(Eo + (size_t)r * ldc + colBase + ci) = p0;
                *reinterpret_cast<__half2*>(Eo + (size_t)(r + 8) * ldc + colBase + ci) = p1;
            }
            // reduce over the 8 lanes sharing these columns (stride-4 lane groups)
            #pragma unroll
            for (int off = 16; off >= 4; off >>= 1) {
                z0 += __shfl_down_sync(0xffffffffu, z0, off);
                z1 += __shfl_down_sync(0xffffffffu, z1, off);
            }
            if (lane < 4) {
                atomicAdd(&sRed[ci], z0);
                atomicAdd(&sRed[ci + 1], z1);
            }
        }
        __syncthreads();
        if (tid < 128)
            atomicAdd(Zp + (size_t)blockIdx.z * ldc + colBase + tid, sRed[tid]);
    } else {
        #pragma unroll
        for (int nt = 0; nt < 4; nt++) {
            #pragma unroll
            for (int mt = 0; mt < 4; mt++) {
                int r = rowBase + wm * 64 + mt * 16 + (lane >> 2);
                int c = colBase + wn * 32 + nt * 8 + (lane & 3) * 2;
                float b0 = 0.f, b1 = 0.f;
                if (bias) { b0 = bias[c]; b1 = bias[c + 1]; }
                float v00 = acc[mt][nt][0] + b0, v01 = acc[mt][nt][1] + b1;
                float v10 = acc[mt][nt][2] + b0, v11 = acc[mt][nt][3] + b1;
                if (EPI == 0) {
                    *reinterpret_cast<float2*>(Cf + zC + (size_t)r * ldc + c)       = make_float2(v00, v01);
                    *reinterpret_cast<float2*>(Cf + zC + (size_t)(r + 8) * ldc + c) = make_float2(v10, v11);
                } else {
                    uint32_t h, l;
                    split2(v00, v01, h, l);
                    *reinterpret_cast<uint32_t*>(Ch + zC + (size_t)r * ldc + c) = h;
                    *reinterpret_cast<uint32_t*>(Cl + zC + (size_t)r * ldc + c) = l;
                    split2(v10, v11, h, l);
                    *reinterpret_cast<uint32_t*>(Ch + zC + (size_t)(r + 8) * ldc + c) = h;
                    *reinterpret_cast<uint32_t*>(Cl + zC + (size_t)(r + 8) * ldc + c) = l;
                }
            }
        }
    }
}

// ---------------------------------------------------------------------------
// PV GEMM in fp16: X_h = E (fp16 single plane) @ V' (fp16 hi/lo planes).
// ---------------------------------------------------------------------------
#define PV_STAGE 49152
#define PV_SMEM  147456

__global__ __launch_bounds__(256) void pv_gemm(
    const __half* __restrict__ Ag,
    const __half* __restrict__ Bhg,
    const __half* __restrict__ Blg,
    bf16* __restrict__ Ch, bf16* __restrict__ Cl)
{
    extern __shared__ __align__(16) char smem[];
    const uint32_t sbase = (uint32_t)__cvta_generic_to_shared(smem);
    const int tid = threadIdx.x, lane = tid & 31, wid = tid >> 5;
    const int wm = wid >> 2, wn = wid & 3;
    const int rowBase = blockIdx.y * 128;
    const __half* A = Ag + (size_t)blockIdx.z * Ss * Ss;
    const __half* Bh = Bhg + (size_t)blockIdx.z * Ss * HD;
    const __half* Bl = Blg + (size_t)blockIdx.z * Ss * HD;
    const size_t zC = (size_t)blockIdx.z * Ss * HD;

    float acc[4][4][4] = {};

    auto copyStage = [&](int st, int k0) {
        uint32_t aOff = sbase + st * PV_STAGE;
        #pragma unroll
        for (int t = 0; t < 4; t++) {
            int idx = tid + t * 256;
            int r = idx >> 3, c = idx & 7;
            int sw = c ^ (r & 7);
            cpa(aOff + r * 128 + sw * 16, A + (size_t)(rowBase + r) * Ss + (k0 + c * 8));
        }
        uint32_t bOff = aOff + 16384;
        #pragma unroll
        for (int t = 0; t < 4; t++) {
            int idx = tid + t * 256;
            int r = idx >> 4, c = idx & 15;
            int sw = c ^ (r & 7);
            uint32_t d = bOff + r * 256 + sw * 16;
            size_t g = (size_t)(k0 + r) * HD + c * 8;
            cpa(d,         Bh + g);
            cpa(d + 16384, Bl + g);
        }
    };

    auto computeStage = [&](int st) {
        uint32_t aP  = sbase + st * PV_STAGE;
        uint32_t bHi = aP + 16384;
        uint32_t bLo = bHi + 16384;
        #pragma unroll
        for (int ks = 0; ks < 4; ks++) {
            uint32_t af[4][4];
            uint32_t bfr[2][4][2];
            #pragma unroll
            for (int mt = 0; mt < 4; mt++) {
                int row = wm * 64 + mt * 16 + (lane & 15);
                int ch = ks * 2 + (lane >> 4);
                uint32_t ad = (uint32_t)(row * 128 + ((ch ^ (row & 7)) * 16));
                ldsm4(af[mt][0], af[mt][1], af[mt][2], af[mt][3], aP + ad);
            }
            #pragma unroll
            for (int i = 0; i < 2; i++) {
                int row = ks * 16 + ((lane >> 3) & 1) * 8 + (lane & 7);
                int ch = wn * 4 + i * 2 + (lane >> 4);
                uint32_t bd = (uint32_t)(row * 256 + ((ch ^ (row & 7)) * 16));
                uint32_t r0, r1, r2, r3;
                ldsm4t(r0, r1, r2, r3, bHi + bd);
                bfr[0][2*i][0] = r0; bfr[0][2*i][1] = r1; bfr[0][2*i+1][0] = r2; bfr[0][2*i+1][1] = r3;
                ldsm4t(r0, r1, r2, r3, bLo + bd);
                bfr[1][2*i][0] = r0; bfr[1][2*i][1] = r1; bfr[1][2*i+1][0] = r2; bfr[1][2*i+1][1] = r3;
            }
            #pragma unroll
            for (int mt = 0; mt < 4; mt++)
                #pragma unroll
                for (int nt = 0; nt < 4; nt++) {
                    mma16816h(acc[mt][nt], af[mt], bfr[0][nt]);
                    mma16816h(acc[mt][nt], af[mt], bfr[1][nt]);
                }
        }
    };

    const int nk = Ss >> 6;   // 32
    copyStage(0, 0);
    asm volatile("cp.async.commit_group;" ::: "memory");
    copyStage(1, 64);
    asm volatile("cp.async.commit_group;" ::: "memory");
    int st = 0;
    for (int kt = 0; kt < nk; kt++) {
        if (kt + 2 < nk) {
            int pst = st + 2; if (pst >= 3) pst -= 3;
            copyStage(pst, (kt + 2) * 64);
            asm volatile("cp.async.commit_group;" ::: "memory");
            asm volatile("cp.async.wait_group 2;" ::: "memory");
        } else if (kt + 1 < nk) {
            asm volatile("cp.async.wait_group 1;" ::: "memory");
        } else {
            asm volatile("cp.async.wait_group 0;" ::: "memory");
        }
        __syncthreads();
        computeStage(st);
        __syncthreads();
        if (++st == 3) st = 0;
    }

    #pragma unroll
    for (int mt = 0; mt < 4; mt++) {
        #pragma unroll
        for (int nt = 0; nt < 4; nt++) {
            int r = rowBase + wm * 64 + mt * 16 + (lane >> 2);
            int c = wn * 32 + nt * 8 + (lane & 3) * 2;
            uint32_t h, l;
            split2(acc[mt][nt][0], acc[mt][nt][1], h, l);
            *reinterpret_cast<uint32_t*>(Ch + zC + (size_t)r * HD + c) = h;
            *reinterpret_cast<uint32_t*>(Cl + zC + (size_t)r * HD + c) = l;
            split2(acc[mt][nt][2], acc[mt][nt][3], h, l);
            *reinterpret_cast<uint32_t*>(Ch + zC + (size_t)(r + 8) * HD + c) = h;
            *reinterpret_cast<uint32_t*>(Cl + zC + (size_t)(r + 8) * HD + c) = l;
        }
    }
}

// ---------------------------------------------------------------------------
// V'[k,d] = V[k,d]/Z[k] -> fp16 hi/lo
// ---------------------------------------------------------------------------
__global__ __launch_bounds__(256) void vscale_kernel(const bf16* __restrict__ Vh, const bf16* __restrict__ Vl,
                                                     const float* __restrict__ Z,
                                                     __half* __restrict__ Voh, __half* __restrict__ Vol)
{
    size_t i = (size_t)blockIdx.x * 256 + threadIdx.x;   // over 8M elements
    size_t kz = i >> 7;                                   // z*Ss + k  (HD = 128)
    float inv = __fdividef(1.0f, Z[kz]);
    float v = (__bfloat162float(Vh[i]) + __bfloat162float(Vl[i])) * inv;
    __half h = __float2half_rn(v);
    __half l = __float2half_rn(v - __half2float(h));
    Voh[i] = h;
    Vol[i] = l;
}

// ---------------------------------------------------------------------------
// Launch
// ---------------------------------------------------------------------------
extern "C" void kernel_launch(void* const* d_in, const int* in_sizes, int n_in,
                              void* d_out, int out_size)
{
    const float* query = (const float*)d_in[0];
    const float* key   = (const float*)d_in[1];
    const float* value = (const float*)d_in[2];
    const float* Wq    = (const float*)d_in[3];
    const float* bq    = (const float*)d_in[4];
    const float* Wk    = (const float*)d_in[5];
    const float* bk    = (const float*)d_in[6];
    const float* Wv    = (const float*)d_in[7];
    const float* bv    = (const float*)d_in[8];
    const float* Wo    = (const float*)d_in[9];
    const float* bo    = (const float*)d_in[10];
    float* out = (float*)d_out;

    #define SYM(p, s) do { void* tmp_; cudaGetSymbolAddress(&tmp_, s); p = (decltype(p))tmp_; } while (0)
    bf16 *iqh, *iql, *ikh, *ikl, *ivh, *ivl;
    bf16 *wqh, *wql, *wkh, *wkl, *wvh, *wvl, *woh, *wol;
    bf16 *Qh, *Ql, *Kh, *Kl, *Vh, *Vl, *Xh, *Xl;
    __half *Ep, *Voh, *Vol;
    float *Mxp, *Zp;
    SYM(iqh, g_iq_h); SYM(iql, g_iq_l); SYM(ikh, g_ik_h); SYM(ikl, g_ik_l);
    SYM(ivh, g_iv_h); SYM(ivl, g_iv_l);
    SYM(wqh, g_wq_h); SYM(wql, g_wq_l); SYM(wkh, g_wk_h); SYM(wkl, g_wk_l);
    SYM(wvh, g_wv_h); SYM(wvl, g_wv_l); SYM(woh, g_wo_h); SYM(wol, g_wo_l);
    SYM(Qh, g_Q_h); SYM(Ql, g_Q_l); SYM(Kh, g_K_h); SYM(Kl, g_K_l);
    SYM(Vh, g_V_h); SYM(Vl, g_V_l); SYM(Voh, g_Vo_h); SYM(Vol, g_Vo_l);
    SYM(Xh, g_X_h); SYM(Xl, g_X_l); SYM(Ep, g_E);
    SYM(Mxp, g_Mx); SYM(Zp, g_Z);
    #undef SYM

    const int SM_FULL = 1024 + 3 * 65536;   // 197632
    const int SM_LITE = 1024 + 3 * 32768;   // 99328
    cudaFuncSetAttribute(mma_gemm<0, 0, 0>, cudaFuncAttributeMaxDynamicSharedMemorySize, SM_FULL);
    cudaFuncSetAttribute(mma_gemm<0, 1, 0>, cudaFuncAttributeMaxDynamicSharedMemorySize, SM_FULL);
    cudaFuncSetAttribute(mma_gemm<1, 2, 1>, cudaFuncAttributeMaxDynamicSharedMemorySize, SM_LITE);
    cudaFuncSetAttribute(mma_gemm<1, 3, 0>, cudaFuncAttributeMaxDynamicSharedMemorySize, SM_FULL);
    cudaFuncSetAttribute(pv_gemm, cudaFuncAttributeMaxDynamicSharedMemorySize, PV_SMEM);

    // 0) Re-init Mx (-inf) and Z (0) — graph-replay safe
    init_mz<<<(BH * Ss) / 256, 256>>>(Mxp, Zp);

    // 1) Split fp32 inputs/weights into bf16 hi/lo planes
    {
        int n4i = (int)(NELEM / 4), n4w = (int)(WELEM / 4);
        split_f32<<<n4i / 256, 256>>>((const float4*)query, (uint2*)iqh, (uint2*)iql, n4i);
        split_f32<<<n4i / 256, 256>>>((const float4*)key,   (uint2*)ikh, (uint2*)ikl, n4i);
        split_f32<<<n4i / 256, 256>>>((const float4*)value, (uint2*)ivh, (uint2*)ivl, n4i);
        split_f32<<<n4w / 256, 256>>>((const float4*)Wq, (uint2*)wqh, (uint2*)wql, n4w);
        split_f32<<<n4w / 256, 256>>>((const float4*)Wk, (uint2*)wkh, (uint2*)wkl, n4w);
        split_f32<<<n4w / 256, 256>>>((const float4*)Wv, (uint2*)wvh, (uint2*)wvl, n4w);
        split_f32<<<n4w / 256, 256>>>((const float4*)Wo, (uint2*)woh, (uint2*)wol, n4w);
    }

    // 2) QKV projections: [8192,1024] @ [1024,1024] + bias -> hi/lo planes
    {
        dim3 grid(Dd / 128, MROWS / 128, 1);
        mma_gemm<0, 1, 0><<<grid, 256, SM_FULL>>>(iqh, iql, wqh, wql, bq, nullptr, Qh, Ql,
                                                  nullptr, nullptr, Dd, Dd, Dd, Dd, 0, 0, 0);
        mma_gemm<0, 1, 0><<<grid, 256, SM_FULL>>>(ikh, ikl, wkh, wkl, bk, nullptr, Kh, Kl,
                                                  nullptr, nullptr, Dd, Dd, Dd, Dd, 0, 0, 0);
        mma_gemm<0, 1, 0><<<grid, 256, SM_FULL>>>(ivh, ivl, wvh, wvl, bv, nullptr, Vh, Vl,
                                                  nullptr, nullptr, Dd, Dd, Dd, Dd, 0, 0, 0);
    }

    // 3a) Scores max pass (1-product, hi planes, no store): Mx = colmax(Q_h @ K_h^T)
    {
        dim3 grid(Ss / 128, Ss / 128, BH);
        mma_gemm<1, 2, 1><<<grid, 256, SM_LITE>>>(Qh, nullptr, Kh, nullptr, nullptr,
                                                  nullptr, nullptr, nullptr, Mxp, nullptr,
                                                  HD, HD, HD, Ss,
                                                  (size_t)Ss * HD, (size_t)Ss * HD, 0);
    }

    // 3b) Scores full pass (3-product) + fused exp + Z: E = exp(S - Mx), Z = colsum(E)
    {
        dim3 grid(Ss / 128, Ss / 128, BH);
        mma_gemm<1, 3, 0><<<grid, 256, SM_FULL>>>(Qh, Ql, Kh, Kl, nullptr,
                                                  nullptr, (bf16*)Ep, nullptr, Mxp, Zp,
                                                  HD, HD, HD, Ss,
                                                  (size_t)Ss * HD, (size_t)Ss * HD, (size_t)Ss * Ss);
    }

    // 4) Fold 1/Z into V' (fp16 hi/lo)
    vscale_kernel<<<(unsigned)(NELEM / 256), 256>>>(Vh, Vl, Zp, Voh, Vol);

    // 5) PV per head (fp16): X_h = E[2048,2048] @ V'[2048,128]
    {
        dim3 grid(1, Ss / 128, BH);
        pv_gemm<<<grid, 256, PV_SMEM>>>(Ep, Voh, Vol, Xh, Xl);
    }

    // 6) Output projection: [8192,1024] @ Wo + bo -> fp32 out
    {
        dim3 grid(Dd / 128, MROWS / 128, 1);
        mma_gemm<0, 0, 0><<<grid, 256, SM_FULL>>>(Xh, Xl, woh, wol, bo, out, nullptr, nullptr,
                                                  nullptr, nullptr, Dd, Dd, Dd, Dd, 0, 0, 0);
    }
}

// round 10
// speedup vs baseline: 5.1107x; 1.1616x over previous
#include <cuda_runtime.h>
#include <cuda_bf16.h>
#include <cuda_fp16.h>
#include <cstdint>
#include <math.h>

// Problem constants
#define Bb 4
#define Ss 2048
#define Dd 1024
#define Hh 8
#define HD 128
#define BH (Bb*Hh)            // 32 head-slices
#define MROWS (Bb*Ss)         // 8192
#define NELEM ((size_t)MROWS * Dd)      // 8M
#define WELEM ((size_t)Dd * Dd)         // 1M
#define SELEM ((size_t)BH * Ss * Ss)    // 128M

typedef __nv_bfloat16 bf16;
typedef __nv_bfloat162 bf162;

// ---------------------------------------------------------------------------
// Device scratch (allocation-free rule: __device__ globals)
// ---------------------------------------------------------------------------
__device__ __align__(256) bf16 g_iq_h[NELEM], g_iq_l[NELEM];
__device__ __align__(256) bf16 g_ik_h[NELEM], g_ik_l[NELEM];
__device__ __align__(256) bf16 g_iv_h[NELEM], g_iv_l[NELEM];
__device__ __align__(256) bf16 g_wq_h[WELEM], g_wq_l[WELEM];
__device__ __align__(256) bf16 g_wk_h[WELEM], g_wk_l[WELEM];
__device__ __align__(256) bf16 g_wv_h[WELEM], g_wv_l[WELEM];
__device__ __align__(256) __half g_Wo16[WELEM];                 // Wo fp16 single
__device__ __align__(256) bf16 g_Q_h[NELEM],  g_Q_l[NELEM];
__device__ __align__(256) bf16 g_K_h[NELEM],  g_K_l[NELEM];
__device__ __align__(256) bf16 g_V_h[NELEM],  g_V_l[NELEM];
__device__ __align__(256) __half g_Vo[NELEM];                   // V' fp16 single
__device__ __align__(256) __half g_X16[NELEM];                  // X fp16 single
__device__ __align__(256) __half g_E[SELEM];                    // fp16 E plane
__device__ __align__(256) float g_Mx[(size_t)BH * Ss];
__device__ __align__(256) float g_Z [(size_t)BH * Ss];

// ---------------------------------------------------------------------------
// PTX helpers
// ---------------------------------------------------------------------------
__device__ __forceinline__ void cpa(uint32_t dst, const void* src) {
    asm volatile("cp.async.cg.shared.global [%0], [%1], 16;\n" :: "r"(dst), "l"(src));
}
__device__ __forceinline__ void ldsm4(uint32_t& r0, uint32_t& r1, uint32_t& r2, uint32_t& r3, uint32_t a) {
    asm volatile("ldmatrix.sync.aligned.m8n8.x4.shared.b16 {%0,%1,%2,%3}, [%4];"
                 : "=r"(r0), "=r"(r1), "=r"(r2), "=r"(r3) : "r"(a));
}
__device__ __forceinline__ void ldsm4t(uint32_t& r0, uint32_t& r1, uint32_t& r2, uint32_t& r3, uint32_t a) {
    asm volatile("ldmatrix.sync.aligned.m8n8.x4.trans.shared.b16 {%0,%1,%2,%3}, [%4];"
                 : "=r"(r0), "=r"(r1), "=r"(r2), "=r"(r3) : "r"(a));
}
__device__ __forceinline__ void mma16816(float* c, const uint32_t* a, const uint32_t* b) {
    asm volatile("mma.sync.aligned.m16n8k16.row.col.f32.bf16.bf16.f32 "
                 "{%0,%1,%2,%3},{%4,%5,%6,%7},{%8,%9},{%0,%1,%2,%3};"
                 : "+f"(c[0]), "+f"(c[1]), "+f"(c[2]), "+f"(c[3])
                 : "r"(a[0]), "r"(a[1]), "r"(a[2]), "r"(a[3]), "r"(b[0]), "r"(b[1]));
}
__device__ __forceinline__ void mma16816h(float* c, const uint32_t* a, const uint32_t* b) {
    asm volatile("mma.sync.aligned.m16n8k16.row.col.f32.f16.f16.f32 "
                 "{%0,%1,%2,%3},{%4,%5,%6,%7},{%8,%9},{%0,%1,%2,%3};"
                 : "+f"(c[0]), "+f"(c[1]), "+f"(c[2]), "+f"(c[3])
                 : "r"(a[0]), "r"(a[1]), "r"(a[2]), "r"(a[3]), "r"(b[0]), "r"(b[1]));
}
__device__ __forceinline__ uint32_t pack2(bf16 a, bf16 b) {
    bf162 t(a, b);
    return *reinterpret_cast<uint32_t*>(&t);
}
__device__ __forceinline__ void split2(float v0, float v1, uint32_t& hi, uint32_t& lo) {
    bf16 h0 = __float2bfloat16_rn(v0);
    bf16 h1 = __float2bfloat16_rn(v1);
    bf16 l0 = __float2bfloat16_rn(v0 - __bfloat162float(h0));
    bf16 l1 = __float2bfloat16_rn(v1 - __bfloat162float(h1));
    hi = pack2(h0, h1);
    lo = pack2(l0, l1);
}
__device__ __forceinline__ void atomicMaxF(float* addr, float v) {
    if (v >= 0.f) atomicMax((int*)addr, __float_as_int(v));
    else          atomicMin((unsigned int*)addr, (unsigned int)__float_as_int(v));
}

// ---------------------------------------------------------------------------
// Elementwise prep
// ---------------------------------------------------------------------------
__global__ __launch_bounds__(256) void split_f32(const float4* __restrict__ x,
                                                 uint2* __restrict__ hi, uint2* __restrict__ lo, int n4)
{
    int i = blockIdx.x * 256 + threadIdx.x;
    if (i >= n4) return;
    float4 v = x[i];
    uint32_t h01, l01, h23, l23;
    split2(v.x, v.y, h01, l01);
    split2(v.z, v.w, h23, l23);
    hi[i] = make_uint2(h01, h23);
    lo[i] = make_uint2(l01, l23);
}

__global__ __launch_bounds__(256) void cvt_f16(const float4* __restrict__ x,
                                               uint2* __restrict__ o, int n4)
{
    int i = blockIdx.x * 256 + threadIdx.x;
    if (i >= n4) return;
    float4 v = x[i];
    __half2 a = __floats2half2_rn(v.x, v.y);
    __half2 b = __floats2half2_rn(v.z, v.w);
    o[i] = make_uint2(*reinterpret_cast<uint32_t*>(&a), *reinterpret_cast<uint32_t*>(&b));
}

__global__ __launch_bounds__(256) void init_mz(float* __restrict__ Mx, float* __restrict__ Z)
{
    int i = blockIdx.x * 256 + threadIdx.x;   // BH*Ss = 65536
    Mx[i] = -1e30f;
    Z[i] = 0.f;
}

// ---------------------------------------------------------------------------
// MMA GEMM, 3-stage cp.async pipeline.
// BM=BN=128, BK=64, 256 threads (8 warps 2x4), warp tile 64x32.
// BLAY: 0 = B global [k][n], 1 = B global [n][k].
// EPI:  0 = fp32 out (+bias), 1 = hi/lo bf16 planes out,
//       2 = no store, column max -> Mx (atomicMaxF),
//       3 = exp(s - Mx) -> fp16 E plane + column sums Z (atomicAdd).
// LITE: 1 = hi planes only, 1 MMA product.
// FK:   0 = bf16 MMA, 1 = fp16 MMA (LITE path only).
// ---------------------------------------------------------------------------
template<int BLAY, int EPI, int LITE, int FK>
__global__ __launch_bounds__(256) void mma_gemm(
    const bf16* __restrict__ Ah, const bf16* __restrict__ Al,
    const bf16* __restrict__ Bh, const bf16* __restrict__ Bl,
    const float* __restrict__ bias,
    float* __restrict__ Cf, bf16* __restrict__ Ch, bf16* __restrict__ Cl,
    float* __restrict__ Mx, float* __restrict__ Zp,
    int K, int lda, int ldb, int ldc,
    size_t sA, size_t sB, size_t sC)
{
    constexpr int APL = LITE ? 1 : 2;
    constexpr int STG = APL * 16384 + (LITE ? 16384 : 32768);
    extern __shared__ __align__(16) char smem[];
    float* sRed = reinterpret_cast<float*>(smem);             // 128 floats scratch
    const uint32_t sbase = (uint32_t)__cvta_generic_to_shared(smem) + 1024;
    const int tid = threadIdx.x, lane = tid & 31, wid = tid >> 5;
    const int wm = wid >> 2, wn = wid & 3;
    const int rowBase = blockIdx.y * 128, colBase = blockIdx.x * 128;
    const bf16* Agh = Ah + (size_t)blockIdx.z * sA;
    const bf16* Agl = Al + (size_t)blockIdx.z * sA;
    const bf16* Bgh = Bh + (size_t)blockIdx.z * sB;
    const bf16* Bgl = Bl + (size_t)blockIdx.z * sB;
    const size_t zC = (size_t)blockIdx.z * sC;

    float acc[4][4][4] = {};

    auto copyStage = [&](int st, int k0) {
        uint32_t aOff = sbase + st * STG;
        #pragma unroll
        for (int t = 0; t < 4; t++) {
            int idx = tid + t * 256;
            int r = idx >> 3, c = idx & 7;
            int sw = c ^ (r & 7);
            uint32_t d = aOff + r * 128 + sw * 16;
            size_t g = (size_t)(rowBase + r) * lda + (k0 + c * 8);
            cpa(d, Agh + g);
            if (!LITE) cpa(d + 16384, Agl + g);
        }
        uint32_t bOff = aOff + APL * 16384;
        #pragma unroll
        for (int t = 0; t < 4; t++) {
            int idx = tid + t * 256;
            if (BLAY == 0) {
                int r = idx >> 4, c = idx & 15;
                int sw = c ^ (r & 7);
                uint32_t d = bOff + r * 256 + sw * 16;
                size_t g = (size_t)(k0 + r) * ldb + (colBase + c * 8);
                cpa(d, Bgh + g);
                if (!LITE) cpa(d + 16384, Bgl + g);
            } else {
                int r = idx >> 3, c = idx & 7;
                int sw = c ^ (r & 7);
                uint32_t d = bOff + r * 128 + sw * 16;
                size_t g = (size_t)(colBase + r) * ldb + (k0 + c * 8);
                cpa(d, Bgh + g);
                if (!LITE) cpa(d + 16384, Bgl + g);
            }
        }
    };

    auto computeStage = [&](int st) {
        uint32_t aHi = sbase + st * STG;
        uint32_t aLo = aHi + 16384;
        uint32_t bHi = aHi + APL * 16384;
        uint32_t bLo = bHi + 16384;
        #pragma unroll
        for (int ks = 0; ks < 4; ks++) {
            uint32_t af[2][4][4];
            uint32_t bfr[2][4][2];
            #pragma unroll
            for (int mt = 0; mt < 4; mt++) {
                int row = wm * 64 + mt * 16 + (lane & 15);
                int ch = ks * 2 + (lane >> 4);
                uint32_t ad = (uint32_t)(row * 128 + ((ch ^ (row & 7)) * 16));
                ldsm4(af[0][mt][0], af[0][mt][1], af[0][mt][2], af[0][mt][3], aHi + ad);
                if (!LITE)
                    ldsm4(af[1][mt][0], af[1][mt][1], af[1][mt][2], af[1][mt][3], aLo + ad);
            }
            #pragma unroll
            for (int i = 0; i < 2; i++) {
                if (BLAY == 0) {
                    int row = ks * 16 + ((lane >> 3) & 1) * 8 + (lane & 7);
                    int ch = wn * 4 + i * 2 + (lane >> 4);
                    uint32_t bd = (uint32_t)(row * 256 + ((ch ^ (row & 7)) * 16));
                    uint32_t r0, r1, r2, r3;
                    ldsm4t(r0, r1, r2, r3, bHi + bd);
                    bfr[0][2*i][0] = r0; bfr[0][2*i][1] = r1; bfr[0][2*i+1][0] = r2; bfr[0][2*i+1][1] = r3;
                    if (!LITE) {
                        ldsm4t(r0, r1, r2, r3, bLo + bd);
                        bfr[1][2*i][0] = r0; bfr[1][2*i][1] = r1; bfr[1][2*i+1][0] = r2; bfr[1][2*i+1][1] = r3;
                    }
                } else {
                    int row = wn * 32 + i * 16 + ((lane >> 4) << 3) + (lane & 7);
                    int ch = ks * 2 + ((lane >> 3) & 1);
                    uint32_t bd = (uint32_t)(row * 128 + ((ch ^ (row & 7)) * 16));
                    uint32_t r0, r1, r2, r3;
                    ldsm4(r0, r1, r2, r3, bHi + bd);
                    bfr[0][2*i][0] = r0; bfr[0][2*i][1] = r1; bfr[0][2*i+1][0] = r2; bfr[0][2*i+1][1] = r3;
                    if (!LITE) {
                        ldsm4(r0, r1, r2, r3, bLo + bd);
                        bfr[1][2*i][0] = r0; bfr[1][2*i][1] = r1; bfr[1][2*i+1][0] = r2; bfr[1][2*i+1][1] = r3;
                    }
                }
            }
            #pragma unroll
            for (int mt = 0; mt < 4; mt++)
                #pragma unroll
                for (int nt = 0; nt < 4; nt++) {
                    if (FK) mma16816h(acc[mt][nt], af[0][mt], bfr[0][nt]);
                    else    mma16816(acc[mt][nt], af[0][mt], bfr[0][nt]);
                    if (!LITE) {
                        mma16816(acc[mt][nt], af[0][mt], bfr[1][nt]);
                        mma16816(acc[mt][nt], af[1][mt], bfr[0][nt]);
                    }
                }
        }
    };

    const int nk = K >> 6;
    copyStage(0, 0);
    asm volatile("cp.async.commit_group;" ::: "memory");
    if (nk > 1) {
        copyStage(1, 64);
        asm volatile("cp.async.commit_group;" ::: "memory");
    }
    int st = 0;
    for (int kt = 0; kt < nk; kt++) {
        if (kt + 2 < nk) {
            int pst = st + 2; if (pst >= 3) pst -= 3;
            copyStage(pst, (kt + 2) * 64);
            asm volatile("cp.async.commit_group;" ::: "memory");
            asm volatile("cp.async.wait_group 2;" ::: "memory");
        } else if (kt + 1 < nk) {
            asm volatile("cp.async.wait_group 1;" ::: "memory");
        } else {
            asm volatile("cp.async.wait_group 0;" ::: "memory");
        }
        __syncthreads();
        computeStage(st);
        __syncthreads();
        if (++st == 3) st = 0;
    }

    if (EPI == 2) {
        // Column-max only (scores max pass)
        if (tid < 128) sRed[tid] = -1e30f;
        __syncthreads();
        #pragma unroll
        for (int nt = 0; nt < 4; nt++) {
            float cm0 = -1e30f, cm1 = -1e30f;
            #pragma unroll
            for (int mt = 0; mt < 4; mt++) {
                cm0 = fmaxf(cm0, fmaxf(acc[mt][nt][0], acc[mt][nt][2]));
                cm1 = fmaxf(cm1, fmaxf(acc[mt][nt][1], acc[mt][nt][3]));
            }
            int ci = wn * 32 + nt * 8 + (lane & 3) * 2;
            atomicMaxF(&sRed[ci], cm0);
            atomicMaxF(&sRed[ci + 1], cm1);
        }
        __syncthreads();
        if (tid < 128)
            atomicMaxF(Mx + (size_t)blockIdx.z * ldc + colBase + tid, sRed[tid]);
    } else if (EPI == 3) {
        // exp(s - M) -> fp16 E plane, column sums -> Z
        if (tid < 128) sRed[tid] = 0.f;
        __syncthreads();
        const float* Mrow = Mx + (size_t)blockIdx.z * ldc + colBase;
        __half* Eo = reinterpret_cast<__half*>(Ch) + zC;
        #pragma unroll
        for (int nt = 0; nt < 4; nt++) {
            int ci = wn * 32 + nt * 8 + (lane & 3) * 2;
            float m0 = Mrow[ci], m1 = Mrow[ci + 1];
            float z0 = 0.f, z1 = 0.f;
            #pragma unroll
            for (int mt = 0; mt < 4; mt++) {
                int r = rowBase + wm * 64 + mt * 16 + (lane >> 2);
                float e00 = __expf(acc[mt][nt][0] - m0);
                float e01 = __expf(acc[mt][nt][1] - m1);
                float e10 = __expf(acc[mt][nt][2] - m0);
                float e11 = __expf(acc[mt][nt][3] - m1);
                z0 += e00 + e10;
                z1 += e01 + e11;
                __half2 p0 = __floats2half2_rn(e00, e01);
                __half2 p1 = __floats2half2_rn(e10, e11);
                *reinterpret_cast<__half2*>(Eo + (size_t)r * ldc + colBase + ci) = p0;
                *reinterpret_cast<__half2*>(Eo + (size_t)(r + 8) * ldc + colBase + ci) = p1;
            }
            #pragma unroll
            for (int off = 16; off >= 4; off >>= 1) {
                z0 += __shfl_down_sync(0xffffffffu, z0, off);
                z1 += __shfl_down_sync(0xffffffffu, z1, off);
            }
            if (lane < 4) {
                atomicAdd(&sRed[ci], z0);
                atomicAdd(&sRed[ci + 1], z1);
            }
        }
        __syncthreads();
        if (tid < 128)
            atomicAdd(Zp + (size_t)blockIdx.z * ldc + colBase + tid, sRed[tid]);
    } else {
        #pragma unroll
        for (int nt = 0; nt < 4; nt++) {
            #pragma unroll
            for (int mt = 0; mt < 4; mt++) {
                int r = rowBase + wm * 64 + mt * 16 + (lane >> 2);
                int c = colBase + wn * 32 + nt * 8 + (lane & 3) * 2;
                float b0 = 0.f, b1 = 0.f;
                if (bias) { b0 = bias[c]; b1 = bias[c + 1]; }
                float v00 = acc[mt][nt][0] + b0, v01 = acc[mt][nt][1] + b1;
                float v10 = acc[mt][nt][2] + b0, v11 = acc[mt][nt][3] + b1;
                if (EPI == 0) {
                    *reinterpret_cast<float2*>(Cf + zC + (size_t)r * ldc + c)       = make_float2(v00, v01);
                    *reinterpret_cast<float2*>(Cf + zC + (size_t)(r + 8) * ldc + c) = make_float2(v10, v11);
                } else {
                    uint32_t h, l;
                    split2(v00, v01, h, l);
                    *reinterpret_cast<uint32_t*>(Ch + zC + (size_t)r * ldc + c) = h;
                    *reinterpret_cast<uint32_t*>(Cl + zC + (size_t)r * ldc + c) = l;
                    split2(v10, v11, h, l);
                    *reinterpret_cast<uint32_t*>(Ch + zC + (size_t)(r + 8) * ldc + c) = h;
                    *reinterpret_cast<uint32_t*>(Cl + zC + (size_t)(r + 8) * ldc + c) = l;
                }
            }
        }
    }
}

// ---------------------------------------------------------------------------
// PV GEMM fp16, 1 product: X_h = E (fp16) @ V' (fp16 single plane).
// Output X as single fp16 plane.
// ---------------------------------------------------------------------------
#define PV_STAGE 32768
#define PV_SMEM  98304

__global__ __launch_bounds__(256) void pv_gemm(
    const __half* __restrict__ Ag,
    const __half* __restrict__ Bg,
    __half* __restrict__ Co)
{
    extern __shared__ __align__(16) char smem[];
    const uint32_t sbase = (uint32_t)__cvta_generic_to_shared(smem);
    const int tid = threadIdx.x, lane = tid & 31, wid = tid >> 5;
    const int wm = wid >> 2, wn = wid & 3;
    const int rowBase = blockIdx.y * 128;
    const __half* A = Ag + (size_t)blockIdx.z * Ss * Ss;
    const __half* B = Bg + (size_t)blockIdx.z * Ss * HD;
    const size_t zC = (size_t)blockIdx.z * Ss * HD;

    float acc[4][4][4] = {};

    auto copyStage = [&](int st, int k0) {
        uint32_t aOff = sbase + st * PV_STAGE;
        #pragma unroll
        for (int t = 0; t < 4; t++) {
            int idx = tid + t * 256;
            int r = idx >> 3, c = idx & 7;
            int sw = c ^ (r & 7);
            cpa(aOff + r * 128 + sw * 16, A + (size_t)(rowBase + r) * Ss + (k0 + c * 8));
        }
        uint32_t bOff = aOff + 16384;
        #pragma unroll
        for (int t = 0; t < 4; t++) {     // full 64-row B tile
            int idx = tid + t * 256;
            int r = idx >> 4, c = idx & 15;
            int sw = c ^ (r & 7);
            cpa(bOff + r * 256 + sw * 16, B + (size_t)(k0 + r) * HD + c * 8);
        }
    };

    auto computeStage = [&](int st) {
        uint32_t aP  = sbase + st * PV_STAGE;
        uint32_t bP  = aP + 16384;
        #pragma unroll
        for (int ks = 0; ks < 4; ks++) {
            uint32_t af[4][4];
            uint32_t bfr[4][2];
            #pragma unroll
            for (int mt = 0; mt < 4; mt++) {
                int row = wm * 64 + mt * 16 + (lane & 15);
                int ch = ks * 2 + (lane >> 4);
                uint32_t ad = (uint32_t)(row * 128 + ((ch ^ (row & 7)) * 16));
                ldsm4(af[mt][0], af[mt][1], af[mt][2], af[mt][3], aP + ad);
            }
            #pragma unroll
            for (int i = 0; i < 2; i++) {
                int row = ks * 16 + ((lane >> 3) & 1) * 8 + (lane & 7);
                int ch = wn * 4 + i * 2 + (lane >> 4);
                uint32_t bd = (uint32_t)(row * 256 + ((ch ^ (row & 7)) * 16));
                uint32_t r0, r1, r2, r3;
                ldsm4t(r0, r1, r2, r3, bP + bd);
                bfr[2*i][0] = r0; bfr[2*i][1] = r1; bfr[2*i+1][0] = r2; bfr[2*i+1][1] = r3;
            }
            #pragma unroll
            for (int mt = 0; mt < 4; mt++)
                #pragma unroll
                for (int nt = 0; nt < 4; nt++)
                    mma16816h(acc[mt][nt], af[mt], bfr[nt]);
        }
    };

    const int nk = Ss >> 6;   // 32
    copyStage(0, 0);
    asm volatile("cp.async.commit_group;" ::: "memory");
    copyStage(1, 64);
    asm volatile("cp.async.commit_group;" ::: "memory");
    int st = 0;
    for (int kt = 0; kt < nk; kt++) {
        if (kt + 2 < nk) {
            int pst = st + 2; if (pst >= 3) pst -= 3;
            copyStage(pst, (kt + 2) * 64);
            asm volatile("cp.async.commit_group;" ::: "memory");
            asm volatile("cp.async.wait_group 2;" ::: "memory");
        } else if (kt + 1 < nk) {
            asm volatile("cp.async.wait_group 1;" ::: "memory");
        } else {
            asm volatile("cp.async.wait_group 0;" ::: "memory");
        }
        __syncthreads();
        computeStage(st);
        __syncthreads();
        if (++st == 3) st = 0;
    }

    #pragma unroll
    for (int mt = 0; mt < 4; mt++) {
        #pragma unroll
        for (int nt = 0; nt < 4; nt++) {
            int r = rowBase + wm * 64 + mt * 16 + (lane >> 2);
            int c = wn * 32 + nt * 8 + (lane & 3) * 2;
            __half2 p0 = __floats2half2_rn(acc[mt][nt][0], acc[mt][nt][1]);
            __half2 p1 = __floats2half2_rn(acc[mt][nt][2], acc[mt][nt][3]);
            *reinterpret_cast<__half2*>(Co + zC + (size_t)r * HD + c) = p0;
            *reinterpret_cast<__half2*>(Co + zC + (size_t)(r + 8) * HD + c) = p1;
        }
    }
}

// ---------------------------------------------------------------------------
// V'[k,d] = V[k,d]/Z[k] -> fp16 single plane
// ---------------------------------------------------------------------------
__global__ __launch_bounds__(256) void vscale_kernel(const bf16* __restrict__ Vh, const bf16* __restrict__ Vl,
                                                     const float* __restrict__ Z,
                                                     __half* __restrict__ Vo)
{
    size_t i = (size_t)blockIdx.x * 256 + threadIdx.x;   // over 8M elements
    size_t kz = i >> 7;                                   // z*Ss + k  (HD = 128)
    float inv = __fdividef(1.0f, Z[kz]);
    float v = (__bfloat162float(Vh[i]) + __bfloat162float(Vl[i])) * inv;
    Vo[i] = __float2half_rn(v);
}

// ---------------------------------------------------------------------------
// Launch
// ---------------------------------------------------------------------------
extern "C" void kernel_launch(void* const* d_in, const int* in_sizes, int n_in,
                              void* d_out, int out_size)
{
    const float* query = (const float*)d_in[0];
    const float* key   = (const float*)d_in[1];
    const float* value = (const float*)d_in[2];
    const float* Wq    = (const float*)d_in[3];
    const float* bq    = (const float*)d_in[4];
    const float* Wk    = (const float*)d_in[5];
    const float* bk    = (const float*)d_in[6];
    const float* Wv    = (const float*)d_in[7];
    const float* bv    = (const float*)d_in[8];
    const float* Wo    = (const float*)d_in[9];
    const float* bo    = (const float*)d_in[10];
    float* out = (float*)d_out;

    #define SYM(p, s) do { void* tmp_; cudaGetSymbolAddress(&tmp_, s); p = (decltype(p))tmp_; } while (0)
    bf16 *iqh, *iql, *ikh, *ikl, *ivh, *ivl;
    bf16 *wqh, *wql, *wkh, *wkl, *wvh, *wvl;
    bf16 *Qh, *Ql, *Kh, *Kl, *Vh, *Vl;
    __half *Wo16, *Ep, *Vop, *X16;
    float *Mxp, *Zp;
    SYM(iqh, g_iq_h); SYM(iql, g_iq_l); SYM(ikh, g_ik_h); SYM(ikl, g_ik_l);
    SYM(ivh, g_iv_h); SYM(ivl, g_iv_l);
    SYM(wqh, g_wq_h); SYM(wql, g_wq_l); SYM(wkh, g_wk_h); SYM(wkl, g_wk_l);
    SYM(wvh, g_wv_h); SYM(wvl, g_wv_l); SYM(Wo16, g_Wo16);
    SYM(Qh, g_Q_h); SYM(Ql, g_Q_l); SYM(Kh, g_K_h); SYM(Kl, g_K_l);
    SYM(Vh, g_V_h); SYM(Vl, g_V_l); SYM(Vop, g_Vo); SYM(X16, g_X16);
    SYM(Ep, g_E); SYM(Mxp, g_Mx); SYM(Zp, g_Z);
    #undef SYM

    const int SM_FULL = 1024 + 3 * 65536;   // 197632
    const int SM_LITE = 1024 + 3 * 32768;   // 99328
    cudaFuncSetAttribute(mma_gemm<0, 1, 0, 0>, cudaFuncAttributeMaxDynamicSharedMemorySize, SM_FULL);
    cudaFuncSetAttribute(mma_gemm<1, 2, 1, 0>, cudaFuncAttributeMaxDynamicSharedMemorySize, SM_LITE);
    cudaFuncSetAttribute(mma_gemm<1, 3, 0, 0>, cudaFuncAttributeMaxDynamicSharedMemorySize, SM_FULL);
    cudaFuncSetAttribute(mma_gemm<0, 0, 1, 1>, cudaFuncAttributeMaxDynamicSharedMemorySize, SM_LITE);
    cudaFuncSetAttribute(pv_gemm, cudaFuncAttributeMaxDynamicSharedMemorySize, PV_SMEM);

    // 0) Re-init Mx (-inf) and Z (0) — graph-replay safe
    init_mz<<<(BH * Ss) / 256, 256>>>(Mxp, Zp);

    // 1) Split fp32 inputs/weights into planes
    {
        int n4i = (int)(NELEM / 4), n4w = (int)(WELEM / 4);
        split_f32<<<n4i / 256, 256>>>((const float4*)query, (uint2*)iqh, (uint2*)iql, n4i);
        split_f32<<<n4i / 256, 256>>>((const float4*)key,   (uint2*)ikh, (uint2*)ikl, n4i);
        split_f32<<<n4i / 256, 256>>>((const float4*)value, (uint2*)ivh, (uint2*)ivl, n4i);
        split_f32<<<n4w / 256, 256>>>((const float4*)Wq, (uint2*)wqh, (uint2*)wql, n4w);
        split_f32<<<n4w / 256, 256>>>((const float4*)Wk, (uint2*)wkh, (uint2*)wkl, n4w);
        split_f32<<<n4w / 256, 256>>>((const float4*)Wv, (uint2*)wvh, (uint2*)wvl, n4w);
        cvt_f16<<<n4w / 256, 256>>>((const float4*)Wo, (uint2*)Wo16, n4w);
    }

    // 2) QKV projections (bf16x3): [8192,1024] @ [1024,1024] + bias -> hi/lo planes
    {
        dim3 grid(Dd / 128, MROWS / 128, 1);
        mma_gemm<0, 1, 0, 0><<<grid, 256, SM_FULL>>>(iqh, iql, wqh, wql, bq, nullptr, Qh, Ql,
                                                     nullptr, nullptr, Dd, Dd, Dd, Dd, 0, 0, 0);
        mma_gemm<0, 1, 0, 0><<<grid, 256, SM_FULL>>>(ikh, ikl, wkh, wkl, bk, nullptr, Kh, Kl,
                                                     nullptr, nullptr, Dd, Dd, Dd, Dd, 0, 0, 0);
        mma_gemm<0, 1, 0, 0><<<grid, 256, SM_FULL>>>(ivh, ivl, wvh, wvl, bv, nullptr, Vh, Vl,
                                                     nullptr, nullptr, Dd, Dd, Dd, Dd, 0, 0, 0);
    }

    // 3a) Scores max pass (1-product, hi planes, no store): Mx = colmax(Q_h @ K_h^T)
    {
        dim3 grid(Ss / 128, Ss / 128, BH);
        mma_gemm<1, 2, 1, 0><<<grid, 256, SM_LITE>>>(Qh, nullptr, Kh, nullptr, nullptr,
                                                     nullptr, nullptr, nullptr, Mxp, nullptr,
                                                     HD, HD, HD, Ss,
                                                     (size_t)Ss * HD, (size_t)Ss * HD, 0);
    }

    // 3b) Scores full pass (3-product) + fused exp + Z: E = exp(S - Mx), Z = colsum(E)
    {
        dim3 grid(Ss / 128, Ss / 128, BH);
        mma_gemm<1, 3, 0, 0><<<grid, 256, SM_FULL>>>(Qh, Ql, Kh, Kl, nullptr,
                                                     nullptr, (bf16*)Ep, nullptr, Mxp, Zp,
                                                     HD, HD, HD, Ss,
                                                     (size_t)Ss * HD, (size_t)Ss * HD, (size_t)Ss * Ss);
    }

    // 4) Fold 1/Z into V' (fp16 single plane)
    vscale_kernel<<<(unsigned)(NELEM / 256), 256>>>(Vh, Vl, Zp, Vop);

    // 5) PV per head (fp16 1-product): X_h = E[2048,2048] @ V'[2048,128] -> fp16
    {
        dim3 grid(1, Ss / 128, BH);
        pv_gemm<<<grid, 256, PV_SMEM>>>(Ep, Vop, X16);
    }

    // 6) Output projection (fp16 1-product): [8192,1024] @ Wo16 + bo -> fp32 out
    {
        dim3 grid(Dd / 128, MROWS / 128, 1);
        mma_gemm<0, 0, 1, 1><<<grid, 256, SM_LITE>>>((const bf16*)X16, nullptr,
                                                     (const bf16*)Wo16, nullptr, bo,
                                                     out, nullptr, nullptr,
                                                     nullptr, nullptr, Dd, Dd, Dd, Dd, 0, 0, 0);
    }
}

// round 11
// speedup vs baseline: 5.5706x; 1.0900x over previous
#include <cuda_runtime.h>
#include <cuda_bf16.h>
#include <cuda_fp16.h>
#include <cstdint>
#include <math.h>

// Problem constants
#define Bb 4
#define Ss 2048
#define Dd 1024
#define Hh 8
#define HD 128
#define BH (Bb*Hh)            // 32 head-slices
#define MROWS (Bb*Ss)         // 8192
#define NELEM ((size_t)MROWS * Dd)      // 8M
#define WELEM ((size_t)Dd * Dd)         // 1M
#define SELEM ((size_t)BH * Ss * Ss)    // 128M

typedef __nv_bfloat16 bf16;
typedef __nv_bfloat162 bf162;

// ---------------------------------------------------------------------------
// Device scratch (allocation-free rule: __device__ globals)
// ---------------------------------------------------------------------------
__device__ __align__(256) bf16 g_iq_h[NELEM], g_iq_l[NELEM];
__device__ __align__(256) bf16 g_ik_h[NELEM], g_ik_l[NELEM];
__device__ __align__(256) __half g_iv16[NELEM];                 // value fp16 single
__device__ __align__(256) bf16 g_wq_h[WELEM], g_wq_l[WELEM];
__device__ __align__(256) bf16 g_wk_h[WELEM], g_wk_l[WELEM];
__device__ __align__(256) __half g_Wv16[WELEM];                 // Wv fp16 single
__device__ __align__(256) __half g_Wo16[WELEM];                 // Wo fp16 single
__device__ __align__(256) bf16 g_Q_h[NELEM],  g_Q_l[NELEM];
__device__ __align__(256) bf16 g_K_h[NELEM],  g_K_l[NELEM];
__device__ __align__(256) __half g_V16[NELEM];                  // V fp16 single
__device__ __align__(256) __half g_Vo[NELEM];                   // V' fp16 single
__device__ __align__(256) __half g_X16[NELEM];                  // X fp16 single
__device__ __align__(256) __half g_E[SELEM];                    // fp16 E plane
__device__ __align__(256) float g_Mx[(size_t)BH * Ss];
__device__ __align__(256) float g_Z [(size_t)BH * Ss];

// ---------------------------------------------------------------------------
// PTX helpers
// ---------------------------------------------------------------------------
__device__ __forceinline__ void cpa(uint32_t dst, const void* src) {
    asm volatile("cp.async.cg.shared.global [%0], [%1], 16;\n" :: "r"(dst), "l"(src));
}
__device__ __forceinline__ void ldsm4(uint32_t& r0, uint32_t& r1, uint32_t& r2, uint32_t& r3, uint32_t a) {
    asm volatile("ldmatrix.sync.aligned.m8n8.x4.shared.b16 {%0,%1,%2,%3}, [%4];"
                 : "=r"(r0), "=r"(r1), "=r"(r2), "=r"(r3) : "r"(a));
}
__device__ __forceinline__ void ldsm4t(uint32_t& r0, uint32_t& r1, uint32_t& r2, uint32_t& r3, uint32_t a) {
    asm volatile("ldmatrix.sync.aligned.m8n8.x4.trans.shared.b16 {%0,%1,%2,%3}, [%4];"
                 : "=r"(r0), "=r"(r1), "=r"(r2), "=r"(r3) : "r"(a));
}
__device__ __forceinline__ void mma16816(float* c, const uint32_t* a, const uint32_t* b) {
    asm volatile("mma.sync.aligned.m16n8k16.row.col.f32.bf16.bf16.f32 "
                 "{%0,%1,%2,%3},{%4,%5,%6,%7},{%8,%9},{%0,%1,%2,%3};"
                 : "+f"(c[0]), "+f"(c[1]), "+f"(c[2]), "+f"(c[3])
                 : "r"(a[0]), "r"(a[1]), "r"(a[2]), "r"(a[3]), "r"(b[0]), "r"(b[1]));
}
__device__ __forceinline__ void mma16816h(float* c, const uint32_t* a, const uint32_t* b) {
    asm volatile("mma.sync.aligned.m16n8k16.row.col.f32.f16.f16.f32 "
                 "{%0,%1,%2,%3},{%4,%5,%6,%7},{%8,%9},{%0,%1,%2,%3};"
                 : "+f"(c[0]), "+f"(c[1]), "+f"(c[2]), "+f"(c[3])
                 : "r"(a[0]), "r"(a[1]), "r"(a[2]), "r"(a[3]), "r"(b[0]), "r"(b[1]));
}
__device__ __forceinline__ uint32_t pack2(bf16 a, bf16 b) {
    bf162 t(a, b);
    return *reinterpret_cast<uint32_t*>(&t);
}
__device__ __forceinline__ void split2(float v0, float v1, uint32_t& hi, uint32_t& lo) {
    bf16 h0 = __float2bfloat16_rn(v0);
    bf16 h1 = __float2bfloat16_rn(v1);
    bf16 l0 = __float2bfloat16_rn(v0 - __bfloat162float(h0));
    bf16 l1 = __float2bfloat16_rn(v1 - __bfloat162float(h1));
    hi = pack2(h0, h1);
    lo = pack2(l0, l1);
}
__device__ __forceinline__ void atomicMaxF(float* addr, float v) {
    if (v >= 0.f) atomicMax((int*)addr, __float_as_int(v));
    else          atomicMin((unsigned int*)addr, (unsigned int)__float_as_int(v));
}

// ---------------------------------------------------------------------------
// Elementwise prep
// ---------------------------------------------------------------------------
__global__ __launch_bounds__(256) void split_f32(const float4* __restrict__ x,
                                                 uint2* __restrict__ hi, uint2* __restrict__ lo, int n4)
{
    int i = blockIdx.x * 256 + threadIdx.x;
    if (i >= n4) return;
    float4 v = x[i];
    uint32_t h01, l01, h23, l23;
    split2(v.x, v.y, h01, l01);
    split2(v.z, v.w, h23, l23);
    hi[i] = make_uint2(h01, h23);
    lo[i] = make_uint2(l01, l23);
}

__global__ __launch_bounds__(256) void cvt_f16(const float4* __restrict__ x,
                                               uint2* __restrict__ o, int n4)
{
    int i = blockIdx.x * 256 + threadIdx.x;
    if (i >= n4) return;
    float4 v = x[i];
    __half2 a = __floats2half2_rn(v.x, v.y);
    __half2 b = __floats2half2_rn(v.z, v.w);
    o[i] = make_uint2(*reinterpret_cast<uint32_t*>(&a), *reinterpret_cast<uint32_t*>(&b));
}

__global__ __launch_bounds__(256) void init_mz(float* __restrict__ Mx, float* __restrict__ Z)
{
    int i = blockIdx.x * 256 + threadIdx.x;   // BH*Ss = 65536
    Mx[i] = -1e30f;
    Z[i] = 0.f;
}

// ---------------------------------------------------------------------------
// MMA GEMM, 3-stage cp.async pipeline.
// BM=BN=128, BK=64, 256 threads (8 warps 2x4), warp tile 64x32.
// BLAY: 0 = B global [k][n], 1 = B global [n][k].
// EPI:  0 = fp32 out (+bias), 1 = hi/lo bf16 planes out,
//       2 = no store, column max -> Mx (atomicMaxF),
//       3 = exp(s - Mx) -> fp16 E plane + column sums Z (atomicAdd),
//       4 = fp16 single-plane out (+bias).
// LITE: 1 = hi planes only, 1 MMA product.
// FK:   0 = bf16 MMA, 1 = fp16 MMA (LITE path only).
// ---------------------------------------------------------------------------
template<int BLAY, int EPI, int LITE, int FK>
__global__ __launch_bounds__(256) void mma_gemm(
    const bf16* __restrict__ Ah, const bf16* __restrict__ Al,
    const bf16* __restrict__ Bh, const bf16* __restrict__ Bl,
    const float* __restrict__ bias,
    float* __restrict__ Cf, bf16* __restrict__ Ch, bf16* __restrict__ Cl,
    float* __restrict__ Mx, float* __restrict__ Zp,
    int K, int lda, int ldb, int ldc,
    size_t sA, size_t sB, size_t sC)
{
    constexpr int APL = LITE ? 1 : 2;
    constexpr int STG = APL * 16384 + (LITE ? 16384 : 32768);
    extern __shared__ __align__(16) char smem[];
    float* sRed = reinterpret_cast<float*>(smem);             // 128 floats scratch
    const uint32_t sbase = (uint32_t)__cvta_generic_to_shared(smem) + 1024;
    const int tid = threadIdx.x, lane = tid & 31, wid = tid >> 5;
    const int wm = wid >> 2, wn = wid & 3;
    const int rowBase = blockIdx.y * 128, colBase = blockIdx.x * 128;
    const bf16* Agh = Ah + (size_t)blockIdx.z * sA;
    const bf16* Agl = Al + (size_t)blockIdx.z * sA;
    const bf16* Bgh = Bh + (size_t)blockIdx.z * sB;
    const bf16* Bgl = Bl + (size_t)blockIdx.z * sB;
    const size_t zC = (size_t)blockIdx.z * sC;

    float acc[4][4][4] = {};

    auto copyStage = [&](int st, int k0) {
        uint32_t aOff = sbase + st * STG;
        #pragma unroll
        for (int t = 0; t < 4; t++) {
            int idx = tid + t * 256;
            int r = idx >> 3, c = idx & 7;
            int sw = c ^ (r & 7);
            uint32_t d = aOff + r * 128 + sw * 16;
            size_t g = (size_t)(rowBase + r) * lda + (k0 + c * 8);
            cpa(d, Agh + g);
            if (!LITE) cpa(d + 16384, Agl + g);
        }
        uint32_t bOff = aOff + APL * 16384;
        #pragma unroll
        for (int t = 0; t < 4; t++) {
            int idx = tid + t * 256;
            if (BLAY == 0) {
                int r = idx >> 4, c = idx & 15;
                int sw = c ^ (r & 7);
                uint32_t d = bOff + r * 256 + sw * 16;
                size_t g = (size_t)(k0 + r) * ldb + (colBase + c * 8);
                cpa(d, Bgh + g);
                if (!LITE) cpa(d + 16384, Bgl + g);
            } else {
                int r = idx >> 3, c = idx & 7;
                int sw = c ^ (r & 7);
                uint32_t d = bOff + r * 128 + sw * 16;
                size_t g = (size_t)(colBase + r) * ldb + (k0 + c * 8);
                cpa(d, Bgh + g);
                if (!LITE) cpa(d + 16384, Bgl + g);
            }
        }
    };

    auto computeStage = [&](int st) {
        uint32_t aHi = sbase + st * STG;
        uint32_t aLo = aHi + 16384;
        uint32_t bHi = aHi + APL * 16384;
        uint32_t bLo = bHi + 16384;
        #pragma unroll
        for (int ks = 0; ks < 4; ks++) {
            uint32_t af[2][4][4];
            uint32_t bfr[2][4][2];
            #pragma unroll
            for (int mt = 0; mt < 4; mt++) {
                int row = wm * 64 + mt * 16 + (lane & 15);
                int ch = ks * 2 + (lane >> 4);
                uint32_t ad = (uint32_t)(row * 128 + ((ch ^ (row & 7)) * 16));
                ldsm4(af[0][mt][0], af[0][mt][1], af[0][mt][2], af[0][mt][3], aHi + ad);
                if (!LITE)
                    ldsm4(af[1][mt][0], af[1][mt][1], af[1][mt][2], af[1][mt][3], aLo + ad);
            }
            #pragma unroll
            for (int i = 0; i < 2; i++) {
                if (BLAY == 0) {
                    int row = ks * 16 + ((lane >> 3) & 1) * 8 + (lane & 7);
                    int ch = wn * 4 + i * 2 + (lane >> 4);
                    uint32_t bd = (uint32_t)(row * 256 + ((ch ^ (row & 7)) * 16));
                    uint32_t r0, r1, r2, r3;
                    ldsm4t(r0, r1, r2, r3, bHi + bd);
                    bfr[0][2*i][0] = r0; bfr[0][2*i][1] = r1; bfr[0][2*i+1][0] = r2; bfr[0][2*i+1][1] = r3;
                    if (!LITE) {
                        ldsm4t(r0, r1, r2, r3, bLo + bd);
                        bfr[1][2*i][0] = r0; bfr[1][2*i][1] = r1; bfr[1][2*i+1][0] = r2; bfr[1][2*i+1][1] = r3;
                    }
                } else {
                    int row = wn * 32 + i * 16 + ((lane >> 4) << 3) + (lane & 7);
                    int ch = ks * 2 + ((lane >> 3) & 1);
                    uint32_t bd = (uint32_t)(row * 128 + ((ch ^ (row & 7)) * 16));
                    uint32_t r0, r1, r2, r3;
                    ldsm4(r0, r1, r2, r3, bHi + bd);
                    bfr[0][2*i][0] = r0; bfr[0][2*i][1] = r1; bfr[0][2*i+1][0] = r2; bfr[0][2*i+1][1] = r3;
                    if (!LITE) {
                        ldsm4(r0, r1, r2, r3, bLo + bd);
                        bfr[1][2*i][0] = r0; bfr[1][2*i][1] = r1; bfr[1][2*i+1][0] = r2; bfr[1][2*i+1][1] = r3;
                    }
                }
            }
            #pragma unroll
            for (int mt = 0; mt < 4; mt++)
                #pragma unroll
                for (int nt = 0; nt < 4; nt++) {
                    if (FK) mma16816h(acc[mt][nt], af[0][mt], bfr[0][nt]);
                    else    mma16816(acc[mt][nt], af[0][mt], bfr[0][nt]);
                    if (!LITE) {
                        mma16816(acc[mt][nt], af[0][mt], bfr[1][nt]);
                        mma16816(acc[mt][nt], af[1][mt], bfr[0][nt]);
                    }
                }
        }
    };

    const int nk = K >> 6;
    copyStage(0, 0);
    asm volatile("cp.async.commit_group;" ::: "memory");
    if (nk > 1) {
        copyStage(1, 64);
        asm volatile("cp.async.commit_group;" ::: "memory");
    }
    int st = 0;
    for (int kt = 0; kt < nk; kt++) {
        if (kt + 2 < nk) {
            int pst = st + 2; if (pst >= 3) pst -= 3;
            copyStage(pst, (kt + 2) * 64);
            asm volatile("cp.async.commit_group;" ::: "memory");
            asm volatile("cp.async.wait_group 2;" ::: "memory");
        } else if (kt + 1 < nk) {
            asm volatile("cp.async.wait_group 1;" ::: "memory");
        } else {
            asm volatile("cp.async.wait_group 0;" ::: "memory");
        }
        __syncthreads();
        computeStage(st);
        __syncthreads();
        if (++st == 3) st = 0;
    }

    if (EPI == 2) {
        // Column-max only (scores max pass)
        if (tid < 128) sRed[tid] = -1e30f;
        __syncthreads();
        #pragma unroll
        for (int nt = 0; nt < 4; nt++) {
            float cm0 = -1e30f, cm1 = -1e30f;
            #pragma unroll
            for (int mt = 0; mt < 4; mt++) {
                cm0 = fmaxf(cm0, fmaxf(acc[mt][nt][0], acc[mt][nt][2]));
                cm1 = fmaxf(cm1, fmaxf(acc[mt][nt][1], acc[mt][nt][3]));
            }
            int ci = wn * 32 + nt * 8 + (lane & 3) * 2;
            atomicMaxF(&sRed[ci], cm0);
            atomicMaxF(&sRed[ci + 1], cm1);
        }
        __syncthreads();
        if (tid < 128)
            atomicMaxF(Mx + (size_t)blockIdx.z * ldc + colBase + tid, sRed[tid]);
    } else if (EPI == 3) {
        // exp(s - M) -> fp16 E plane, column sums -> Z
        if (tid < 128) sRed[tid] = 0.f;
        __syncthreads();
        const float* Mrow = Mx + (size_t)blockIdx.z * ldc + colBase;
        __half* Eo = reinterpret_cast<__half*>(Ch) + zC;
        #pragma unroll
        for (int nt = 0; nt < 4; nt++) {
            int ci = wn * 32 + nt * 8 + (lane & 3) * 2;
            float m0 = Mrow[ci], m1 = Mrow[ci + 1];
            float z0 = 0.f, z1 = 0.f;
            #pragma unroll
            for (int mt = 0; mt < 4; mt++) {
                int r = rowBase + wm * 64 + mt * 16 + (lane >> 2);
                float e00 = __expf(acc[mt][nt][0] - m0);
                float e01 = __expf(acc[mt][nt][1] - m1);
                float e10 = __expf(acc[mt][nt][2] - m0);
                float e11 = __expf(acc[mt][nt][3] - m1);
                z0 += e00 + e10;
                z1 += e01 + e11;
                __half2 p0 = __floats2half2_rn(e00, e01);
                __half2 p1 = __floats2half2_rn(e10, e11);
                *reinterpret_cast<__half2*>(Eo + (size_t)r * ldc + colBase + ci) = p0;
                *reinterpret_cast<__half2*>(Eo + (size_t)(r + 8) * ldc + colBase + ci) = p1;
            }
            #pragma unroll
            for (int off = 16; off >= 4; off >>= 1) {
                z0 += __shfl_down_sync(0xffffffffu, z0, off);
                z1 += __shfl_down_sync(0xffffffffu, z1, off);
            }
            if (lane < 4) {
                atomicAdd(&sRed[ci], z0);
                atomicAdd(&sRed[ci + 1], z1);
            }
        }
        __syncthreads();
        if (tid < 128)
            atomicAdd(Zp + (size_t)blockIdx.z * ldc + colBase + tid, sRed[tid]);
    } else {
        #pragma unroll
        for (int nt = 0; nt < 4; nt++) {
            #pragma unroll
            for (int mt = 0; mt < 4; mt++) {
                int r = rowBase + wm * 64 + mt * 16 + (lane >> 2);
                int c = colBase + wn * 32 + nt * 8 + (lane & 3) * 2;
                float b0 = 0.f, b1 = 0.f;
                if (bias) { b0 = bias[c]; b1 = bias[c + 1]; }
                float v00 = acc[mt][nt][0] + b0, v01 = acc[mt][nt][1] + b1;
                float v10 = acc[mt][nt][2] + b0, v11 = acc[mt][nt][3] + b1;
                if (EPI == 0) {
                    *reinterpret_cast<float2*>(Cf + zC + (size_t)r * ldc + c)       = make_float2(v00, v01);
                    *reinterpret_cast<float2*>(Cf + zC + (size_t)(r + 8) * ldc + c) = make_float2(v10, v11);
                } else if (EPI == 4) {
                    __half* Ho = reinterpret_cast<__half*>(Ch);
                    __half2 p0 = __floats2half2_rn(v00, v01);
                    __half2 p1 = __floats2half2_rn(v10, v11);
                    *reinterpret_cast<__half2*>(Ho + zC + (size_t)r * ldc + c)       = p0;
                    *reinterpret_cast<__half2*>(Ho + zC + (size_t)(r + 8) * ldc + c) = p1;
                } else {
                    uint32_t h, l;
                    split2(v00, v01, h, l);
                    *reinterpret_cast<uint32_t*>(Ch + zC + (size_t)r * ldc + c) = h;
                    *reinterpret_cast<uint32_t*>(Cl + zC + (size_t)r * ldc + c) = l;
                    split2(v10, v11, h, l);
                    *reinterpret_cast<uint32_t*>(Ch + zC + (size_t)(r + 8) * ldc + c) = h;
                    *reinterpret_cast<uint32_t*>(Cl + zC + (size_t)(r + 8) * ldc + c) = l;
                }
            }
        }
    }
}

// ---------------------------------------------------------------------------
// PV GEMM fp16, 1 product: X_h = E (fp16) @ V' (fp16 single plane).
// ---------------------------------------------------------------------------
#define PV_STAGE 32768
#define PV_SMEM  98304

__global__ __launch_bounds__(256) void pv_gemm(
    const __half* __restrict__ Ag,
    const __half* __restrict__ Bg,
    __half* __restrict__ Co)
{
    extern __shared__ __align__(16) char smem[];
    const uint32_t sbase = (uint32_t)__cvta_generic_to_shared(smem);
    const int tid = threadIdx.x, lane = tid & 31, wid = tid >> 5;
    const int wm = wid >> 2, wn = wid & 3;
    const int rowBase = blockIdx.y * 128;
    const __half* A = Ag + (size_t)blockIdx.z * Ss * Ss;
    const __half* B = Bg + (size_t)blockIdx.z * Ss * HD;
    const size_t zC = (size_t)blockIdx.z * Ss * HD;

    float acc[4][4][4] = {};

    auto copyStage = [&](int st, int k0) {
        uint32_t aOff = sbase + st * PV_STAGE;
        #pragma unroll
        for (int t = 0; t < 4; t++) {
            int idx = tid + t * 256;
            int r = idx >> 3, c = idx & 7;
            int sw = c ^ (r & 7);
            cpa(aOff + r * 128 + sw * 16, A + (size_t)(rowBase + r) * Ss + (k0 + c * 8));
        }
        uint32_t bOff = aOff + 16384;
        #pragma unroll
        for (int t = 0; t < 4; t++) {     // full 64-row B tile
            int idx = tid + t * 256;
            int r = idx >> 4, c = idx & 15;
            int sw = c ^ (r & 7);
            cpa(bOff + r * 256 + sw * 16, B + (size_t)(k0 + r) * HD + c * 8);
        }
    };

    auto computeStage = [&](int st) {
        uint32_t aP  = sbase + st * PV_STAGE;
        uint32_t bP  = aP + 16384;
        #pragma unroll
        for (int ks = 0; ks < 4; ks++) {
            uint32_t af[4][4];
            uint32_t bfr[4][2];
            #pragma unroll
            for (int mt = 0; mt < 4; mt++) {
                int row = wm * 64 + mt * 16 + (lane & 15);
                int ch = ks * 2 + (lane >> 4);
                uint32_t ad = (uint32_t)(row * 128 + ((ch ^ (row & 7)) * 16));
                ldsm4(af[mt][0], af[mt][1], af[mt][2], af[mt][3], aP + ad);
            }
            #pragma unroll
            for (int i = 0; i < 2; i++) {
                int row = ks * 16 + ((lane >> 3) & 1) * 8 + (lane & 7);
                int ch = wn * 4 + i * 2 + (lane >> 4);
                uint32_t bd = (uint32_t)(row * 256 + ((ch ^ (row & 7)) * 16));
                uint32_t r0, r1, r2, r3;
                ldsm4t(r0, r1, r2, r3, bP + bd);
                bfr[2*i][0] = r0; bfr[2*i][1] = r1; bfr[2*i+1][0] = r2; bfr[2*i+1][1] = r3;
            }
            #pragma unroll
            for (int mt = 0; mt < 4; mt++)
                #pragma unroll
                for (int nt = 0; nt < 4; nt++)
                    mma16816h(acc[mt][nt], af[mt], bfr[nt]);
        }
    };

    const int nk = Ss >> 6;   // 32
    copyStage(0, 0);
    asm volatile("cp.async.commit_group;" ::: "memory");
    copyStage(1, 64);
    asm volatile("cp.async.commit_group;" ::: "memory");
    int st = 0;
    for (int kt = 0; kt < nk; kt++) {
        if (kt + 2 < nk) {
            int pst = st + 2; if (pst >= 3) pst -= 3;
            copyStage(pst, (kt + 2) * 64);
            asm volatile("cp.async.commit_group;" ::: "memory");
            asm volatile("cp.async.wait_group 2;" ::: "memory");
        } else if (kt + 1 < nk) {
            asm volatile("cp.async.wait_group 1;" ::: "memory");
        } else {
            asm volatile("cp.async.wait_group 0;" ::: "memory");
        }
        __syncthreads();
        computeStage(st);
        __syncthreads();
        if (++st == 3) st = 0;
    }

    #pragma unroll
    for (int mt = 0; mt < 4; mt++) {
        #pragma unroll
        for (int nt = 0; nt < 4; nt++) {
            int r = rowBase + wm * 64 + mt * 16 + (lane >> 2);
            int c = wn * 32 + nt * 8 + (lane & 3) * 2;
            __half2 p0 = __floats2half2_rn(acc[mt][nt][0], acc[mt][nt][1]);
            __half2 p1 = __floats2half2_rn(acc[mt][nt][2], acc[mt][nt][3]);
            *reinterpret_cast<__half2*>(Co + zC + (size_t)r * HD + c) = p0;
            *reinterpret_cast<__half2*>(Co + zC + (size_t)(r + 8) * HD + c) = p1;
        }
    }
}

// ---------------------------------------------------------------------------
// V'[k,d] = V[k,d]/Z[k] -> fp16 single plane
// ---------------------------------------------------------------------------
__global__ __launch_bounds__(256) void vscale_kernel(const __half* __restrict__ V16,
                                                     const float* __restrict__ Z,
                                                     __half* __restrict__ Vo)
{
    size_t i = (size_t)blockIdx.x * 256 + threadIdx.x;   // over 8M elements
    size_t kz = i >> 7;                                   // z*Ss + k  (HD = 128)
    float inv = __fdividef(1.0f, Z[kz]);
    Vo[i] = __float2half_rn(__half2float(V16[i]) * inv);
}

// ---------------------------------------------------------------------------
// Launch
// ---------------------------------------------------------------------------
extern "C" void kernel_launch(void* const* d_in, const int* in_sizes, int n_in,
                              void* d_out, int out_size)
{
    const float* query = (const float*)d_in[0];
    const float* key   = (const float*)d_in[1];
    const float* value = (const float*)d_in[2];
    const float* Wq    = (const float*)d_in[3];
    const float* bq    = (const float*)d_in[4];
    const float* Wk    = (const float*)d_in[5];
    const float* bk    = (const float*)d_in[6];
    const float* Wv    = (const float*)d_in[7];
    const float* bv    = (const float*)d_in[8];
    const float* Wo    = (const float*)d_in[9];
    const float* bo    = (const float*)d_in[10];
    float* out = (float*)d_out;

    #define SYM(p, s) do { void* tmp_; cudaGetSymbolAddress(&tmp_, s); p = (decltype(p))tmp_; } while (0)
    bf16 *iqh, *iql, *ikh, *ikl;
    bf16 *wqh, *wql, *wkh, *wkl;
    bf16 *Qh, *Ql, *Kh, *Kl;
    __half *iv16, *Wv16, *Wo16, *V16, *Ep, *Vop, *X16;
    float *Mxp, *Zp;
    SYM(iqh, g_iq_h); SYM(iql, g_iq_l); SYM(ikh, g_ik_h); SYM(ikl, g_ik_l);
    SYM(iv16, g_iv16);
    SYM(wqh, g_wq_h); SYM(wql, g_wq_l); SYM(wkh, g_wk_h); SYM(wkl, g_wk_l);
    SYM(Wv16, g_Wv16); SYM(Wo16, g_Wo16);
    SYM(Qh, g_Q_h); SYM(Ql, g_Q_l); SYM(Kh, g_K_h); SYM(Kl, g_K_l);
    SYM(V16, g_V16); SYM(Vop, g_Vo); SYM(X16, g_X16);
    SYM(Ep, g_E); SYM(Mxp, g_Mx); SYM(Zp, g_Z);
    #undef SYM

    const int SM_FULL = 1024 + 3 * 65536;   // 197632
    const int SM_LITE = 1024 + 3 * 32768;   // 99328
    cudaFuncSetAttribute(mma_gemm<0, 1, 0, 0>, cudaFuncAttributeMaxDynamicSharedMemorySize, SM_FULL);
    cudaFuncSetAttribute(mma_gemm<1, 2, 1, 0>, cudaFuncAttributeMaxDynamicSharedMemorySize, SM_LITE);
    cudaFuncSetAttribute(mma_gemm<1, 3, 0, 0>, cudaFuncAttributeMaxDynamicSharedMemorySize, SM_FULL);
    cudaFuncSetAttribute(mma_gemm<0, 0, 1, 1>, cudaFuncAttributeMaxDynamicSharedMemorySize, SM_LITE);
    cudaFuncSetAttribute(mma_gemm<0, 4, 1, 1>, cudaFuncAttributeMaxDynamicSharedMemorySize, SM_LITE);
    cudaFuncSetAttribute(pv_gemm, cudaFuncAttributeMaxDynamicSharedMemorySize, PV_SMEM);

    // 0) Re-init Mx (-inf) and Z (0) — graph-replay safe
    init_mz<<<(BH * Ss) / 256, 256>>>(Mxp, Zp);

    // 1) Split/convert fp32 inputs/weights into planes
    {
        int n4i = (int)(NELEM / 4), n4w = (int)(WELEM / 4);
        split_f32<<<n4i / 256, 256>>>((const float4*)query, (uint2*)iqh, (uint2*)iql, n4i);
        split_f32<<<n4i / 256, 256>>>((const float4*)key,   (uint2*)ikh, (uint2*)ikl, n4i);
        cvt_f16<<<n4i / 256, 256>>>((const float4*)value, (uint2*)iv16, n4i);
        split_f32<<<n4w / 256, 256>>>((const float4*)Wq, (uint2*)wqh, (uint2*)wql, n4w);
        split_f32<<<n4w / 256, 256>>>((const float4*)Wk, (uint2*)wkh, (uint2*)wkl, n4w);
        cvt_f16<<<n4w / 256, 256>>>((const float4*)Wv, (uint2*)Wv16, n4w);
        cvt_f16<<<n4w / 256, 256>>>((const float4*)Wo, (uint2*)Wo16, n4w);
    }

    // 2) Q/K projections (bf16x3) + V projection (fp16 1-product)
    {
        dim3 grid(Dd / 128, MROWS / 128, 1);
        mma_gemm<0, 1, 0, 0><<<grid, 256, SM_FULL>>>(iqh, iql, wqh, wql, bq, nullptr, Qh, Ql,
                                                     nullptr, nullptr, Dd, Dd, Dd, Dd, 0, 0, 0);
        mma_gemm<0, 1, 0, 0><<<grid, 256, SM_FULL>>>(ikh, ikl, wkh, wkl, bk, nullptr, Kh, Kl,
                                                     nullptr, nullptr, Dd, Dd, Dd, Dd, 0, 0, 0);
        mma_gemm<0, 4, 1, 1><<<grid, 256, SM_LITE>>>((const bf16*)iv16, nullptr,
                                                     (const bf16*)Wv16, nullptr, bv,
                                                     nullptr, (bf16*)V16, nullptr,
                                                     nullptr, nullptr, Dd, Dd, Dd, Dd, 0, 0, 0);
    }

    // 3a) Scores max pass (1-product, hi planes, no store): Mx = colmax(Q_h @ K_h^T)
    {
        dim3 grid(Ss / 128, Ss / 128, BH);
        mma_gemm<1, 2, 1, 0><<<grid, 256, SM_LITE>>>(Qh, nullptr, Kh, nullptr, nullptr,
                                                     nullptr, nullptr, nullptr, Mxp, nullptr,
                                                     HD, HD, HD, Ss,
                                                     (size_t)Ss * HD, (size_t)Ss * HD, 0);
    }

    // 3b) Scores full pass (3-product) + fused exp + Z: E = exp(S - Mx), Z = colsum(E)
    {
        dim3 grid(Ss / 128, Ss / 128, BH);
        mma_gemm<1, 3, 0, 0><<<grid, 256, SM_FULL>>>(Qh, Ql, Kh, Kl, nullptr,
                                                     nullptr, (bf16*)Ep, nullptr, Mxp, Zp,
                                                     HD, HD, HD, Ss,
                                                     (size_t)Ss * HD, (size_t)Ss * HD, (size_t)Ss * Ss);
    }

    // 4) Fold 1/Z into V' (fp16 single plane)
    vscale_kernel<<<(unsigned)(NELEM / 256), 256>>>(V16, Zp, Vop);

    // 5) PV per head (fp16 1-product): X_h = E[2048,2048] @ V'[2048,128] -> fp16
    {
        dim3 grid(1, Ss / 128, BH);
        pv_gemm<<<grid, 256, PV_SMEM>>>(Ep, Vop, X16);
    }

    // 6) Output projection (fp16 1-product): [8192,1024] @ Wo16 + bo -> fp32 out
    {
        dim3 grid(Dd / 128, MROWS / 128, 1);
        mma_gemm<0, 0, 1, 1><<<grid, 256, SM_LITE>>>((const bf16*)X16, nullptr,
                                                     (const bf16*)Wo16, nullptr, bo,
                                                     out, nullptr, nullptr,
                                                     nullptr, nullptr, Dd, Dd, Dd, Dd, 0, 0, 0);
    }
}

// round 12
// speedup vs baseline: 5.8010x; 1.0414x over previous
#include <cuda_runtime.h>
#include <cuda_bf16.h>
#include <cuda_fp16.h>
#include <cstdint>
#include <math.h>

// Problem constants
#define Bb 4
#define Ss 2048
#define Dd 1024
#define Hh 8
#define HD 128
#define BH (Bb*Hh)            // 32 head-slices
#define MROWS (Bb*Ss)         // 8192
#define NELEM ((size_t)MROWS * Dd)      // 8M
#define WELEM ((size_t)Dd * Dd)         // 1M
#define SELEM ((size_t)BH * Ss * Ss)    // 128M

typedef __nv_bfloat16 bf16;
typedef __nv_bfloat162 bf162;

// ---------------------------------------------------------------------------
// Device scratch (allocation-free rule: __device__ globals)
// Q/K buffers are contiguous pairs so projections batch via grid.z.
// ---------------------------------------------------------------------------
__device__ __align__(256) bf16 g_iqk_h[2*NELEM], g_iqk_l[2*NELEM];   // [query | key]
__device__ __align__(256) bf16 g_wqk_h[2*WELEM], g_wqk_l[2*WELEM];   // [Wq | Wk]
__device__ __align__(256) float g_bqk[2*Dd];                          // [bq | bk]
__device__ __align__(256) __half g_iv16[NELEM];                       // value fp16
__device__ __align__(256) __half g_Wv16[WELEM];                       // Wv fp16
__device__ __align__(256) __half g_Wo16[WELEM];                       // Wo fp16
__device__ __align__(256) bf16 g_QK_h[2*NELEM], g_QK_l[2*NELEM];     // [Q | K]
__device__ __align__(256) __half g_V16[NELEM];                        // V fp16
__device__ __align__(256) __half g_Vo[NELEM];                         // V' fp16
__device__ __align__(256) __half g_X16[NELEM];                        // X fp16
__device__ __align__(256) __half g_E[SELEM];                          // fp16 E plane
__device__ __align__(256) float g_Mx[(size_t)BH * Ss];
__device__ __align__(256) float g_Z [(size_t)BH * Ss];

// ---------------------------------------------------------------------------
// PTX helpers
// ---------------------------------------------------------------------------
__device__ __forceinline__ void cpa(uint32_t dst, const void* src) {
    asm volatile("cp.async.cg.shared.global [%0], [%1], 16;\n" :: "r"(dst), "l"(src));
}
__device__ __forceinline__ void ldsm4(uint32_t& r0, uint32_t& r1, uint32_t& r2, uint32_t& r3, uint32_t a) {
    asm volatile("ldmatrix.sync.aligned.m8n8.x4.shared.b16 {%0,%1,%2,%3}, [%4];"
                 : "=r"(r0), "=r"(r1), "=r"(r2), "=r"(r3) : "r"(a));
}
__device__ __forceinline__ void ldsm4t(uint32_t& r0, uint32_t& r1, uint32_t& r2, uint32_t& r3, uint32_t a) {
    asm volatile("ldmatrix.sync.aligned.m8n8.x4.trans.shared.b16 {%0,%1,%2,%3}, [%4];"
                 : "=r"(r0), "=r"(r1), "=r"(r2), "=r"(r3) : "r"(a));
}
__device__ __forceinline__ void mma16816(float* c, const uint32_t* a, const uint32_t* b) {
    asm volatile("mma.sync.aligned.m16n8k16.row.col.f32.bf16.bf16.f32 "
                 "{%0,%1,%2,%3},{%4,%5,%6,%7},{%8,%9},{%0,%1,%2,%3};"
                 : "+f"(c[0]), "+f"(c[1]), "+f"(c[2]), "+f"(c[3])
                 : "r"(a[0]), "r"(a[1]), "r"(a[2]), "r"(a[3]), "r"(b[0]), "r"(b[1]));
}
__device__ __forceinline__ void mma16816h(float* c, const uint32_t* a, const uint32_t* b) {
    asm volatile("mma.sync.aligned.m16n8k16.row.col.f32.f16.f16.f32 "
                 "{%0,%1,%2,%3},{%4,%5,%6,%7},{%8,%9},{%0,%1,%2,%3};"
                 : "+f"(c[0]), "+f"(c[1]), "+f"(c[2]), "+f"(c[3])
                 : "r"(a[0]), "r"(a[1]), "r"(a[2]), "r"(a[3]), "r"(b[0]), "r"(b[1]));
}
__device__ __forceinline__ uint32_t pack2(bf16 a, bf16 b) {
    bf162 t(a, b);
    return *reinterpret_cast<uint32_t*>(&t);
}
__device__ __forceinline__ void split2(float v0, float v1, uint32_t& hi, uint32_t& lo) {
    bf16 h0 = __float2bfloat16_rn(v0);
    bf16 h1 = __float2bfloat16_rn(v1);
    bf16 l0 = __float2bfloat16_rn(v0 - __bfloat162float(h0));
    bf16 l1 = __float2bfloat16_rn(v1 - __bfloat162float(h1));
    hi = pack2(h0, h1);
    lo = pack2(l0, l1);
}
__device__ __forceinline__ void atomicMaxF(float* addr, float v) {
    if (v >= 0.f) atomicMax((int*)addr, __float_as_int(v));
    else          atomicMin((unsigned int*)addr, (unsigned int)__float_as_int(v));
}

// ---------------------------------------------------------------------------
// Elementwise prep (fused multi-source kernels)
// ---------------------------------------------------------------------------
// Split two fp32 sources into contiguous halves of one hi/lo bf16 buffer.
__global__ __launch_bounds__(256) void split2_f32(const float4* __restrict__ x0,
                                                  const float4* __restrict__ x1,
                                                  uint2* __restrict__ hi, uint2* __restrict__ lo,
                                                  int n4)
{
    int i = blockIdx.x * 256 + threadIdx.x;
    float4 v = (i < n4) ? x0[i] : x1[i - n4];
    uint32_t h01, l01, h23, l23;
    split2(v.x, v.y, h01, l01);
    split2(v.z, v.w, h23, l23);
    hi[i] = make_uint2(h01, h23);
    lo[i] = make_uint2(l01, l23);
}

// Convert three fp32 sources to three fp16 dests in one launch.
__global__ __launch_bounds__(256) void cvt3_f16(const float4* __restrict__ x0, uint2* __restrict__ o0, int n0,
                                                const float4* __restrict__ x1, uint2* __restrict__ o1, int n1,
                                                const float4* __restrict__ x2, uint2* __restrict__ o2)
{
    int i = blockIdx.x * 256 + threadIdx.x;
    const float4* x; uint2* o; int j;
    if (i < n0)           { x = x0; o = o0; j = i; }
    else if (i < n0 + n1) { x = x1; o = o1; j = i - n0; }
    else                  { x = x2; o = o2; j = i - n0 - n1; }
    float4 v = x[j];
    __half2 a = __floats2half2_rn(v.x, v.y);
    __half2 b = __floats2half2_rn(v.z, v.w);
    o[j] = make_uint2(*reinterpret_cast<uint32_t*>(&a), *reinterpret_cast<uint32_t*>(&b));
}

__global__ __launch_bounds__(256) void init_mz(float* __restrict__ Mx, float* __restrict__ Z)
{
    int i = blockIdx.x * 256 + threadIdx.x;   // BH*Ss = 65536
    Mx[i] = -1e30f;
    Z[i] = 0.f;
}

// ---------------------------------------------------------------------------
// MMA GEMM, 3-stage cp.async pipeline.
// BM=BN=128, BK=64, 256 threads (8 warps 2x4), warp tile 64x32.
// BLAY: 0 = B global [k][n], 1 = B global [n][k].
// EPI:  0 = fp32 out (+bias), 1 = hi/lo bf16 planes out (+bias),
//       2 = no store, column max -> Mx (atomicMaxF),
//       3 = exp(s - Mx) -> fp16 E plane + column sums Z (atomicAdd),
//       4 = fp16 single-plane out (+bias).
// LITE: 1 = hi planes only, 1 MMA product.
// FK:   0 = bf16 MMA, 1 = fp16 MMA (LITE path only).
// bias is indexed bias[blockIdx.z*ldc + c] (per-z bias for batched launches).
// ---------------------------------------------------------------------------
template<int BLAY, int EPI, int LITE, int FK>
__global__ __launch_bounds__(256) void mma_gemm(
    const bf16* __restrict__ Ah, const bf16* __restrict__ Al,
    const bf16* __restrict__ Bh, const bf16* __restrict__ Bl,
    const float* __restrict__ bias,
    float* __restrict__ Cf, bf16* __restrict__ Ch, bf16* __restrict__ Cl,
    float* __restrict__ Mx, float* __restrict__ Zp,
    int K, int lda, int ldb, int ldc,
    size_t sA, size_t sB, size_t sC)
{
    constexpr int APL = LITE ? 1 : 2;
    constexpr int STG = APL * 16384 + (LITE ? 16384 : 32768);
    extern __shared__ __align__(16) char smem[];
    float* sRed = reinterpret_cast<float*>(smem);             // 128 floats scratch
    const uint32_t sbase = (uint32_t)__cvta_generic_to_shared(smem) + 1024;
    const int tid = threadIdx.x, lane = tid & 31, wid = tid >> 5;
    const int wm = wid >> 2, wn = wid & 3;
    const int rowBase = blockIdx.y * 128, colBase = blockIdx.x * 128;
    const bf16* Agh = Ah + (size_t)blockIdx.z * sA;
    const bf16* Agl = Al + (size_t)blockIdx.z * sA;
    const bf16* Bgh = Bh + (size_t)blockIdx.z * sB;
    const bf16* Bgl = Bl + (size_t)blockIdx.z * sB;
    const size_t zC = (size_t)blockIdx.z * sC;
    const size_t zBias = (size_t)blockIdx.z * ldc;

    float acc[4][4][4] = {};

    auto copyStage = [&](int st, int k0) {
        uint32_t aOff = sbase + st * STG;
        #pragma unroll
        for (int t = 0; t < 4; t++) {
            int idx = tid + t * 256;
            int r = idx >> 3, c = idx & 7;
            int sw = c ^ (r & 7);
            uint32_t d = aOff + r * 128 + sw * 16;
            size_t g = (size_t)(rowBase + r) * lda + (k0 + c * 8);
            cpa(d, Agh + g);
            if (!LITE) cpa(d + 16384, Agl + g);
        }
        uint32_t bOff = aOff + APL * 16384;
        #pragma unroll
        for (int t = 0; t < 4; t++) {
            int idx = tid + t * 256;
            if (BLAY == 0) {
                int r = idx >> 4, c = idx & 15;
                int sw = c ^ (r & 7);
                uint32_t d = bOff + r * 256 + sw * 16;
                size_t g = (size_t)(k0 + r) * ldb + (colBase + c * 8);
                cpa(d, Bgh + g);
                if (!LITE) cpa(d + 16384, Bgl + g);
            } else {
                int r = idx >> 3, c = idx & 7;
                int sw = c ^ (r & 7);
                uint32_t d = bOff + r * 128 + sw * 16;
                size_t g = (size_t)(colBase + r) * ldb + (k0 + c * 8);
                cpa(d, Bgh + g);
                if (!LITE) cpa(d + 16384, Bgl + g);
            }
        }
    };

    auto computeStage = [&](int st) {
        uint32_t aHi = sbase + st * STG;
        uint32_t aLo = aHi + 16384;
        uint32_t bHi = aHi + APL * 16384;
        uint32_t bLo = bHi + 16384;
        #pragma unroll
        for (int ks = 0; ks < 4; ks++) {
            uint32_t af[2][4][4];
            uint32_t bfr[2][4][2];
            #pragma unroll
            for (int mt = 0; mt < 4; mt++) {
                int row = wm * 64 + mt * 16 + (lane & 15);
                int ch = ks * 2 + (lane >> 4);
                uint32_t ad = (uint32_t)(row * 128 + ((ch ^ (row & 7)) * 16));
                ldsm4(af[0][mt][0], af[0][mt][1], af[0][mt][2], af[0][mt][3], aHi + ad);
                if (!LITE)
                    ldsm4(af[1][mt][0], af[1][mt][1], af[1][mt][2], af[1][mt][3], aLo + ad);
            }
            #pragma unroll
            for (int i = 0; i < 2; i++) {
                if (BLAY == 0) {
                    int row = ks * 16 + ((lane >> 3) & 1) * 8 + (lane & 7);
                    int ch = wn * 4 + i * 2 + (lane >> 4);
                    uint32_t bd = (uint32_t)(row * 256 + ((ch ^ (row & 7)) * 16));
                    uint32_t r0, r1, r2, r3;
                    ldsm4t(r0, r1, r2, r3, bHi + bd);
                    bfr[0][2*i][0] = r0; bfr[0][2*i][1] = r1; bfr[0][2*i+1][0] = r2; bfr[0][2*i+1][1] = r3;
                    if (!LITE) {
                        ldsm4t(r0, r1, r2, r3, bLo + bd);
                        bfr[1][2*i][0] = r0; bfr[1][2*i][1] = r1; bfr[1][2*i+1][0] = r2; bfr[1][2*i+1][1] = r3;
                    }
                } else {
                    int row = wn * 32 + i * 16 + ((lane >> 4) << 3) + (lane & 7);
                    int ch = ks * 2 + ((lane >> 3) & 1);
                    uint32_t bd = (uint32_t)(row * 128 + ((ch ^ (row & 7)) * 16));
                    uint32_t r0, r1, r2, r3;
                    ldsm4(r0, r1, r2, r3, bHi + bd);
                    bfr[0][2*i][0] = r0; bfr[0][2*i][1] = r1; bfr[0][2*i+1][0] = r2; bfr[0][2*i+1][1] = r3;
                    if (!LITE) {
                        ldsm4(r0, r1, r2, r3, bLo + bd);
                        bfr[1][2*i][0] = r0; bfr[1][2*i][1] = r1; bfr[1][2*i+1][0] = r2; bfr[1][2*i+1][1] = r3;
                    }
                }
            }
            #pragma unroll
            for (int mt = 0; mt < 4; mt++)
                #pragma unroll
                for (int nt = 0; nt < 4; nt++) {
                    if (FK) mma16816h(acc[mt][nt], af[0][mt], bfr[0][nt]);
                    else    mma16816(acc[mt][nt], af[0][mt], bfr[0][nt]);
                    if (!LITE) {
                        mma16816(acc[mt][nt], af[0][mt], bfr[1][nt]);
                        mma16816(acc[mt][nt], af[1][mt], bfr[0][nt]);
                    }
                }
        }
    };

    const int nk = K >> 6;
    copyStage(0, 0);
    asm volatile("cp.async.commit_group;" ::: "memory");
    if (nk > 1) {
        copyStage(1, 64);
        asm volatile("cp.async.commit_group;" ::: "memory");
    }
    int st = 0;
    for (int kt = 0; kt < nk; kt++) {
        if (kt + 2 < nk) {
            int pst = st + 2; if (pst >= 3) pst -= 3;
            copyStage(pst, (kt + 2) * 64);
            asm volatile("cp.async.commit_group;" ::: "memory");
            asm volatile("cp.async.wait_group 2;" ::: "memory");
        } else if (kt + 1 < nk) {
            asm volatile("cp.async.wait_group 1;" ::: "memory");
        } else {
            asm volatile("cp.async.wait_group 0;" ::: "memory");
        }
        __syncthreads();
        computeStage(st);
        __syncthreads();
        if (++st == 3) st = 0;
    }

    if (EPI == 2) {
        // Column-max only (scores max pass)
        if (tid < 128) sRed[tid] = -1e30f;
        __syncthreads();
        #pragma unroll
        for (int nt = 0; nt < 4; nt++) {
            float cm0 = -1e30f, cm1 = -1e30f;
            #pragma unroll
            for (int mt = 0; mt < 4; mt++) {
                cm0 = fmaxf(cm0, fmaxf(acc[mt][nt][0], acc[mt][nt][2]));
                cm1 = fmaxf(cm1, fmaxf(acc[mt][nt][1], acc[mt][nt][3]));
            }
            int ci = wn * 32 + nt * 8 + (lane & 3) * 2;
            atomicMaxF(&sRed[ci], cm0);
            atomicMaxF(&sRed[ci + 1], cm1);
        }
        __syncthreads();
        if (tid < 128)
            atomicMaxF(Mx + (size_t)blockIdx.z * ldc + colBase + tid, sRed[tid]);
    } else if (EPI == 3) {
        // exp(s - M) -> fp16 E plane, column sums -> Z
        if (tid < 128) sRed[tid] = 0.f;
        __syncthreads();
        const float* Mrow = Mx + (size_t)blockIdx.z * ldc + colBase;
        __half* Eo = reinterpret_cast<__half*>(Ch) + zC;
        #pragma unroll
        for (int nt = 0; nt < 4; nt++) {
            int ci = wn * 32 + nt * 8 + (lane & 3) * 2;
            float m0 = Mrow[ci], m1 = Mrow[ci + 1];
            float z0 = 0.f, z1 = 0.f;
            #pragma unroll
            for (int mt = 0; mt < 4; mt++) {
                int r = rowBase + wm * 64 + mt * 16 + (lane >> 2);
                float e00 = __expf(acc[mt][nt][0] - m0);
                float e01 = __expf(acc[mt][nt][1] - m1);
                float e10 = __expf(acc[mt][nt][2] - m0);
                float e11 = __expf(acc[mt][nt][3] - m1);
                z0 += e00 + e10;
                z1 += e01 + e11;
                __half2 p0 = __floats2half2_rn(e00, e01);
                __half2 p1 = __floats2half2_rn(e10, e11);
                *reinterpret_cast<__half2*>(Eo + (size_t)r * ldc + colBase + ci) = p0;
                *reinterpret_cast<__half2*>(Eo + (size_t)(r + 8) * ldc + colBase + ci) = p1;
            }
            #pragma unroll
            for (int off = 16; off >= 4; off >>= 1) {
                z0 += __shfl_down_sync(0xffffffffu, z0, off);
                z1 += __shfl_down_sync(0xffffffffu, z1, off);
            }
            if (lane < 4) {
                atomicAdd(&sRed[ci], z0);
                atomicAdd(&sRed[ci + 1], z1);
            }
        }
        __syncthreads();
        if (tid < 128)
            atomicAdd(Zp + (size_t)blockIdx.z * ldc + colBase + tid, sRed[tid]);
    } else {
        #pragma unroll
        for (int nt = 0; nt < 4; nt++) {
            #pragma unroll
            for (int mt = 0; mt < 4; mt++) {
                int r = rowBase + wm * 64 + mt * 16 + (lane >> 2);
                int c = colBase + wn * 32 + nt * 8 + (lane & 3) * 2;
                float b0 = 0.f, b1 = 0.f;
                if (bias) { b0 = bias[zBias + c]; b1 = bias[zBias + c + 1]; }
                float v00 = acc[mt][nt][0] + b0, v01 = acc[mt][nt][1] + b1;
                float v10 = acc[mt][nt][2] + b0, v11 = acc[mt][nt][3] + b1;
                if (EPI == 0) {
                    *reinterpret_cast<float2*>(Cf + zC + (size_t)r * ldc + c)       = make_float2(v00, v01);
                    *reinterpret_cast<float2*>(Cf + zC + (size_t)(r + 8) * ldc + c) = make_float2(v10, v11);
                } else if (EPI == 4) {
                    __half* Ho = reinterpret_cast<__half*>(Ch);
                    __half2 p0 = __floats2half2_rn(v00, v01);
                    __half2 p1 = __floats2half2_rn(v10, v11);
                    *reinterpret_cast<__half2*>(Ho + zC + (size_t)r * ldc + c)       = p0;
                    *reinterpret_cast<__half2*>(Ho + zC + (size_t)(r + 8) * ldc + c) = p1;
                } else {
                    uint32_t h, l;
                    split2(v00, v01, h, l);
                    *reinterpret_cast<uint32_t*>(Ch + zC + (size_t)r * ldc + c) = h;
                    *reinterpret_cast<uint32_t*>(Cl + zC + (size_t)r * ldc + c) = l;
                    split2(v10, v11, h, l);
                    *reinterpret_cast<uint32_t*>(Ch + zC + (size_t)(r + 8) * ldc + c) = h;
                    *reinterpret_cast<uint32_t*>(Cl + zC + (size_t)(r + 8) * ldc + c) = l;
                }
            }
        }
    }
}

// ---------------------------------------------------------------------------
// PV GEMM fp16, 1 product: X_h = E (fp16) @ V' (fp16 single plane).
// ---------------------------------------------------------------------------
#define PV_STAGE 32768
#define PV_SMEM  98304

__global__ __launch_bounds__(256) void pv_gemm(
    const __half* __restrict__ Ag,
    const __half* __restrict__ Bg,
    __half* __restrict__ Co)
{
    extern __shared__ __align__(16) char smem[];
    const uint32_t sbase = (uint32_t)__cvta_generic_to_shared(smem);
    const int tid = threadIdx.x, lane = tid & 31, wid = tid >> 5;
    const int wm = wid >> 2, wn = wid & 3;
    const int rowBase = blockIdx.y * 128;
    const __half* A = Ag + (size_t)blockIdx.z * Ss * Ss;
    const __half* B = Bg + (size_t)blockIdx.z * Ss * HD;
    const size_t zC = (size_t)blockIdx.z * Ss * HD;

    float acc[4][4][4] = {};

    auto copyStage = [&](int st, int k0) {
        uint32_t aOff = sbase + st * PV_STAGE;
        #pragma unroll
        for (int t = 0; t < 4; t++) {
            int idx = tid + t * 256;
            int r = idx >> 3, c = idx & 7;
            int sw = c ^ (r & 7);
            cpa(aOff + r * 128 + sw * 16, A + (size_t)(rowBase + r) * Ss + (k0 + c * 8));
        }
        uint32_t bOff = aOff + 16384;
        #pragma unroll
        for (int t = 0; t < 4; t++) {
            int idx = tid + t * 256;
            int r = idx >> 4, c = idx & 15;
            int sw = c ^ (r & 7);
            cpa(bOff + r * 256 + sw * 16, B + (size_t)(k0 + r) * HD + c * 8);
        }
    };

    auto computeStage = [&](int st) {
        uint32_t aP  = sbase + st * PV_STAGE;
        uint32_t bP  = aP + 16384;
        #pragma unroll
        for (int ks = 0; ks < 4; ks++) {
            uint32_t af[4][4];
            uint32_t bfr[4][2];
            #pragma unroll
            for (int mt = 0; mt < 4; mt++) {
                int row = wm * 64 + mt * 16 + (lane & 15);
                int ch = ks * 2 + (lane >> 4);
                uint32_t ad = (uint32_t)(row * 128 + ((ch ^ (row & 7)) * 16));
                ldsm4(af[mt][0], af[mt][1], af[mt][2], af[mt][3], aP + ad);
            }
            #pragma unroll
            for (int i = 0; i < 2; i++) {
                int row = ks * 16 + ((lane >> 3) & 1) * 8 + (lane & 7);
                int ch = wn * 4 + i * 2 + (lane >> 4);
                uint32_t bd = (uint32_t)(row * 256 + ((ch ^ (row & 7)) * 16));
                uint32_t r0, r1, r2, r3;
                ldsm4t(r0, r1, r2, r3, bP + bd);
                bfr[2*i][0] = r0; bfr[2*i][1] = r1; bfr[2*i+1][0] = r2; bfr[2*i+1][1] = r3;
            }
            #pragma unroll
            for (int mt = 0; mt < 4; mt++)
                #pragma unroll
                for (int nt = 0; nt < 4; nt++)
                    mma16816h(acc[mt][nt], af[mt], bfr[nt]);
        }
    };

    const int nk = Ss >> 6;   // 32
    copyStage(0, 0);
    asm volatile("cp.async.commit_group;" ::: "memory");
    copyStage(1, 64);
    asm volatile("cp.async.commit_group;" ::: "memory");
    int st = 0;
    for (int kt = 0; kt < nk; kt++) {
        if (kt + 2 < nk) {
            int pst = st + 2; if (pst >= 3) pst -= 3;
            copyStage(pst, (kt + 2) * 64);
            asm volatile("cp.async.commit_group;" ::: "memory");
            asm volatile("cp.async.wait_group 2;" ::: "memory");
        } else if (kt + 1 < nk) {
            asm volatile("cp.async.wait_group 1;" ::: "memory");
        } else {
            asm volatile("cp.async.wait_group 0;" ::: "memory");
        }
        __syncthreads();
        computeStage(st);
        __syncthreads();
        if (++st == 3) st = 0;
    }

    #pragma unroll
    for (int mt = 0; mt < 4; mt++) {
        #pragma unroll
        for (int nt = 0; nt < 4; nt++) {
            int r = rowBase + wm * 64 + mt * 16 + (lane >> 2);
            int c = wn * 32 + nt * 8 + (lane & 3) * 2;
            __half2 p0 = __floats2half2_rn(acc[mt][nt][0], acc[mt][nt][1]);
            __half2 p1 = __floats2half2_rn(acc[mt][nt][2], acc[mt][nt][3]);
            *reinterpret_cast<__half2*>(Co + zC + (size_t)r * HD + c) = p0;
            *reinterpret_cast<__half2*>(Co + zC + (size_t)(r + 8) * HD + c) = p1;
        }
    }
}

// ---------------------------------------------------------------------------
// V'[k,d] = V[k,d]/Z[k] -> fp16 single plane
// ---------------------------------------------------------------------------
__global__ __launch_bounds__(256) void vscale_kernel(const __half* __restrict__ V16,
                                                     const float* __restrict__ Z,
                                                     __half* __restrict__ Vo)
{
    size_t i = (size_t)blockIdx.x * 256 + threadIdx.x;   // over 8M elements
    size_t kz = i >> 7;                                   // z*Ss + k  (HD = 128)
    float inv = __fdividef(1.0f, Z[kz]);
    Vo[i] = __float2half_rn(__half2float(V16[i]) * inv);
}

// ---------------------------------------------------------------------------
// Launch
// ---------------------------------------------------------------------------
extern "C" void kernel_launch(void* const* d_in, const int* in_sizes, int n_in,
                              void* d_out, int out_size)
{
    const float* query = (const float*)d_in[0];
    const float* key   = (const float*)d_in[1];
    const float* value = (const float*)d_in[2];
    const float* Wq    = (const float*)d_in[3];
    const float* bq    = (const float*)d_in[4];
    const float* Wk    = (const float*)d_in[5];
    const float* bk    = (const float*)d_in[6];
    const float* Wv    = (const float*)d_in[7];
    const float* bv    = (const float*)d_in[8];
    const float* Wo    = (const float*)d_in[9];
    const float* bo    = (const float*)d_in[10];
    float* out = (float*)d_out;

    #define SYM(p, s) do { void* tmp_; cudaGetSymbolAddress(&tmp_, s); p = (decltype(p))tmp_; } while (0)
    bf16 *iqkh, *iqkl, *wqkh, *wqkl, *QKh, *QKl;
    __half *iv16, *Wv16, *Wo16, *V16, *Ep, *Vop, *X16;
    float *bqk, *Mxp, *Zp;
    SYM(iqkh, g_iqk_h); SYM(iqkl, g_iqk_l);
    SYM(wqkh, g_wqk_h); SYM(wqkl, g_wqk_l);
    SYM(bqk, g_bqk);
    SYM(iv16, g_iv16); SYM(Wv16, g_Wv16); SYM(Wo16, g_Wo16);
    SYM(QKh, g_QK_h); SYM(QKl, g_QK_l);
    SYM(V16, g_V16); SYM(Vop, g_Vo); SYM(X16, g_X16);
    SYM(Ep, g_E); SYM(Mxp, g_Mx); SYM(Zp, g_Z);
    #undef SYM
    bf16 *Qh = QKh, *Ql = QKl, *Kh = QKh + NELEM, *Kl = QKl + NELEM;

    const int SM_FULL = 1024 + 3 * 65536;   // 197632
    const int SM_LITE = 1024 + 3 * 32768;   // 99328
    cudaFuncSetAttribute(mma_gemm<0, 1, 0, 0>, cudaFuncAttributeMaxDynamicSharedMemorySize, SM_FULL);
    cudaFuncSetAttribute(mma_gemm<1, 2, 1, 0>, cudaFuncAttributeMaxDynamicSharedMemorySize, SM_LITE);
    cudaFuncSetAttribute(mma_gemm<1, 3, 0, 0>, cudaFuncAttributeMaxDynamicSharedMemorySize, SM_FULL);
    cudaFuncSetAttribute(mma_gemm<0, 0, 1, 1>, cudaFuncAttributeMaxDynamicSharedMemorySize, SM_LITE);
    cudaFuncSetAttribute(mma_gemm<0, 4, 1, 1>, cudaFuncAttributeMaxDynamicSharedMemorySize, SM_LITE);
    cudaFuncSetAttribute(pv_gemm, cudaFuncAttributeMaxDynamicSharedMemorySize, PV_SMEM);

    // 0) Re-init Mx (-inf) and Z (0) — graph-replay safe; copy biases to pair buffer
    init_mz<<<(BH * Ss) / 256, 256>>>(Mxp, Zp);
    cudaMemcpyAsync(bqk,      bq, Dd * sizeof(float), cudaMemcpyDeviceToDevice);
    cudaMemcpyAsync(bqk + Dd, bk, Dd * sizeof(float), cudaMemcpyDeviceToDevice);

    // 1) Fused prep: split query+key, split Wq+Wk, cvt value/Wv/Wo
    {
        int n4i = (int)(NELEM / 4), n4w = (int)(WELEM / 4);
        split2_f32<<<2 * n4i / 256, 256>>>((const float4*)query, (const float4*)key,
                                           (uint2*)iqkh, (uint2*)iqkl, n4i);
        split2_f32<<<2 * n4w / 256, 256>>>((const float4*)Wq, (const float4*)Wk,
                                           (uint2*)wqkh, (uint2*)wqkl, n4w);
        cvt3_f16<<<(n4i + 2 * n4w) / 256, 256>>>((const float4*)value, (uint2*)iv16, n4i,
                                                 (const float4*)Wv, (uint2*)Wv16, n4w,
                                                 (const float4*)Wo, (uint2*)Wo16);
    }

    // 2) Q+K projections batched (bf16x3, grid.z=2) + V projection (fp16 1-product)
    {
        dim3 gridQK(Dd / 128, MROWS / 128, 2);
        mma_gemm<0, 1, 0, 0><<<gridQK, 256, SM_FULL>>>(iqkh, iqkl, wqkh, wqkl, bqk,
                                                       nullptr, QKh, QKl,
                                                       nullptr, nullptr, Dd, Dd, Dd, Dd,
                                                       NELEM, WELEM, NELEM);
        dim3 gridV(Dd / 128, MROWS / 128, 1);
        mma_gemm<0, 4, 1, 1><<<gridV, 256, SM_LITE>>>((const bf16*)iv16, nullptr,
                                                      (const bf16*)Wv16, nullptr, bv,
                                                      nullptr, (bf16*)V16, nullptr,
                                                      nullptr, nullptr, Dd, Dd, Dd, Dd, 0, 0, 0);
    }

    // 3a) Scores max pass (1-product, hi planes, no store): Mx = colmax(Q_h @ K_h^T)
    {
        dim3 grid(Ss / 128, Ss / 128, BH);
        mma_gemm<1, 2, 1, 0><<<grid, 256, SM_LITE>>>(Qh, nullptr, Kh, nullptr, nullptr,
                                                     nullptr, nullptr, nullptr, Mxp, nullptr,
                                                     HD, HD, HD, Ss,
                                                     (size_t)Ss * HD, (size_t)Ss * HD, 0);
    }

    // 3b) Scores full pass (3-product) + fused exp + Z: E = exp(S - Mx), Z = colsum(E)
    {
        dim3 grid(Ss / 128, Ss / 128, BH);
        mma_gemm<1, 3, 0, 0><<<grid, 256, SM_FULL>>>(Qh, Ql, Kh, Kl, nullptr,
                                                     nullptr, (bf16*)Ep, nullptr, Mxp, Zp,
                                                     HD, HD, HD, Ss,
                                                     (size_t)Ss * HD, (size_t)Ss * HD, (size_t)Ss * Ss);
    }

    // 4) Fold 1/Z into V' (fp16 single plane)
    vscale_kernel<<<(unsigned)(NELEM / 256), 256>>>(V16, Zp, Vop);

    // 5) PV per head (fp16 1-product): X_h = E[2048,2048] @ V'[2048,128] -> fp16
    {
        dim3 grid(1, Ss / 128, BH);
        pv_gemm<<<grid, 256, PV_SMEM>>>(Ep, Vop, X16);
    }

    // 6) Output projection (fp16 1-product): [8192,1024] @ Wo16 + bo -> fp32 out
    {
        dim3 grid(Dd / 128, MROWS / 128, 1);
        mma_gemm<0, 0, 1, 1><<<grid, 256, SM_LITE>>>((const bf16*)X16, nullptr,
                                                     (const bf16*)Wo16, nullptr, bo,
                                                     out, nullptr, nullptr,
                                                     nullptr, nullptr, Dd, Dd, Dd, Dd, 0, 0, 0);
    }
}

// round 13
// speedup vs baseline: 6.1598x; 1.0619x over previous
#include <cuda_runtime.h>
#include <cuda_bf16.h>
#include <cuda_fp16.h>
#include <cstdint>
#include <math.h>

// Problem constants
#define Bb 4
#define Ss 2048
#define Dd 1024
#define Hh 8
#define HD 128
#define BH (Bb*Hh)            // 32 head-slices
#define MROWS (Bb*Ss)         // 8192
#define NELEM ((size_t)MROWS * Dd)      // 8M
#define WELEM ((size_t)Dd * Dd)         // 1M
#define SELEM ((size_t)BH * Ss * Ss)    // 128M

typedef __nv_bfloat16 bf16;
typedef __nv_bfloat162 bf162;

// ---------------------------------------------------------------------------
// Device scratch (allocation-free rule: __device__ globals)
// ---------------------------------------------------------------------------
__device__ __align__(256) bf16 g_iqk_h[2*NELEM], g_iqk_l[2*NELEM];   // [query | key]
__device__ __align__(256) bf16 g_wqk_h[2*WELEM], g_wqk_l[2*WELEM];   // [Wq | Wk]
__device__ __align__(256) float g_bqk[2*Dd];                          // [bq | bk]
__device__ __align__(256) __half g_iv16[NELEM];                       // value fp16
__device__ __align__(256) __half g_Wv16[WELEM];                       // Wv fp16
__device__ __align__(256) __half g_Wo16[WELEM];                       // Wo fp16
__device__ __align__(256) bf16 g_QK_h[2*NELEM], g_QK_l[2*NELEM];     // [Q | K]
__device__ __align__(256) __half g_V16[NELEM];                        // V fp16
__device__ __align__(256) __half g_Vo[NELEM];                         // V' fp16
__device__ __align__(256) __half g_X16[NELEM];                        // X fp16
__device__ __align__(256) __half g_E[SELEM];                          // fp16 E plane
__device__ __align__(256) float g_Mx[(size_t)BH * Ss];
__device__ __align__(256) float g_Z [(size_t)BH * Ss];

// ---------------------------------------------------------------------------
// PTX helpers
// ---------------------------------------------------------------------------
__device__ __forceinline__ void cpa(uint32_t dst, const void* src) {
    asm volatile("cp.async.cg.shared.global [%0], [%1], 16;\n" :: "r"(dst), "l"(src));
}
__device__ __forceinline__ void ldsm4(uint32_t& r0, uint32_t& r1, uint32_t& r2, uint32_t& r3, uint32_t a) {
    asm volatile("ldmatrix.sync.aligned.m8n8.x4.shared.b16 {%0,%1,%2,%3}, [%4];"
                 : "=r"(r0), "=r"(r1), "=r"(r2), "=r"(r3) : "r"(a));
}
__device__ __forceinline__ void ldsm4t(uint32_t& r0, uint32_t& r1, uint32_t& r2, uint32_t& r3, uint32_t a) {
    asm volatile("ldmatrix.sync.aligned.m8n8.x4.trans.shared.b16 {%0,%1,%2,%3}, [%4];"
                 : "=r"(r0), "=r"(r1), "=r"(r2), "=r"(r3) : "r"(a));
}
__device__ __forceinline__ void mma16816(float* c, const uint32_t* a, const uint32_t* b) {
    asm volatile("mma.sync.aligned.m16n8k16.row.col.f32.bf16.bf16.f32 "
                 "{%0,%1,%2,%3},{%4,%5,%6,%7},{%8,%9},{%0,%1,%2,%3};"
                 : "+f"(c[0]), "+f"(c[1]), "+f"(c[2]), "+f"(c[3])
                 : "r"(a[0]), "r"(a[1]), "r"(a[2]), "r"(a[3]), "r"(b[0]), "r"(b[1]));
}
__device__ __forceinline__ void mma16816h(float* c, const uint32_t* a, const uint32_t* b) {
    asm volatile("mma.sync.aligned.m16n8k16.row.col.f32.f16.f16.f32 "
                 "{%0,%1,%2,%3},{%4,%5,%6,%7},{%8,%9},{%0,%1,%2,%3};"
                 : "+f"(c[0]), "+f"(c[1]), "+f"(c[2]), "+f"(c[3])
                 : "r"(a[0]), "r"(a[1]), "r"(a[2]), "r"(a[3]), "r"(b[0]), "r"(b[1]));
}
__device__ __forceinline__ uint32_t pack2(bf16 a, bf16 b) {
    bf162 t(a, b);
    return *reinterpret_cast<uint32_t*>(&t);
}
__device__ __forceinline__ void split2(float v0, float v1, uint32_t& hi, uint32_t& lo) {
    bf16 h0 = __float2bfloat16_rn(v0);
    bf16 h1 = __float2bfloat16_rn(v1);
    bf16 l0 = __float2bfloat16_rn(v0 - __bfloat162float(h0));
    bf16 l1 = __float2bfloat16_rn(v1 - __bfloat162float(h1));
    hi = pack2(h0, h1);
    lo = pack2(l0, l1);
}
__device__ __forceinline__ void atomicMaxF(float* addr, float v) {
    if (v >= 0.f) atomicMax((int*)addr, __float_as_int(v));
    else          atomicMin((unsigned int*)addr, (unsigned int)__float_as_int(v));
}

// ---------------------------------------------------------------------------
// Elementwise prep (fused multi-source kernels)
// ---------------------------------------------------------------------------
__global__ __launch_bounds__(256) void split2_f32(const float4* __restrict__ x0,
                                                  const float4* __restrict__ x1,
                                                  uint2* __restrict__ hi, uint2* __restrict__ lo,
                                                  int n4)
{
    int i = blockIdx.x * 256 + threadIdx.x;
    float4 v = (i < n4) ? x0[i] : x1[i - n4];
    uint32_t h01, l01, h23, l23;
    split2(v.x, v.y, h01, l01);
    split2(v.z, v.w, h23, l23);
    hi[i] = make_uint2(h01, h23);
    lo[i] = make_uint2(l01, l23);
}

__global__ __launch_bounds__(256) void cvt3_f16(const float4* __restrict__ x0, uint2* __restrict__ o0, int n0,
                                                const float4* __restrict__ x1, uint2* __restrict__ o1, int n1,
                                                const float4* __restrict__ x2, uint2* __restrict__ o2)
{
    int i = blockIdx.x * 256 + threadIdx.x;
    const float4* x; uint2* o; int j;
    if (i < n0)           { x = x0; o = o0; j = i; }
    else if (i < n0 + n1) { x = x1; o = o1; j = i - n0; }
    else                  { x = x2; o = o2; j = i - n0 - n1; }
    float4 v = x[j];
    __half2 a = __floats2half2_rn(v.x, v.y);
    __half2 b = __floats2half2_rn(v.z, v.w);
    o[j] = make_uint2(*reinterpret_cast<uint32_t*>(&a), *reinterpret_cast<uint32_t*>(&b));
}

__global__ __launch_bounds__(256) void init_mz(float* __restrict__ Mx, float* __restrict__ Z)
{
    int i = blockIdx.x * 256 + threadIdx.x;   // BH*Ss = 65536
    Mx[i] = -1e30f;
    Z[i] = 0.f;
}

// ---------------------------------------------------------------------------
// MMA GEMM, 3-stage cp.async pipeline, 32KB stages -> 2 blocks/SM everywhere.
// FULL (!LITE): BK=32, combined-plane layout.
//   A rows 128B = [hi 64B | lo 64B]; chunk c: c<4 hi (k=kc*8), c>=4 lo.
//   B BLAY1 same combined layout. B BLAY0 (k-major): planes stacked at +8KB.
// LITE: BK=64, single hi plane per operand (unchanged from R12).
// EPI:  0 fp32 out, 1 bf16 hi/lo out, 2 colmax->Mx, 3 exp->E + Z, 4 fp16 out.
// FK:   0 bf16 MMA, 1 fp16 MMA (LITE only).
// bias indexed bias[blockIdx.z*ldc + c].
// ---------------------------------------------------------------------------
#define STG 32768

template<int BLAY, int EPI, int LITE, int FK>
__global__ __launch_bounds__(256) void mma_gemm(
    const bf16* __restrict__ Ah, const bf16* __restrict__ Al,
    const bf16* __restrict__ Bh, const bf16* __restrict__ Bl,
    const float* __restrict__ bias,
    float* __restrict__ Cf, bf16* __restrict__ Ch, bf16* __restrict__ Cl,
    float* __restrict__ Mx, float* __restrict__ Zp,
    int K, int lda, int ldb, int ldc,
    size_t sA, size_t sB, size_t sC)
{
    constexpr int BKI = LITE ? 64 : 32;
    extern __shared__ __align__(16) char smem[];
    float* sRed = reinterpret_cast<float*>(smem);
    const uint32_t sbase = (uint32_t)__cvta_generic_to_shared(smem) + 1024;
    const int tid = threadIdx.x, lane = tid & 31, wid = tid >> 5;
    const int wm = wid >> 2, wn = wid & 3;
    const int rowBase = blockIdx.y * 128, colBase = blockIdx.x * 128;
    const bf16* Agh = Ah + (size_t)blockIdx.z * sA;
    const bf16* Agl = Al + (size_t)blockIdx.z * sA;
    const bf16* Bgh = Bh + (size_t)blockIdx.z * sB;
    const bf16* Bgl = Bl + (size_t)blockIdx.z * sB;
    const size_t zC = (size_t)blockIdx.z * sC;
    const size_t zBias = (size_t)blockIdx.z * ldc;

    float acc[4][4][4] = {};

    auto copyStage = [&](int st, int k0) {
        uint32_t aOff = sbase + st * STG;
        uint32_t bOff = aOff + 16384;
        if (LITE) {
            #pragma unroll
            for (int t = 0; t < 4; t++) {
                int idx = tid + t * 256;
                int r = idx >> 3, c = idx & 7;
                cpa(aOff + r * 128 + ((c ^ (r & 7)) << 4),
                    Agh + (size_t)(rowBase + r) * lda + (k0 + c * 8));
            }
            #pragma unroll
            for (int t = 0; t < 4; t++) {
                int idx = tid + t * 256;
                if (BLAY == 0) {
                    int r = idx >> 4, c = idx & 15;
                    cpa(bOff + r * 256 + ((c ^ (r & 7)) << 4),
                        Bgh + (size_t)(k0 + r) * ldb + (colBase + c * 8));
                } else {
                    int r = idx >> 3, c = idx & 7;
                    cpa(bOff + r * 128 + ((c ^ (r & 7)) << 4),
                        Bgh + (size_t)(colBase + r) * ldb + (k0 + c * 8));
                }
            }
        } else {
            // A combined hi|lo, 128 rows x 8 chunks
            #pragma unroll
            for (int t = 0; t < 4; t++) {
                int idx = tid + t * 256;
                int r = idx >> 3, c = idx & 7;
                const bf16* Ag = (c & 4) ? Agl : Agh;
                int kc = c & 3;
                cpa(aOff + r * 128 + ((c ^ (r & 7)) << 4),
                    Ag + (size_t)(rowBase + r) * lda + (k0 + kc * 8));
            }
            if (BLAY == 0) {
                // k-major B: 32 rows x 16 chunks x 2 planes (stacked 8KB)
                #pragma unroll
                for (int t = 0; t < 4; t++) {
                    int idx = tid + t * 256;
                    int plane = idx >> 9;
                    int rem = idx & 511;
                    int r = rem >> 4, c = rem & 15;
                    const bf16* Bg = plane ? Bgl : Bgh;
                    cpa(bOff + plane * 8192 + r * 256 + ((c ^ (r & 7)) << 4),
                        Bg + (size_t)(k0 + r) * ldb + (colBase + c * 8));
                }
            } else {
                // n-major B: combined hi|lo like A
                #pragma unroll
                for (int t = 0; t < 4; t++) {
                    int idx = tid + t * 256;
                    int r = idx >> 3, c = idx & 7;
                    const bf16* Bg = (c & 4) ? Bgl : Bgh;
                    int kc = c & 3;
                    cpa(bOff + r * 128 + ((c ^ (r & 7)) << 4),
                        Bg + (size_t)(colBase + r) * ldb + (k0 + kc * 8));
                }
            }
        }
    };

    auto computeStage = [&](int st) {
        uint32_t aOff = sbase + st * STG;
        uint32_t bOff = aOff + 16384;
        constexpr int NKS = LITE ? 4 : 2;
        #pragma unroll
        for (int ks = 0; ks < NKS; ks++) {
            uint32_t af[2][4][4];
            uint32_t bfr[2][4][2];
            #pragma unroll
            for (int mt = 0; mt < 4; mt++) {
                int row = wm * 64 + mt * 16 + (lane & 15);
                int chh = ks * 2 + (lane >> 4);
                ldsm4(af[0][mt][0], af[0][mt][1], af[0][mt][2], af[0][mt][3],
                      aOff + (uint32_t)(row * 128 + ((chh ^ (row & 7)) << 4)));
                if (!LITE) {
                    int chl = chh + 4;
                    ldsm4(af[1][mt][0], af[1][mt][1], af[1][mt][2], af[1][mt][3],
                          aOff + (uint32_t)(row * 128 + ((chl ^ (row & 7)) << 4)));
                }
            }
            #pragma unroll
            for (int i = 0; i < 2; i++) {
                if (BLAY == 0) {
                    int row = ks * 16 + ((lane >> 3) & 1) * 8 + (lane & 7);
                    int ch = wn * 4 + i * 2 + (lane >> 4);
                    uint32_t bd = (uint32_t)(row * 256 + ((ch ^ (row & 7)) << 4));
                    uint32_t r0, r1, r2, r3;
                    ldsm4t(r0, r1, r2, r3, bOff + bd);
                    bfr[0][2*i][0] = r0; bfr[0][2*i][1] = r1; bfr[0][2*i+1][0] = r2; bfr[0][2*i+1][1] = r3;
                    if (!LITE) {
                        ldsm4t(r0, r1, r2, r3, bOff + 8192 + bd);
                        bfr[1][2*i][0] = r0; bfr[1][2*i][1] = r1; bfr[1][2*i+1][0] = r2; bfr[1][2*i+1][1] = r3;
                    }
                } else {
                    int row = wn * 32 + i * 16 + ((lane >> 4) << 3) + (lane & 7);
                    int chh = ks * 2 + ((lane >> 3) & 1);
                    uint32_t r0, r1, r2, r3;
                    ldsm4(r0, r1, r2, r3, bOff + (uint32_t)(row * 128 + ((chh ^ (row & 7)) << 4)));
                    bfr[0][2*i][0] = r0; bfr[0][2*i][1] = r1; bfr[0][2*i+1][0] = r2; bfr[0][2*i+1][1] = r3;
                    if (!LITE) {
                        int chl = chh + 4;
                        ldsm4(r0, r1, r2, r3, bOff + (uint32_t)(row * 128 + ((chl ^ (row & 7)) << 4)));
                        bfr[1][2*i][0] = r0; bfr[1][2*i][1] = r1; bfr[1][2*i+1][0] = r2; bfr[1][2*i+1][1] = r3;
                    }
                }
            }
            #pragma unroll
            for (int mt = 0; mt < 4; mt++)
                #pragma unroll
                for (int nt = 0; nt < 4; nt++) {
                    if (FK) mma16816h(acc[mt][nt], af[0][mt], bfr[0][nt]);
                    else    mma16816(acc[mt][nt], af[0][mt], bfr[0][nt]);
                    if (!LITE) {
                        mma16816(acc[mt][nt], af[0][mt], bfr[1][nt]);
                        mma16816(acc[mt][nt], af[1][mt], bfr[0][nt]);
                    }
                }
        }
    };

    const int nk = K / BKI;
    copyStage(0, 0);
    asm volatile("cp.async.commit_group;" ::: "memory");
    if (nk > 1) {
        copyStage(1, BKI);
        asm volatile("cp.async.commit_group;" ::: "memory");
    }
    if (nk > 2) {
        copyStage(2, 2 * BKI);
        asm volatile("cp.async.commit_group;" ::: "memory");
    }
    int st = 0;
    for (int kt = 0; kt < nk; kt++) {
        int rem = nk - 1 - kt;
        if (rem >= 2)      asm volatile("cp.async.wait_group 2;" ::: "memory");
        else if (rem == 1) asm volatile("cp.async.wait_group 1;" ::: "memory");
        else               asm volatile("cp.async.wait_group 0;" ::: "memory");
        __syncthreads();
        computeStage(st);
        __syncthreads();
        if (kt + 3 < nk) {
            copyStage(st, (kt + 3) * BKI);
            asm volatile("cp.async.commit_group;" ::: "memory");
        }
        if (++st == 3) st = 0;
    }

    if (EPI == 2) {
        if (tid < 128) sRed[tid] = -1e30f;
        __syncthreads();
        #pragma unroll
        for (int nt = 0; nt < 4; nt++) {
            float cm0 = -1e30f, cm1 = -1e30f;
            #pragma unroll
            for (int mt = 0; mt < 4; mt++) {
                cm0 = fmaxf(cm0, fmaxf(acc[mt][nt][0], acc[mt][nt][2]));
                cm1 = fmaxf(cm1, fmaxf(acc[mt][nt][1], acc[mt][nt][3]));
            }
            int ci = wn * 32 + nt * 8 + (lane & 3) * 2;
            atomicMaxF(&sRed[ci], cm0);
            atomicMaxF(&sRed[ci + 1], cm1);
        }
        __syncthreads();
        if (tid < 128)
            atomicMaxF(Mx + (size_t)blockIdx.z * ldc + colBase + tid, sRed[tid]);
    } else if (EPI == 3) {
        if (tid < 128) sRed[tid] = 0.f;
        __syncthreads();
        const float* Mrow = Mx + (size_t)blockIdx.z * ldc + colBase;
        __half* Eo = reinterpret_cast<__half*>(Ch) + zC;
        #pragma unroll
        for (int nt = 0; nt < 4; nt++) {
            int ci = wn * 32 + nt * 8 + (lane & 3) * 2;
            float m0 = Mrow[ci], m1 = Mrow[ci + 1];
            float z0 = 0.f, z1 = 0.f;
            #pragma unroll
            for (int mt = 0; mt < 4; mt++) {
                int r = rowBase + wm * 64 + mt * 16 + (lane >> 2);
                float e00 = __expf(acc[mt][nt][0] - m0);
                float e01 = __expf(acc[mt][nt][1] - m1);
                float e10 = __expf(acc[mt][nt][2] - m0);
                float e11 = __expf(acc[mt][nt][3] - m1);
                z0 += e00 + e10;
                z1 += e01 + e11;
                __half2 p0 = __floats2half2_rn(e00, e01);
                __half2 p1 = __floats2half2_rn(e10, e11);
                *reinterpret_cast<__half2*>(Eo + (size_t)r * ldc + colBase + ci) = p0;
                *reinterpret_cast<__half2*>(Eo + (size_t)(r + 8) * ldc + colBase + ci) = p1;
            }
            #pragma unroll
            for (int off = 16; off >= 4; off >>= 1) {
                z0 += __shfl_down_sync(0xffffffffu, z0, off);
                z1 += __shfl_down_sync(0xffffffffu, z1, off);
            }
            if (lane < 4) {
                atomicAdd(&sRed[ci], z0);
                atomicAdd(&sRed[ci + 1], z1);
            }
        }
        __syncthreads();
        if (tid < 128)
            atomicAdd(Zp + (size_t)blockIdx.z * ldc + colBase + tid, sRed[tid]);
    } else {
        #pragma unroll
        for (int nt = 0; nt < 4; nt++) {
            #pragma unroll
            for (int mt = 0; mt < 4; mt++) {
                int r = rowBase + wm * 64 + mt * 16 + (lane >> 2);
                int c = colBase + wn * 32 + nt * 8 + (lane & 3) * 2;
                float b0 = 0.f, b1 = 0.f;
                if (bias) { b0 = bias[zBias + c]; b1 = bias[zBias + c + 1]; }
                float v00 = acc[mt][nt][0] + b0, v01 = acc[mt][nt][1] + b1;
                float v10 = acc[mt][nt][2] + b0, v11 = acc[mt][nt][3] + b1;
                if (EPI == 0) {
                    *reinterpret_cast<float2*>(Cf + zC + (size_t)r * ldc + c)       = make_float2(v00, v01);
                    *reinterpret_cast<float2*>(Cf + zC + (size_t)(r + 8) * ldc + c) = make_float2(v10, v11);
                } else if (EPI == 4) {
                    __half* Ho = reinterpret_cast<__half*>(Ch);
                    __half2 p0 = __floats2half2_rn(v00, v01);
                    __half2 p1 = __floats2half2_rn(v10, v11);
                    *reinterpret_cast<__half2*>(Ho + zC + (size_t)r * ldc + c)       = p0;
                    *reinterpret_cast<__half2*>(Ho + zC + (size_t)(r + 8) * ldc + c) = p1;
                } else {
                    uint32_t h, l;
                    split2(v00, v01, h, l);
                    *reinterpret_cast<uint32_t*>(Ch + zC + (size_t)r * ldc + c) = h;
                    *reinterpret_cast<uint32_t*>(Cl + zC + (size_t)r * ldc + c) = l;
                    split2(v10, v11, h, l);
                    *reinterpret_cast<uint32_t*>(Ch + zC + (size_t)(r + 8) * ldc + c) = h;
                    *reinterpret_cast<uint32_t*>(Cl + zC + (size_t)(r + 8) * ldc + c) = l;
                }
            }
        }
    }
}

// ---------------------------------------------------------------------------
// PV GEMM fp16, 1 product: X_h = E (fp16) @ V' (fp16 single plane).
// ---------------------------------------------------------------------------
#define PV_STAGE 32768
#define PV_SMEM  98304

__global__ __launch_bounds__(256) void pv_gemm(
    const __half* __restrict__ Ag,
    const __half* __restrict__ Bg,
    __half* __restrict__ Co)
{
    extern __shared__ __align__(16) char smem[];
    const uint32_t sbase = (uint32_t)__cvta_generic_to_shared(smem);
    const int tid = threadIdx.x, lane = tid & 31, wid = tid >> 5;
    const int wm = wid >> 2, wn = wid & 3;
    const int rowBase = blockIdx.y * 128;
    const __half* A = Ag + (size_t)blockIdx.z * Ss * Ss;
    const __half* B = Bg + (size_t)blockIdx.z * Ss * HD;
    const size_t zC = (size_t)blockIdx.z * Ss * HD;

    float acc[4][4][4] = {};

    auto copyStage = [&](int st, int k0) {
        uint32_t aOff = sbase + st * PV_STAGE;
        #pragma unroll
        for (int t = 0; t < 4; t++) {
            int idx = tid + t * 256;
            int r = idx >> 3, c = idx & 7;
            cpa(aOff + r * 128 + ((c ^ (r & 7)) << 4), A + (size_t)(rowBase + r) * Ss + (k0 + c * 8));
        }
        uint32_t bOff = aOff + 16384;
        #pragma unroll
        for (int t = 0; t < 4; t++) {
            int idx = tid + t * 256;
            int r = idx >> 4, c = idx & 15;
            cpa(bOff + r * 256 + ((c ^ (r & 7)) << 4), B + (size_t)(k0 + r) * HD + c * 8);
        }
    };

    auto computeStage = [&](int st) {
        uint32_t aP  = sbase + st * PV_STAGE;
        uint32_t bP  = aP + 16384;
        #pragma unroll
        for (int ks = 0; ks < 4; ks++) {
            uint32_t af[4][4];
            uint32_t bfr[4][2];
            #pragma unroll
            for (int mt = 0; mt < 4; mt++) {
                int row = wm * 64 + mt * 16 + (lane & 15);
                int ch = ks * 2 + (lane >> 4);
                ldsm4(af[mt][0], af[mt][1], af[mt][2], af[mt][3],
                      aP + (uint32_t)(row * 128 + ((ch ^ (row & 7)) << 4)));
            }
            #pragma unroll
            for (int i = 0; i < 2; i++) {
                int row = ks * 16 + ((lane >> 3) & 1) * 8 + (lane & 7);
                int ch = wn * 4 + i * 2 + (lane >> 4);
                uint32_t bd = (uint32_t)(row * 256 + ((ch ^ (row & 7)) << 4));
                uint32_t r0, r1, r2, r3;
                ldsm4t(r0, r1, r2, r3, bP + bd);
                bfr[2*i][0] = r0; bfr[2*i][1] = r1; bfr[2*i+1][0] = r2; bfr[2*i+1][1] = r3;
            }
            #pragma unroll
            for (int mt = 0; mt < 4; mt++)
                #pragma unroll
                for (int nt = 0; nt < 4; nt++)
                    mma16816h(acc[mt][nt], af[mt], bfr[nt]);
        }
    };

    const int nk = Ss >> 6;   // 32
    copyStage(0, 0);
    asm volatile("cp.async.commit_group;" ::: "memory");
    copyStage(1, 64);
    asm volatile("cp.async.commit_group;" ::: "memory");
    int st = 0;
    for (int kt = 0; kt < nk; kt++) {
        if (kt + 2 < nk) {
            int pst = st + 2; if (pst >= 3) pst -= 3;
            copyStage(pst, (kt + 2) * 64);
            asm volatile("cp.async.commit_group;" ::: "memory");
            asm volatile("cp.async.wait_group 2;" ::: "memory");
        } else if (kt + 1 < nk) {
            asm volatile("cp.async.wait_group 1;" ::: "memory");
        } else {
            asm volatile("cp.async.wait_group 0;" ::: "memory");
        }
        __syncthreads();
        computeStage(st);
        __syncthreads();
        if (++st == 3) st = 0;
    }

    #pragma unroll
    for (int mt = 0; mt < 4; mt++) {
        #pragma unroll
        for (int nt = 0; nt < 4; nt++) {
            int r = rowBase + wm * 64 + mt * 16 + (lane >> 2);
            int c = wn * 32 + nt * 8 + (lane & 3) * 2;
            __half2 p0 = __floats2half2_rn(acc[mt][nt][0], acc[mt][nt][1]);
            __half2 p1 = __floats2half2_rn(acc[mt][nt][2], acc[mt][nt][3]);
            *reinterpret_cast<__half2*>(Co + zC + (size_t)r * HD + c) = p0;
            *reinterpret_cast<__half2*>(Co + zC + (size_t)(r + 8) * HD + c) = p1;
        }
    }
}

// ---------------------------------------------------------------------------
// V'[k,d] = V[k,d]/Z[k] -> fp16 single plane
// ---------------------------------------------------------------------------
__global__ __launch_bounds__(256) void vscale_kernel(const __half* __restrict__ V16,
                                                     const float* __restrict__ Z,
                                                     __half* __restrict__ Vo)
{
    size_t i = (size_t)blockIdx.x * 256 + threadIdx.x;
    size_t kz = i >> 7;
    float inv = __fdividef(1.0f, Z[kz]);
    Vo[i] = __float2half_rn(__half2float(V16[i]) * inv);
}

// ---------------------------------------------------------------------------
// Launch
// ---------------------------------------------------------------------------
extern "C" void kernel_launch(void* const* d_in, const int* in_sizes, int n_in,
                              void* d_out, int out_size)
{
    const float* query = (const float*)d_in[0];
    const float* key   = (const float*)d_in[1];
    const float* value = (const float*)d_in[2];
    const float* Wq    = (const float*)d_in[3];
    const float* bq    = (const float*)d_in[4];
    const float* Wk    = (const float*)d_in[5];
    const float* bk    = (const float*)d_in[6];
    const float* Wv    = (const float*)d_in[7];
    const float* bv    = (const float*)d_in[8];
    const float* Wo    = (const float*)d_in[9];
    const float* bo    = (const float*)d_in[10];
    float* out = (float*)d_out;

    #define SYM(p, s) do { void* tmp_; cudaGetSymbolAddress(&tmp_, s); p = (decltype(p))tmp_; } while (0)
    bf16 *iqkh, *iqkl, *wqkh, *wqkl, *QKh, *QKl;
    __half *iv16, *Wv16, *Wo16, *V16, *Ep, *Vop, *X16;
    float *bqk, *Mxp, *Zp;
    SYM(iqkh, g_iqk_h); SYM(iqkl, g_iqk_l);
    SYM(wqkh, g_wqk_h); SYM(wqkl, g_wqk_l);
    SYM(bqk, g_bqk);
    SYM(iv16, g_iv16); SYM(Wv16, g_Wv16); SYM(Wo16, g_Wo16);
    SYM(QKh, g_QK_h); SYM(QKl, g_QK_l);
    SYM(V16, g_V16); SYM(Vop, g_Vo); SYM(X16, g_X16);
    SYM(Ep, g_E); SYM(Mxp, g_Mx); SYM(Zp, g_Z);
    #undef SYM
    bf16 *Qh = QKh, *Ql = QKl, *Kh = QKh + NELEM, *Kl = QKl + NELEM;

    const int SMEMB = 1024 + 3 * STG;   // 99328 for all GEMM variants
    cudaFuncSetAttribute(mma_gemm<0, 1, 0, 0>, cudaFuncAttributeMaxDynamicSharedMemorySize, SMEMB);
    cudaFuncSetAttribute(mma_gemm<1, 2, 1, 0>, cudaFuncAttributeMaxDynamicSharedMemorySize, SMEMB);
    cudaFuncSetAttribute(mma_gemm<1, 3, 0, 0>, cudaFuncAttributeMaxDynamicSharedMemorySize, SMEMB);
    cudaFuncSetAttribute(mma_gemm<0, 0, 1, 1>, cudaFuncAttributeMaxDynamicSharedMemorySize, SMEMB);
    cudaFuncSetAttribute(mma_gemm<0, 4, 1, 1>, cudaFuncAttributeMaxDynamicSharedMemorySize, SMEMB);
    cudaFuncSetAttribute(pv_gemm, cudaFuncAttributeMaxDynamicSharedMemorySize, PV_SMEM);

    // 0) Re-init Mx (-inf) and Z (0); copy biases to pair buffer
    init_mz<<<(BH * Ss) / 256, 256>>>(Mxp, Zp);
    cudaMemcpyAsync(bqk,      bq, Dd * sizeof(float), cudaMemcpyDeviceToDevice);
    cudaMemcpyAsync(bqk + Dd, bk, Dd * sizeof(float), cudaMemcpyDeviceToDevice);

    // 1) Fused prep
    {
        int n4i = (int)(NELEM / 4), n4w = (int)(WELEM / 4);
        split2_f32<<<2 * n4i / 256, 256>>>((const float4*)query, (const float4*)key,
                                           (uint2*)iqkh, (uint2*)iqkl, n4i);
        split2_f32<<<2 * n4w / 256, 256>>>((const float4*)Wq, (const float4*)Wk,
                                           (uint2*)wqkh, (uint2*)wqkl, n4w);
        cvt3_f16<<<(n4i + 2 * n4w) / 256, 256>>>((const float4*)value, (uint2*)iv16, n4i,
                                                 (const float4*)Wv, (uint2*)Wv16, n4w,
                                                 (const float4*)Wo, (uint2*)Wo16);
    }

    // 2) Q+K projections batched (bf16x3, grid.z=2) + V projection (fp16 1-product)
    {
        dim3 gridQK(Dd / 128, MROWS / 128, 2);
        mma_gemm<0, 1, 0, 0><<<gridQK, 256, SMEMB>>>(iqkh, iqkl, wqkh, wqkl, bqk,
                                                     nullptr, QKh, QKl,
                                                     nullptr, nullptr, Dd, Dd, Dd, Dd,
                                                     NELEM, WELEM, NELEM);
        dim3 gridV(Dd / 128, MROWS / 128, 1);
        mma_gemm<0, 4, 1, 1><<<gridV, 256, SMEMB>>>((const bf16*)iv16, nullptr,
                                                    (const bf16*)Wv16, nullptr, bv,
                                                    nullptr, (bf16*)V16, nullptr,
                                                    nullptr, nullptr, Dd, Dd, Dd, Dd, 0, 0, 0);
    }

    // 3a) Scores max pass: Mx = colmax(Q_h @ K_h^T)
    {
        dim3 grid(Ss / 128, Ss / 128, BH);
        mma_gemm<1, 2, 1, 0><<<grid, 256, SMEMB>>>(Qh, nullptr, Kh, nullptr, nullptr,
                                                   nullptr, nullptr, nullptr, Mxp, nullptr,
                                                   HD, HD, HD, Ss,
                                                   (size_t)Ss * HD, (size_t)Ss * HD, 0);
    }

    // 3b) Scores full pass (3-product, BK=32) + fused exp + Z
    {
        dim3 grid(Ss / 128, Ss / 128, BH);
        mma_gemm<1, 3, 0, 0><<<grid, 256, SMEMB>>>(Qh, Ql, Kh, Kl, nullptr,
                                                   nullptr, (bf16*)Ep, nullptr, Mxp, Zp,
                                                   HD, HD, HD, Ss,
                                                   (size_t)Ss * HD, (size_t)Ss * HD, (size_t)Ss * Ss);
    }

    // 4) V' = V/Z (fp16)
    vscale_kernel<<<(unsigned)(NELEM / 256), 256>>>(V16, Zp, Vop);

    // 5) PV per head (fp16 1-product)
    {
        dim3 grid(1, Ss / 128, BH);
        pv_gemm<<<grid, 256, PV_SMEM>>>(Ep, Vop, X16);
    }

    // 6) Output projection (fp16 1-product) -> fp32 out
    {
        dim3 grid(Dd / 128, MROWS / 128, 1);
        mma_gemm<0, 0, 1, 1><<<grid, 256, SMEMB>>>((const bf16*)X16, nullptr,
                                                   (const bf16*)Wo16, nullptr, bo,
                                                   out, nullptr, nullptr,
                                                   nullptr, nullptr, Dd, Dd, Dd, Dd, 0, 0, 0);
    }
}

// round 16
// speedup vs baseline: 6.1861x; 1.0043x over previous
#include <cuda_runtime.h>
#include <cuda_bf16.h>
#include <cuda_fp16.h>
#include <cstdint>
#include <math.h>

// Problem constants
#define Bb 4
#define Ss 2048
#define Dd 1024
#define Hh 8
#define HD 128
#define BH (Bb*Hh)            // 32 head-slices
#define MROWS (Bb*Ss)         // 8192
#define NELEM ((size_t)MROWS * Dd)      // 8M
#define WELEM ((size_t)Dd * Dd)         // 1M
#define SELEM ((size_t)BH * Ss * Ss)    // 128M

typedef __nv_bfloat16 bf16;
typedef __nv_bfloat162 bf162;

// ---------------------------------------------------------------------------
// Device scratch (allocation-free rule: __device__ globals)
// ---------------------------------------------------------------------------
__device__ __align__(256) bf16 g_iqk_h[2*NELEM], g_iqk_l[2*NELEM];   // [query | key]
__device__ __align__(256) bf16 g_wqk_h[2*WELEM], g_wqk_l[2*WELEM];   // [Wq | Wk]
__device__ __align__(256) float g_bqk[2*Dd];                          // [bq | bk]
__device__ __align__(256) __half g_iv16[NELEM];                       // value fp16
__device__ __align__(256) __half g_Wv16[WELEM];                       // Wv fp16
__device__ __align__(256) __half g_Wo16[WELEM];                       // Wo fp16
__device__ __align__(256) bf16 g_QK_h[2*NELEM], g_QK_l[2*NELEM];     // [Q | K]
__device__ __align__(256) __half g_V16[NELEM];                        // V fp16
__device__ __align__(256) __half g_Vo[NELEM];                         // V' fp16
__device__ __align__(256) __half g_X16[NELEM];                        // X fp16
__device__ __align__(256) __half g_E[SELEM];                          // fp16 E plane
__device__ __align__(256) float g_Mx[(size_t)BH * Ss];
__device__ __align__(256) float g_Z [(size_t)BH * Ss];

// ---------------------------------------------------------------------------
// PTX helpers
// ---------------------------------------------------------------------------
__device__ __forceinline__ void cpa(uint32_t dst, const void* src) {
    asm volatile("cp.async.cg.shared.global [%0], [%1], 16;\n" :: "r"(dst), "l"(src));
}
__device__ __forceinline__ void ldsm4(uint32_t& r0, uint32_t& r1, uint32_t& r2, uint32_t& r3, uint32_t a) {
    asm volatile("ldmatrix.sync.aligned.m8n8.x4.shared.b16 {%0,%1,%2,%3}, [%4];"
                 : "=r"(r0), "=r"(r1), "=r"(r2), "=r"(r3) : "r"(a));
}
__device__ __forceinline__ void ldsm4t(uint32_t& r0, uint32_t& r1, uint32_t& r2, uint32_t& r3, uint32_t a) {
    asm volatile("ldmatrix.sync.aligned.m8n8.x4.trans.shared.b16 {%0,%1,%2,%3}, [%4];"
                 : "=r"(r0), "=r"(r1), "=r"(r2), "=r"(r3) : "r"(a));
}
__device__ __forceinline__ void mma16816(float* c, const uint32_t* a, const uint32_t* b) {
    asm volatile("mma.sync.aligned.m16n8k16.row.col.f32.bf16.bf16.f32 "
                 "{%0,%1,%2,%3},{%4,%5,%6,%7},{%8,%9},{%0,%1,%2,%3};"
                 : "+f"(c[0]), "+f"(c[1]), "+f"(c[2]), "+f"(c[3])
                 : "r"(a[0]), "r"(a[1]), "r"(a[2]), "r"(a[3]), "r"(b[0]), "r"(b[1]));
}
__device__ __forceinline__ void mma16816h(float* c, const uint32_t* a, const uint32_t* b) {
    asm volatile("mma.sync.aligned.m16n8k16.row.col.f32.f16.f16.f32 "
                 "{%0,%1,%2,%3},{%4,%5,%6,%7},{%8,%9},{%0,%1,%2,%3};"
                 : "+f"(c[0]), "+f"(c[1]), "+f"(c[2]), "+f"(c[3])
                 : "r"(a[0]), "r"(a[1]), "r"(a[2]), "r"(a[3]), "r"(b[0]), "r"(b[1]));
}
__device__ __forceinline__ uint32_t pack2(bf16 a, bf16 b) {
    bf162 t(a, b);
    return *reinterpret_cast<uint32_t*>(&t);
}
__device__ __forceinline__ void split2(float v0, float v1, uint32_t& hi, uint32_t& lo) {
    bf16 h0 = __float2bfloat16_rn(v0);
    bf16 h1 = __float2bfloat16_rn(v1);
    bf16 l0 = __float2bfloat16_rn(v0 - __bfloat162float(h0));
    bf16 l1 = __float2bfloat16_rn(v1 - __bfloat162float(h1));
    hi = pack2(h0, h1);
    lo = pack2(l0, l1);
}
__device__ __forceinline__ void atomicMaxF(float* addr, float v) {
    if (v >= 0.f) atomicMax((int*)addr, __float_as_int(v));
    else          atomicMin((unsigned int*)addr, (unsigned int)__float_as_int(v));
}

// ---------------------------------------------------------------------------
// Elementwise prep (fused multi-source kernels)
// ---------------------------------------------------------------------------
__global__ __launch_bounds__(256) void split2_f32(const float4* __restrict__ x0,
                                                  const float4* __restrict__ x1,
                                                  uint2* __restrict__ hi, uint2* __restrict__ lo,
                                                  int n4)
{
    int i = blockIdx.x * 256 + threadIdx.x;
    float4 v = (i < n4) ? x0[i] : x1[i - n4];
    uint32_t h01, l01, h23, l23;
    split2(v.x, v.y, h01, l01);
    split2(v.z, v.w, h23, l23);
    hi[i] = make_uint2(h01, h23);
    lo[i] = make_uint2(l01, l23);
}

__global__ __launch_bounds__(256) void cvt3_f16(const float4* __restrict__ x0, uint2* __restrict__ o0, int n0,
                                                const float4* __restrict__ x1, uint2* __restrict__ o1, int n1,
                                                const float4* __restrict__ x2, uint2* __restrict__ o2)
{
    int i = blockIdx.x * 256 + threadIdx.x;
    const float4* x; uint2* o; int j;
    if (i < n0)           { x = x0; o = o0; j = i; }
    else if (i < n0 + n1) { x = x1; o = o1; j = i - n0; }
    else                  { x = x2; o = o2; j = i - n0 - n1; }
    float4 v = x[j];
    __half2 a = __floats2half2_rn(v.x, v.y);
    __half2 b = __floats2half2_rn(v.z, v.w);
    o[j] = make_uint2(*reinterpret_cast<uint32_t*>(&a), *reinterpret_cast<uint32_t*>(&b));
}

// Re-init Mx/Z every launch (graph-replay safe) + copy bq/bk into pair buffer.
__global__ __launch_bounds__(256) void init_mz(float* __restrict__ Mx, float* __restrict__ Z,
                                               const float* __restrict__ bq, const float* __restrict__ bk,
                                               float* __restrict__ bqk)
{
    int i = blockIdx.x * 256 + threadIdx.x;   // BH*Ss = 65536
    Mx[i] = -1e30f;
    Z[i] = 0.f;
    if (i < Dd)           bqk[i] = bq[i];
    else if (i < 2 * Dd)  bqk[i] = bk[i - Dd];
}

// ---------------------------------------------------------------------------
// MMA GEMM, 3-stage cp.async pipeline, 32KB stages -> 2 blocks/SM everywhere.
// FULL (!LITE): BK=32, combined-plane layout (A rows = [hi 64B | lo 64B]).
// LITE: BK=64, single hi plane per operand.
// EPI:  0 fp32 out, 1 bf16 hi/lo out, 2 colmax->Mx, 3 exp->E + Z, 4 fp16 out.
// FK:   0 bf16 MMA, 1 fp16 MMA (LITE only).
// bias indexed bias[blockIdx.z*ldc + c].
// ---------------------------------------------------------------------------
#define STG 32768

template<int BLAY, int EPI, int LITE, int FK>
__global__ __launch_bounds__(256) void mma_gemm(
    const bf16* __restrict__ Ah, const bf16* __restrict__ Al,
    const bf16* __restrict__ Bh, const bf16* __restrict__ Bl,
    const float* __restrict__ bias,
    float* __restrict__ Cf, bf16* __restrict__ Ch, bf16* __restrict__ Cl,
    float* __restrict__ Mx, float* __restrict__ Zp,
    int K, int lda, int ldb, int ldc,
    size_t sA, size_t sB, size_t sC)
{
    constexpr int BKI = LITE ? 64 : 32;
    extern __shared__ __align__(16) char smem[];
    float* sRed = reinterpret_cast<float*>(smem);
    const uint32_t sbase = (uint32_t)__cvta_generic_to_shared(smem) + 1024;
    const int tid = threadIdx.x, lane = tid & 31, wid = tid >> 5;
    const int wm = wid >> 2, wn = wid & 3;
    const int rowBase = blockIdx.y * 128, colBase = blockIdx.x * 128;
    const bf16* Agh = Ah + (size_t)blockIdx.z * sA;
    const bf16* Agl = Al + (size_t)blockIdx.z * sA;
    const bf16* Bgh = Bh + (size_t)blockIdx.z * sB;
    const bf16* Bgl = Bl + (size_t)blockIdx.z * sB;
    const size_t zC = (size_t)blockIdx.z * sC;
    const size_t zBias = (size_t)blockIdx.z * ldc;

    float acc[4][4][4] = {};

    auto copyStage = [&](int st, int k0) {
        uint32_t aOff = sbase + st * STG;
        uint32_t bOff = aOff + 16384;
        if (LITE) {
            #pragma unroll
            for (int t = 0; t < 4; t++) {
                int idx = tid + t * 256;
                int r = idx >> 3, c = idx & 7;
                cpa(aOff + r * 128 + ((c ^ (r & 7)) << 4),
                    Agh + (size_t)(rowBase + r) * lda + (k0 + c * 8));
            }
            #pragma unroll
            for (int t = 0; t < 4; t++) {
                int idx = tid + t * 256;
                if (BLAY == 0) {
                    int r = idx >> 4, c = idx & 15;
                    cpa(bOff + r * 256 + ((c ^ (r & 7)) << 4),
                        Bgh + (size_t)(k0 + r) * ldb + (colBase + c * 8));
                } else {
                    int r = idx >> 3, c = idx & 7;
                    cpa(bOff + r * 128 + ((c ^ (r & 7)) << 4),
                        Bgh + (size_t)(colBase + r) * ldb + (k0 + c * 8));
                }
            }
        } else {
            #pragma unroll
            for (int t = 0; t < 4; t++) {
                int idx = tid + t * 256;
                int r = idx >> 3, c = idx & 7;
                const bf16* Ag = (c & 4) ? Agl : Agh;
                int kc = c & 3;
                cpa(aOff + r * 128 + ((c ^ (r & 7)) << 4),
                    Ag + (size_t)(rowBase + r) * lda + (k0 + kc * 8));
            }
            if (BLAY == 0) {
                #pragma unroll
                for (int t = 0; t < 4; t++) {
                    int idx = tid + t * 256;
                    int plane = idx >> 9;
                    int rem = idx & 511;
                    int r = rem >> 4, c = rem & 15;
                    const bf16* Bg = plane ? Bgl : Bgh;
                    cpa(bOff + plane * 8192 + r * 256 + ((c ^ (r & 7)) << 4),
                        Bg + (size_t)(k0 + r) * ldb + (colBase + c * 8));
                }
            } else {
                #pragma unroll
                for (int t = 0; t < 4; t++) {
                    int idx = tid + t * 256;
                    int r = idx >> 3, c = idx & 7;
                    const bf16* Bg = (c & 4) ? Bgl : Bgh;
                    int kc = c & 3;
                    cpa(bOff + r * 128 + ((c ^ (r & 7)) << 4),
                        Bg + (size_t)(colBase + r) * ldb + (k0 + kc * 8));
                }
            }
        }
    };

    auto computeStage = [&](int st) {
        uint32_t aOff = sbase + st * STG;
        uint32_t bOff = aOff + 16384;
        constexpr int NKS = LITE ? 4 : 2;
        #pragma unroll
        for (int ks = 0; ks < NKS; ks++) {
            uint32_t af[2][4][4];
            uint32_t bfr[2][4][2];
            #pragma unroll
            for (int mt = 0; mt < 4; mt++) {
                int row = wm * 64 + mt * 16 + (lane & 15);
                int chh = ks * 2 + (lane >> 4);
                ldsm4(af[0][mt][0], af[0][mt][1], af[0][mt][2], af[0][mt][3],
                      aOff + (uint32_t)(row * 128 + ((chh ^ (row & 7)) << 4)));
                if (!LITE) {
                    int chl = chh + 4;
                    ldsm4(af[1][mt][0], af[1][mt][1], af[1][mt][2], af[1][mt][3],
                          aOff + (uint32_t)(row * 128 + ((chl ^ (row & 7)) << 4)));
                }
            }
            #pragma unroll
            for (int i = 0; i < 2; i++) {
                if (BLAY == 0) {
                    int row = ks * 16 + ((lane >> 3) & 1) * 8 + (lane & 7);
                    int ch = wn * 4 + i * 2 + (lane >> 4);
                    uint32_t bd = (uint32_t)(row * 256 + ((ch ^ (row & 7)) << 4));
                    uint32_t r0, r1, r2, r3;
                    ldsm4t(r0, r1, r2, r3, bOff + bd);
                    bfr[0][2*i][0] = r0; bfr[0][2*i][1] = r1; bfr[0][2*i+1][0] = r2; bfr[0][2*i+1][1] = r3;
                    if (!LITE) {
                        ldsm4t(r0, r1, r2, r3, bOff + 8192 + bd);
                        bfr[1][2*i][0] = r0; bfr[1][2*i][1] = r1; bfr[1][2*i+1][0] = r2; bfr[1][2*i+1][1] = r3;
                    }
                } else {
                    int row = wn * 32 + i * 16 + ((lane >> 4) << 3) + (lane & 7);
                    int chh = ks * 2 + ((lane >> 3) & 1);
                    uint32_t r0, r1, r2, r3;
                    ldsm4(r0, r1, r2, r3, bOff + (uint32_t)(row * 128 + ((chh ^ (row & 7)) << 4)));
                    bfr[0][2*i][0] = r0; bfr[0][2*i][1] = r1; bfr[0][2*i+1][0] = r2; bfr[0][2*i+1][1] = r3;
                    if (!LITE) {
                        int chl = chh + 4;
                        ldsm4(r0, r1, r2, r3, bOff + (uint32_t)(row * 128 + ((chl ^ (row & 7)) << 4)));
                        bfr[1][2*i][0] = r0; bfr[1][2*i][1] = r1; bfr[1][2*i+1][0] = r2; bfr[1][2*i+1][1] = r3;
                    }
                }
            }
            #pragma unroll
            for (int mt = 0; mt < 4; mt++)
                #pragma unroll
                for (int nt = 0; nt < 4; nt++) {
                    if (FK) mma16816h(acc[mt][nt], af[0][mt], bfr[0][nt]);
                    else    mma16816(acc[mt][nt], af[0][mt], bfr[0][nt]);
                    if (!LITE) {
                        mma16816(acc[mt][nt], af[0][mt], bfr[1][nt]);
                        mma16816(acc[mt][nt], af[1][mt], bfr[0][nt]);
                    }
                }
        }
    };

    const int nk = K / BKI;
    copyStage(0, 0);
    asm volatile("cp.async.commit_group;" ::: "memory");
    if (nk > 1) {
        copyStage(1, BKI);
        asm volatile("cp.async.commit_group;" ::: "memory");
    }
    if (nk > 2) {
        copyStage(2, 2 * BKI);
        asm volatile("cp.async.commit_group;" ::: "memory");
    }
    int st = 0;
    for (int kt = 0; kt < nk; kt++) {
        int rem = nk - 1 - kt;
        if (rem >= 2)      asm volatile("cp.async.wait_group 2;" ::: "memory");
        else if (rem == 1) asm volatile("cp.async.wait_group 1;" ::: "memory");
        else               asm volatile("cp.async.wait_group 0;" ::: "memory");
        __syncthreads();
        computeStage(st);
        __syncthreads();
        if (kt + 3 < nk) {
            copyStage(st, (kt + 3) * BKI);
            asm volatile("cp.async.commit_group;" ::: "memory");
        }
        if (++st == 3) st = 0;
    }

    if (EPI == 2) {
        if (tid < 128) sRed[tid] = -1e30f;
        __syncthreads();
        #pragma unroll
        for (int nt = 0; nt < 4; nt++) {
            float cm0 = -1e30f, cm1 = -1e30f;
            #pragma unroll
            for (int mt = 0; mt < 4; mt++) {
                cm0 = fmaxf(cm0, fmaxf(acc[mt][nt][0], acc[mt][nt][2]));
                cm1 = fmaxf(cm1, fmaxf(acc[mt][nt][1], acc[mt][nt][3]));
            }
            int ci = wn * 32 + nt * 8 + (lane & 3) * 2;
            atomicMaxF(&sRed[ci], cm0);
            atomicMaxF(&sRed[ci + 1], cm1);
        }
        __syncthreads();
        if (tid < 128)
            atomicMaxF(Mx + (size_t)blockIdx.z * ldc + colBase + tid, sRed[tid]);
    } else if (EPI == 3) {
        if (tid < 128) sRed[tid] = 0.f;
        __syncthreads();
        const float* Mrow = Mx + (size_t)blockIdx.z * ldc + colBase;
        __half* Eo = reinterpret_cast<__half*>(Ch) + zC;
        #pragma unroll
        for (int nt = 0; nt < 4; nt++) {
            int ci = wn * 32 + nt * 8 + (lane & 3) * 2;
            float m0 = Mrow[ci], m1 = Mrow[ci + 1];
            float z0 = 0.f, z1 = 0.f;
            #pragma unroll
            for (int mt = 0; mt < 4; mt++) {
                int r = rowBase + wm * 64 + mt * 16 + (lane >> 2);
                float e00 = __expf(acc[mt][nt][0] - m0);
                float e01 = __expf(acc[mt][nt][1] - m1);
                float e10 = __expf(acc[mt][nt][2] - m0);
                float e11 = __expf(acc[mt][nt][3] - m1);
                z0 += e00 + e10;
                z1 += e01 + e11;
                __half2 p0 = __floats2half2_rn(e00, e01);
                __half2 p1 = __floats2half2_rn(e10, e11);
                *reinterpret_cast<__half2*>(Eo + (size_t)r * ldc + colBase + ci) = p0;
                *reinterpret_cast<__half2*>(Eo + (size_t)(r + 8) * ldc + colBase + ci) = p1;
            }
            #pragma unroll
            for (int off = 16; off >= 4; off >>= 1) {
                z0 += __shfl_down_sync(0xffffffffu, z0, off);
                z1 += __shfl_down_sync(0xffffffffu, z1, off);
            }
            if (lane < 4) {
                atomicAdd(&sRed[ci], z0);
                atomicAdd(&sRed[ci + 1], z1);
            }
        }
        __syncthreads();
        if (tid < 128)
            atomicAdd(Zp + (size_t)blockIdx.z * ldc + colBase + tid, sRed[tid]);
    } else {
        #pragma unroll
        for (int nt = 0; nt < 4; nt++) {
            #pragma unroll
            for (int mt = 0; mt < 4; mt++) {
                int r = rowBase + wm * 64 + mt * 16 + (lane >> 2);
                int c = colBase + wn * 32 + nt * 8 + (lane & 3) * 2;
                float b0 = 0.f, b1 = 0.f;
                if (bias) { b0 = bias[zBias + c]; b1 = bias[zBias + c + 1]; }
                float v00 = acc[mt][nt][0] + b0, v01 = acc[mt][nt][1] + b1;
                float v10 = acc[mt][nt][2] + b0, v11 = acc[mt][nt][3] + b1;
                if (EPI == 0) {
                    *reinterpret_cast<float2*>(Cf + zC + (size_t)r * ldc + c)       = make_float2(v00, v01);
                    *reinterpret_cast<float2*>(Cf + zC + (size_t)(r + 8) * ldc + c) = make_float2(v10, v11);
                } else if (EPI == 4) {
                    __half* Ho = reinterpret_cast<__half*>(Ch);
                    __half2 p0 = __floats2half2_rn(v00, v01);
                    __half2 p1 = __floats2half2_rn(v10, v11);
                    *reinterpret_cast<__half2*>(Ho + zC + (size_t)r * ldc + c)       = p0;
                    *reinterpret_cast<__half2*>(Ho + zC + (size_t)(r + 8) * ldc + c) = p1;
                } else {
                    uint32_t h, l;
                    split2(v00, v01, h, l);
                    *reinterpret_cast<uint32_t*>(Ch + zC + (size_t)r * ldc + c) = h;
                    *reinterpret_cast<uint32_t*>(Cl + zC + (size_t)r * ldc + c) = l;
                    split2(v10, v11, h, l);
                    *reinterpret_cast<uint32_t*>(Ch + zC + (size_t)(r + 8) * ldc + c) = h;
                    *reinterpret_cast<uint32_t*>(Cl + zC + (size_t)(r + 8) * ldc + c) = l;
                }
            }
        }
    }
}

// ---------------------------------------------------------------------------
// PV GEMM fp16, 1 product: X_h = E (fp16) @ V' (fp16 single plane).
// ---------------------------------------------------------------------------
#define PV_STAGE 32768
#define PV_SMEM  98304

__global__ __launch_bounds__(256) void pv_gemm(
    const __half* __restrict__ Ag,
    const __half* __restrict__ Bg,
    __half* __restrict__ Co)
{
    extern __shared__ __align__(16) char smem[];
    const uint32_t sbase = (uint32_t)__cvta_generic_to_shared(smem);
    const int tid = threadIdx.x, lane = tid & 31, wid = tid >> 5;
    const int wm = wid >> 2, wn = wid & 3;
    const int rowBase = blockIdx.y * 128;
    const __half* A = Ag + (size_t)blockIdx.z * Ss * Ss;
    const __half* B = Bg + (size_t)blockIdx.z * Ss * HD;
    const size_t zC = (size_t)blockIdx.z * Ss * HD;

    float acc[4][4][4] = {};

    auto copyStage = [&](int st, int k0) {
        uint32_t aOff = sbase + st * PV_STAGE;
        #pragma unroll
        for (int t = 0; t < 4; t++) {
            int idx = tid + t * 256;
            int r = idx >> 3, c = idx & 7;
            cpa(aOff + r * 128 + ((c ^ (r & 7)) << 4), A + (size_t)(rowBase + r) * Ss + (k0 + c * 8));
        }
        uint32_t bOff = aOff + 16384;
        #pragma unroll
        for (int t = 0; t < 4; t++) {
            int idx = tid + t * 256;
            int r = idx >> 4, c = idx & 15;
            cpa(bOff + r * 256 + ((c ^ (r & 7)) << 4), B + (size_t)(k0 + r) * HD + c * 8);
        }
    };

    auto computeStage = [&](int st) {
        uint32_t aP  = sbase + st * PV_STAGE;
        uint32_t bP  = aP + 16384;
        #pragma unroll
        for (int ks = 0; ks < 4; ks++) {
            uint32_t af[4][4];
            uint32_t bfr[4][2];
            #pragma unroll
            for (int mt = 0; mt < 4; mt++) {
                int row = wm * 64 + mt * 16 + (lane & 15);
                int ch = ks * 2 + (lane >> 4);
                ldsm4(af[mt][0], af[mt][1], af[mt][2], af[mt][3],
                      aP + (uint32_t)(row * 128 + ((ch ^ (row & 7)) << 4)));
            }
            #pragma unroll
            for (int i = 0; i < 2; i++) {
                int row = ks * 16 + ((lane >> 3) & 1) * 8 + (lane & 7);
                int ch = wn * 4 + i * 2 + (lane >> 4);
                uint32_t bd = (uint32_t)(row * 256 + ((ch ^ (row & 7)) << 4));
                uint32_t r0, r1, r2, r3;
                ldsm4t(r0, r1, r2, r3, bP + bd);
                bfr[2*i][0] = r0; bfr[2*i][1] = r1; bfr[2*i+1][0] = r2; bfr[2*i+1][1] = r3;
            }
            #pragma unroll
            for (int mt = 0; mt < 4; mt++)
                #pragma unroll
                for (int nt = 0; nt < 4; nt++)
                    mma16816h(acc[mt][nt], af[mt], bfr[nt]);
        }
    };

    const int nk = Ss >> 6;   // 32
    copyStage(0, 0);
    asm volatile("cp.async.commit_group;" ::: "memory");
    copyStage(1, 64);
    asm volatile("cp.async.commit_group;" ::: "memory");
    int st = 0;
    for (int kt = 0; kt < nk; kt++) {
        if (kt + 2 < nk) {
            int pst = st + 2; if (pst >= 3) pst -= 3;
            copyStage(pst, (kt + 2) * 64);
            asm volatile("cp.async.commit_group;" ::: "memory");
            asm volatile("cp.async.wait_group 2;" ::: "memory");
        } else if (kt + 1 < nk) {
            asm volatile("cp.async.wait_group 1;" ::: "memory");
        } else {
            asm volatile("cp.async.wait_group 0;" ::: "memory");
        }
        __syncthreads();
        computeStage(st);
        __syncthreads();
        if (++st == 3) st = 0;
    }

    #pragma unroll
    for (int mt = 0; mt < 4; mt++) {
        #pragma unroll
        for (int nt = 0; nt < 4; nt++) {
            int r = rowBase + wm * 64 + mt * 16 + (lane >> 2);
            int c = wn * 32 + nt * 8 + (lane & 3) * 2;
            __half2 p0 = __floats2half2_rn(acc[mt][nt][0], acc[mt][nt][1]);
            __half2 p1 = __floats2half2_rn(acc[mt][nt][2], acc[mt][nt][3]);
            *reinterpret_cast<__half2*>(Co + zC + (size_t)r * HD + c) = p0;
            *reinterpret_cast<__half2*>(Co + zC + (size_t)(r + 8) * HD + c) = p1;
        }
    }
}

// ---------------------------------------------------------------------------
// V'[k,d] = V[k,d]/Z[k] -> fp16 single plane
// ---------------------------------------------------------------------------
__global__ __launch_bounds__(256) void vscale_kernel(const __half* __restrict__ V16,
                                                     const float* __restrict__ Z,
                                                     __half* __restrict__ Vo)
{
    size_t i = (size_t)blockIdx.x * 256 + threadIdx.x;
    size_t kz = i >> 7;
    float inv = __fdividef(1.0f, Z[kz]);
    Vo[i] = __float2half_rn(__half2float(V16[i]) * inv);
}

// ---------------------------------------------------------------------------
// Launch (single stream, no statics, no events)
// ---------------------------------------------------------------------------
extern "C" void kernel_launch(void* const* d_in, const int* in_sizes, int n_in,
                              void* d_out, int out_size)
{
    const float* query = (const float*)d_in[0];
    const float* key   = (const float*)d_in[1];
    const float* value = (const float*)d_in[2];
    const float* Wq    = (const float*)d_in[3];
    const float* bq    = (const float*)d_in[4];
    const float* Wk    = (const float*)d_in[5];
    const float* bk    = (const float*)d_in[6];
    const float* Wv    = (const float*)d_in[7];
    const float* bv    = (const float*)d_in[8];
    const float* Wo    = (const float*)d_in[9];
    const float* bo    = (const float*)d_in[10];
    float* out = (float*)d_out;

    #define SYM(p, s) do { void* tmp_; cudaGetSymbolAddress(&tmp_, s); p = (decltype(p))tmp_; } while (0)
    bf16 *iqkh, *iqkl, *wqkh, *wqkl, *QKh, *QKl;
    __half *iv16, *Wv16, *Wo16, *V16, *Ep, *Vop, *X16;
    float *bqk, *Mxp, *Zp;
    SYM(iqkh, g_iqk_h); SYM(iqkl, g_iqk_l);
    SYM(wqkh, g_wqk_h); SYM(wqkl, g_wqk_l);
    SYM(bqk, g_bqk);
    SYM(iv16, g_iv16); SYM(Wv16, g_Wv16); SYM(Wo16, g_Wo16);
    SYM(QKh, g_QK_h); SYM(QKl, g_QK_l);
    SYM(V16, g_V16); SYM(Vop, g_Vo); SYM(X16, g_X16);
    SYM(Ep, g_E); SYM(Mxp, g_Mx); SYM(Zp, g_Z);
    #undef SYM
    bf16 *Qh = QKh, *Ql = QKl, *Kh = QKh + NELEM, *Kl = QKl + NELEM;

    const int SMEMB = 1024 + 3 * STG;   // 99328 for all GEMM variants
    cudaFuncSetAttribute(mma_gemm<0, 1, 0, 0>, cudaFuncAttributeMaxDynamicSharedMemorySize, SMEMB);
    cudaFuncSetAttribute(mma_gemm<1, 2, 1, 0>, cudaFuncAttributeMaxDynamicSharedMemorySize, SMEMB);
    cudaFuncSetAttribute(mma_gemm<1, 3, 0, 0>, cudaFuncAttributeMaxDynamicSharedMemorySize, SMEMB);
    cudaFuncSetAttribute(mma_gemm<0, 0, 1, 1>, cudaFuncAttributeMaxDynamicSharedMemorySize, SMEMB);
    cudaFuncSetAttribute(mma_gemm<0, 4, 1, 1>, cudaFuncAttributeMaxDynamicSharedMemorySize, SMEMB);
    cudaFuncSetAttribute(pv_gemm, cudaFuncAttributeMaxDynamicSharedMemorySize, PV_SMEM);

    // 0) Re-init Mx/Z + copy biases into pair buffer (one kernel)
    init_mz<<<(BH * Ss) / 256, 256>>>(Mxp, Zp, bq, bk, bqk);

    // 1) Fused prep
    int n4i = (int)(NELEM / 4), n4w = (int)(WELEM / 4);
    split2_f32<<<2 * n4i / 256, 256>>>((const float4*)query, (const float4*)key,
                                       (uint2*)iqkh, (uint2*)iqkl, n4i);
    split2_f32<<<2 * n4w / 256, 256>>>((const float4*)Wq, (const float4*)Wk,
                                       (uint2*)wqkh, (uint2*)wqkl, n4w);
    cvt3_f16<<<(n4i + 2 * n4w) / 256, 256>>>((const float4*)value, (uint2*)iv16, n4i,
                                             (const float4*)Wv, (uint2*)Wv16, n4w,
                                             (const float4*)Wo, (uint2*)Wo16);

    // 2) Q+K projections batched (bf16x3, grid.z=2) + V projection (fp16 1-product)
    {
        dim3 gridQK(Dd / 128, MROWS / 128, 2);
        mma_gemm<0, 1, 0, 0><<<gridQK, 256, SMEMB>>>(iqkh, iqkl, wqkh, wqkl, bqk,
                                                     nullptr, QKh, QKl,
                                                     nullptr, nullptr, Dd, Dd, Dd, Dd,
                                                     NELEM, WELEM, NELEM);
        dim3 gridV(Dd / 128, MROWS / 128, 1);
        mma_gemm<0, 4, 1, 1><<<gridV, 256, SMEMB>>>((const bf16*)iv16, nullptr,
                                                    (const bf16*)Wv16, nullptr, bv,
                                                    nullptr, (bf16*)V16, nullptr,
                                                    nullptr, nullptr, Dd, Dd, Dd, Dd, 0, 0, 0);
    }

    // 3a) Scores max pass: Mx = colmax(Q_h @ K_h^T)
    {
        dim3 grid(Ss / 128, Ss / 128, BH);
        mma_gemm<1, 2, 1, 0><<<grid, 256, SMEMB>>>(Qh, nullptr, Kh, nullptr, nullptr,
                                                   nullptr, nullptr, nullptr, Mxp, nullptr,
                                                   HD, HD, HD, Ss,
                                                   (size_t)Ss * HD, (size_t)Ss * HD, 0);
    }

    // 3b) Scores full pass (3-product, BK=32) + fused exp + Z
    {
        dim3 grid(Ss / 128, Ss / 128, BH);
        mma_gemm<1, 3, 0, 0><<<grid, 256, SMEMB>>>(Qh, Ql, Kh, Kl, nullptr,
                                                   nullptr, (bf16*)Ep, nullptr, Mxp, Zp,
                                                   HD, HD, HD, Ss,
                                                   (size_t)Ss * HD, (size_t)Ss * HD, (size_t)Ss * Ss);
    }

    // 4) V' = V/Z (fp16)
    vscale_kernel<<<(unsigned)(NELEM / 256), 256>>>(V16, Zp, Vop);

    // 5) PV per head (fp16 1-product)
    {
        dim3 grid(1, Ss / 128, BH);
        pv_gemm<<<grid, 256, PV_SMEM>>>(Ep, Vop, X16);
    }

    // 6) Output projection (fp16 1-product) -> fp32 out
    {
        dim3 grid(Dd / 128, MROWS / 128, 1);
        mma_gemm<0, 0, 1, 1><<<grid, 256, SMEMB>>>((const bf16*)X16, nullptr,
                                                   (const bf16*)Wo16, nullptr, bo,
                                                   out, nullptr, nullptr,
                                                   nullptr, nullptr, Dd, Dd, Dd, Dd, 0, 0, 0);
    }
}

// round 17
// speedup vs baseline: 6.1863x; 1.0000x over previous
#include <cuda_runtime.h>
#include <cuda_bf16.h>
#include <cuda_fp16.h>
#include <cstdint>
#include <math.h>

// Problem constants
#define Bb 4
#define Ss 2048
#define Dd 1024
#define Hh 8
#define HD 128
#define BH (Bb*Hh)            // 32 head-slices
#define MROWS (Bb*Ss)         // 8192
#define NELEM ((size_t)MROWS * Dd)      // 8M
#define WELEM ((size_t)Dd * Dd)         // 1M
#define SELEM ((size_t)BH * Ss * Ss)    // 128M

typedef __nv_bfloat16 bf16;
typedef __nv_bfloat162 bf162;

// ---------------------------------------------------------------------------
// Device scratch (allocation-free rule: __device__ globals)
// ---------------------------------------------------------------------------
__device__ __align__(256) bf16 g_iqk_h[2*NELEM], g_iqk_l[2*NELEM];   // [query | key]
__device__ __align__(256) bf16 g_wqk_h[2*WELEM], g_wqk_l[2*WELEM];   // [Wq | Wk]
__device__ __align__(256) float g_bqk[2*Dd];                          // [bq | bk]
__device__ __align__(256) __half g_iv16[NELEM];                       // value fp16
__device__ __align__(256) __half g_Wv16[WELEM];                       // Wv fp16
__device__ __align__(256) __half g_Wo16[WELEM];                       // Wo fp16
__device__ __align__(256) bf16 g_QK_h[2*NELEM], g_QK_l[2*NELEM];     // [Q | K]
__device__ __align__(256) __half g_V16[NELEM];                        // V fp16
__device__ __align__(256) __half g_Vo[NELEM];                         // V' fp16
__device__ __align__(256) __half g_X16[NELEM];                        // X fp16
__device__ __align__(256) __half g_E[SELEM];                          // fp16 E plane
__device__ __align__(256) float g_Mx[(size_t)BH * Ss];
__device__ __align__(256) float g_Z [(size_t)BH * Ss];

// ---------------------------------------------------------------------------
// PTX helpers
// ---------------------------------------------------------------------------
__device__ __forceinline__ void cpa(uint32_t dst, const void* src) {
    asm volatile("cp.async.cg.shared.global [%0], [%1], 16;\n" :: "r"(dst), "l"(src));
}
__device__ __forceinline__ void ldsm4(uint32_t& r0, uint32_t& r1, uint32_t& r2, uint32_t& r3, uint32_t a) {
    asm volatile("ldmatrix.sync.aligned.m8n8.x4.shared.b16 {%0,%1,%2,%3}, [%4];"
                 : "=r"(r0), "=r"(r1), "=r"(r2), "=r"(r3) : "r"(a));
}
__device__ __forceinline__ void ldsm4t(uint32_t& r0, uint32_t& r1, uint32_t& r2, uint32_t& r3, uint32_t a) {
    asm volatile("ldmatrix.sync.aligned.m8n8.x4.trans.shared.b16 {%0,%1,%2,%3}, [%4];"
                 : "=r"(r0), "=r"(r1), "=r"(r2), "=r"(r3) : "r"(a));
}
__device__ __forceinline__ void mma16816(float* c, const uint32_t* a, const uint32_t* b) {
    asm volatile("mma.sync.aligned.m16n8k16.row.col.f32.bf16.bf16.f32 "
                 "{%0,%1,%2,%3},{%4,%5,%6,%7},{%8,%9},{%0,%1,%2,%3};"
                 : "+f"(c[0]), "+f"(c[1]), "+f"(c[2]), "+f"(c[3])
                 : "r"(a[0]), "r"(a[1]), "r"(a[2]), "r"(a[3]), "r"(b[0]), "r"(b[1]));
}
__device__ __forceinline__ void mma16816h(float* c, const uint32_t* a, const uint32_t* b) {
    asm volatile("mma.sync.aligned.m16n8k16.row.col.f32.f16.f16.f32 "
                 "{%0,%1,%2,%3},{%4,%5,%6,%7},{%8,%9},{%0,%1,%2,%3};"
                 : "+f"(c[0]), "+f"(c[1]), "+f"(c[2]), "+f"(c[3])
                 : "r"(a[0]), "r"(a[1]), "r"(a[2]), "r"(a[3]), "r"(b[0]), "r"(b[1]));
}
__device__ __forceinline__ uint32_t pack2(bf16 a, bf16 b) {
    bf162 t(a, b);
    return *reinterpret_cast<uint32_t*>(&t);
}
__device__ __forceinline__ void split2(float v0, float v1, uint32_t& hi, uint32_t& lo) {
    bf16 h0 = __float2bfloat16_rn(v0);
    bf16 h1 = __float2bfloat16_rn(v1);
    bf16 l0 = __float2bfloat16_rn(v0 - __bfloat162float(h0));
    bf16 l1 = __float2bfloat16_rn(v1 - __bfloat162float(h1));
    hi = pack2(h0, h1);
    lo = pack2(l0, l1);
}
__device__ __forceinline__ void atomicMaxF(float* addr, float v) {
    if (v >= 0.f) atomicMax((int*)addr, __float_as_int(v));
    else          atomicMin((unsigned int*)addr, (unsigned int)__float_as_int(v));
}

// ---------------------------------------------------------------------------
// Elementwise prep (fused multi-source kernels)
// ---------------------------------------------------------------------------
__global__ __launch_bounds__(256) void split2_f32(const float4* __restrict__ x0,
                                                  const float4* __restrict__ x1,
                                                  uint2* __restrict__ hi, uint2* __restrict__ lo,
                                                  int n4)
{
    int i = blockIdx.x * 256 + threadIdx.x;
    float4 v = (i < n4) ? x0[i] : x1[i - n4];
    uint32_t h01, l01, h23, l23;
    split2(v.x, v.y, h01, l01);
    split2(v.z, v.w, h23, l23);
    hi[i] = make_uint2(h01, h23);
    lo[i] = make_uint2(l01, l23);
}

__global__ __launch_bounds__(256) void cvt3_f16(const float4* __restrict__ x0, uint2* __restrict__ o0, int n0,
                                                const float4* __restrict__ x1, uint2* __restrict__ o1, int n1,
                                                const float4* __restrict__ x2, uint2* __restrict__ o2)
{
    int i = blockIdx.x * 256 + threadIdx.x;
    const float4* x; uint2* o; int j;
    if (i < n0)           { x = x0; o = o0; j = i; }
    else if (i < n0 + n1) { x = x1; o = o1; j = i - n0; }
    else                  { x = x2; o = o2; j = i - n0 - n1; }
    float4 v = x[j];
    __half2 a = __floats2half2_rn(v.x, v.y);
    __half2 b = __floats2half2_rn(v.z, v.w);
    o[j] = make_uint2(*reinterpret_cast<uint32_t*>(&a), *reinterpret_cast<uint32_t*>(&b));
}

// Re-init Mx/Z every launch (graph-replay safe) + copy bq/bk into pair buffer.
__global__ __launch_bounds__(256) void init_mz(float* __restrict__ Mx, float* __restrict__ Z,
                                               const float* __restrict__ bq, const float* __restrict__ bk,
                                               float* __restrict__ bqk)
{
    int i = blockIdx.x * 256 + threadIdx.x;   // BH*Ss = 65536
    Mx[i] = -1e30f;
    Z[i] = 0.f;
    if (i < Dd)           bqk[i] = bq[i];
    else if (i < 2 * Dd)  bqk[i] = bk[i - Dd];
}

// ---------------------------------------------------------------------------
// MMA GEMM, 3-stage cp.async pipeline, 32KB stages -> 2 blocks/SM everywhere.
// FULL (!LITE): BK=32, combined-plane layout (A rows = [hi 64B | lo 64B]).
// LITE: BK=64, single hi plane per operand.
// EPI:  0 fp32 out, 1 bf16 hi/lo out, 2 colmax->Mx, 3 exp->E + Z, 4 fp16 out.
// FK:   0 bf16 MMA, 1 fp16 MMA (LITE only).
// bias indexed bias[blockIdx.z*ldc + c].
// ---------------------------------------------------------------------------
#define STG 32768

template<int BLAY, int EPI, int LITE, int FK>
__global__ __launch_bounds__(256) void mma_gemm(
    const bf16* __restrict__ Ah, const bf16* __restrict__ Al,
    const bf16* __restrict__ Bh, const bf16* __restrict__ Bl,
    const float* __restrict__ bias,
    float* __restrict__ Cf, bf16* __restrict__ Ch, bf16* __restrict__ Cl,
    float* __restrict__ Mx, float* __restrict__ Zp,
    int K, int lda, int ldb, int ldc,
    size_t sA, size_t sB, size_t sC)
{
    constexpr int BKI = LITE ? 64 : 32;
    extern __shared__ __align__(16) char smem[];
    float* sRed = reinterpret_cast<float*>(smem);
    const uint32_t sbase = (uint32_t)__cvta_generic_to_shared(smem) + 1024;
    const int tid = threadIdx.x, lane = tid & 31, wid = tid >> 5;
    const int wm = wid >> 2, wn = wid & 3;
    const int rowBase = blockIdx.y * 128, colBase = blockIdx.x * 128;
    const bf16* Agh = Ah + (size_t)blockIdx.z * sA;
    const bf16* Agl = Al + (size_t)blockIdx.z * sA;
    const bf16* Bgh = Bh + (size_t)blockIdx.z * sB;
    const bf16* Bgl = Bl + (size_t)blockIdx.z * sB;
    const size_t zC = (size_t)blockIdx.z * sC;
    const size_t zBias = (size_t)blockIdx.z * ldc;

    float acc[4][4][4] = {};

    auto copyStage = [&](int st, int k0) {
        uint32_t aOff = sbase + st * STG;
        uint32_t bOff = aOff + 16384;
        if (LITE) {
            #pragma unroll
            for (int t = 0; t < 4; t++) {
                int idx = tid + t * 256;
                int r = idx >> 3, c = idx & 7;
                cpa(aOff + r * 128 + ((c ^ (r & 7)) << 4),
                    Agh + (size_t)(rowBase + r) * lda + (k0 + c * 8));
            }
            #pragma unroll
            for (int t = 0; t < 4; t++) {
                int idx = tid + t * 256;
                if (BLAY == 0) {
                    int r = idx >> 4, c = idx & 15;
                    cpa(bOff + r * 256 + ((c ^ (r & 7)) << 4),
                        Bgh + (size_t)(k0 + r) * ldb + (colBase + c * 8));
                } else {
                    int r = idx >> 3, c = idx & 7;
                    cpa(bOff + r * 128 + ((c ^ (r & 7)) << 4),
                        Bgh + (size_t)(colBase + r) * ldb + (k0 + c * 8));
                }
            }
        } else {
            #pragma unroll
            for (int t = 0; t < 4; t++) {
                int idx = tid + t * 256;
                int r = idx >> 3, c = idx & 7;
                const bf16* Ag = (c & 4) ? Agl : Agh;
                int kc = c & 3;
                cpa(aOff + r * 128 + ((c ^ (r & 7)) << 4),
                    Ag + (size_t)(rowBase + r) * lda + (k0 + kc * 8));
            }
            if (BLAY == 0) {
                #pragma unroll
                for (int t = 0; t < 4; t++) {
                    int idx = tid + t * 256;
                    int plane = idx >> 9;
                    int rem = idx & 511;
                    int r = rem >> 4, c = rem & 15;
                    const bf16* Bg = plane ? Bgl : Bgh;
                    cpa(bOff + plane * 8192 + r * 256 + ((c ^ (r & 7)) << 4),
                        Bg + (size_t)(k0 + r) * ldb + (colBase + c * 8));
                }
            } else {
                #pragma unroll
                for (int t = 0; t < 4; t++) {
                    int idx = tid + t * 256;
                    int r = idx >> 3, c = idx & 7;
                    const bf16* Bg = (c & 4) ? Bgl : Bgh;
                    int kc = c & 3;
                    cpa(bOff + r * 128 + ((c ^ (r & 7)) << 4),
                        Bg + (size_t)(colBase + r) * ldb + (k0 + kc * 8));
                }
            }
        }
    };

    auto computeStage = [&](int st) {
        uint32_t aOff = sbase + st * STG;
        uint32_t bOff = aOff + 16384;
        constexpr int NKS = LITE ? 4 : 2;
        #pragma unroll
        for (int ks = 0; ks < NKS; ks++) {
            uint32_t af[2][4][4];
            uint32_t bfr[2][4][2];
            #pragma unroll
            for (int mt = 0; mt < 4; mt++) {
                int row = wm * 64 + mt * 16 + (lane & 15);
                int chh = ks * 2 + (lane >> 4);
                ldsm4(af[0][mt][0], af[0][mt][1], af[0][mt][2], af[0][mt][3],
                      aOff + (uint32_t)(row * 128 + ((chh ^ (row & 7)) << 4)));
                if (!LITE) {
                    int chl = chh + 4;
                    ldsm4(af[1][mt][0], af[1][mt][1], af[1][mt][2], af[1][mt][3],
                          aOff + (uint32_t)(row * 128 + ((chl ^ (row & 7)) << 4)));
                }
            }
            #pragma unroll
            for (int i = 0; i < 2; i++) {
                if (BLAY == 0) {
                    int row = ks * 16 + ((lane >> 3) & 1) * 8 + (lane & 7);
                    int ch = wn * 4 + i * 2 + (lane >> 4);
                    uint32_t bd = (uint32_t)(row * 256 + ((ch ^ (row & 7)) << 4));
                    uint32_t r0, r1, r2, r3;
                    ldsm4t(r0, r1, r2, r3, bOff + bd);
                    bfr[0][2*i][0] = r0; bfr[0][2*i][1] = r1; bfr[0][2*i+1][0] = r2; bfr[0][2*i+1][1] = r3;
                    if (!LITE) {
                        ldsm4t(r0, r1, r2, r3, bOff + 8192 + bd);
                        bfr[1][2*i][0] = r0; bfr[1][2*i][1] = r1; bfr[1][2*i+1][0] = r2; bfr[1][2*i+1][1] = r3;
                    }
                } else {
                    int row = wn * 32 + i * 16 + ((lane >> 4) << 3) + (lane & 7);
                    int chh = ks * 2 + ((lane >> 3) & 1);
                    uint32_t r0, r1, r2, r3;
                    ldsm4(r0, r1, r2, r3, bOff + (uint32_t)(row * 128 + ((chh ^ (row & 7)) << 4)));
                    bfr[0][2*i][0] = r0; bfr[0][2*i][1] = r1; bfr[0][2*i+1][0] = r2; bfr[0][2*i+1][1] = r3;
                    if (!LITE) {
                        int chl = chh + 4;
                        ldsm4(r0, r1, r2, r3, bOff + (uint32_t)(row * 128 + ((chl ^ (row & 7)) << 4)));
                        bfr[1][2*i][0] = r0; bfr[1][2*i][1] = r1; bfr[1][2*i+1][0] = r2; bfr[1][2*i+1][1] = r3;
                    }
                }
            }
            #pragma unroll
            for (int mt = 0; mt < 4; mt++)
                #pragma unroll
                for (int nt = 0; nt < 4; nt++) {
                    if (FK) mma16816h(acc[mt][nt], af[0][mt], bfr[0][nt]);
                    else    mma16816(acc[mt][nt], af[0][mt], bfr[0][nt]);
                    if (!LITE) {
                        mma16816(acc[mt][nt], af[0][mt], bfr[1][nt]);
                        mma16816(acc[mt][nt], af[1][mt], bfr[0][nt]);
                    }
                }
        }
    };

    const int nk = K / BKI;
    copyStage(0, 0);
    asm volatile("cp.async.commit_group;" ::: "memory");
    if (nk > 1) {
        copyStage(1, BKI);
        asm volatile("cp.async.commit_group;" ::: "memory");
    }
    if (nk > 2) {
        copyStage(2, 2 * BKI);
        asm volatile("cp.async.commit_group;" ::: "memory");
    }
    int st = 0;
    for (int kt = 0; kt < nk; kt++) {
        int rem = nk - 1 - kt;
        if (rem >= 2)      asm volatile("cp.async.wait_group 2;" ::: "memory");
        else if (rem == 1) asm volatile("cp.async.wait_group 1;" ::: "memory");
        else               asm volatile("cp.async.wait_group 0;" ::: "memory");
        __syncthreads();
        computeStage(st);
        __syncthreads();
        if (kt + 3 < nk) {
            copyStage(st, (kt + 3) * BKI);
            asm volatile("cp.async.commit_group;" ::: "memory");
        }
        if (++st == 3) st = 0;
    }

    if (EPI == 2) {
        if (tid < 128) sRed[tid] = -1e30f;
        __syncthreads();
        #pragma unroll
        for (int nt = 0; nt < 4; nt++) {
            float cm0 = -1e30f, cm1 = -1e30f;
            #pragma unroll
            for (int mt = 0; mt < 4; mt++) {
                cm0 = fmaxf(cm0, fmaxf(acc[mt][nt][0], acc[mt][nt][2]));
                cm1 = fmaxf(cm1, fmaxf(acc[mt][nt][1], acc[mt][nt][3]));
            }
            int ci = wn * 32 + nt * 8 + (lane & 3) * 2;
            atomicMaxF(&sRed[ci], cm0);
            atomicMaxF(&sRed[ci + 1], cm1);
        }
        __syncthreads();
        if (tid < 128)
            atomicMaxF(Mx + (size_t)blockIdx.z * ldc + colBase + tid, sRed[tid]);
    } else if (EPI == 3) {
        if (tid < 128) sRed[tid] = 0.f;
        __syncthreads();
        const float* Mrow = Mx + (size_t)blockIdx.z * ldc + colBase;
        __half* Eo = reinterpret_cast<__half*>(Ch) + zC;
        #pragma unroll
        for (int nt = 0; nt < 4; nt++) {
            int ci = wn * 32 + nt * 8 + (lane & 3) * 2;
            float m0 = Mrow[ci], m1 = Mrow[ci + 1];
            float z0 = 0.f, z1 = 0.f;
            #pragma unroll
            for (int mt = 0; mt < 4; mt++) {
                int r = rowBase + wm * 64 + mt * 16 + (lane >> 2);
                float e00 = __expf(acc[mt][nt][0] - m0);
                float e01 = __expf(acc[mt][nt][1] - m1);
                float e10 = __expf(acc[mt][nt][2] - m0);
                float e11 = __expf(acc[mt][nt][3] - m1);
                z0 += e00 + e10;
                z1 += e01 + e11;
                __half2 p0 = __floats2half2_rn(e00, e01);
                __half2 p1 = __floats2half2_rn(e10, e11);
                *reinterpret_cast<__half2*>(Eo + (size_t)r * ldc + colBase + ci) = p0;
                *reinterpret_cast<__half2*>(Eo + (size_t)(r + 8) * ldc + colBase + ci) = p1;
            }
            #pragma unroll
            for (int off = 16; off >= 4; off >>= 1) {
                z0 += __shfl_down_sync(0xffffffffu, z0, off);
                z1 += __shfl_down_sync(0xffffffffu, z1, off);
            }
            if (lane < 4) {
                atomicAdd(&sRed[ci], z0);
                atomicAdd(&sRed[ci + 1], z1);
            }
        }
        __syncthreads();
        if (tid < 128)
            atomicAdd(Zp + (size_t)blockIdx.z * ldc + colBase + tid, sRed[tid]);
    } else {
        #pragma unroll
        for (int nt = 0; nt < 4; nt++) {
            #pragma unroll
            for (int mt = 0; mt < 4; mt++) {
                int r = rowBase + wm * 64 + mt * 16 + (lane >> 2);
                int c = colBase + wn * 32 + nt * 8 + (lane & 3) * 2;
                float b0 = 0.f, b1 = 0.f;
                if (bias) { b0 = bias[zBias + c]; b1 = bias[zBias + c + 1]; }
                float v00 = acc[mt][nt][0] + b0, v01 = acc[mt][nt][1] + b1;
                float v10 = acc[mt][nt][2] + b0, v11 = acc[mt][nt][3] + b1;
                if (EPI == 0) {
                    *reinterpret_cast<float2*>(Cf + zC + (size_t)r * ldc + c)       = make_float2(v00, v01);
                    *reinterpret_cast<float2*>(Cf + zC + (size_t)(r + 8) * ldc + c) = make_float2(v10, v11);
                } else if (EPI == 4) {
                    __half* Ho = reinterpret_cast<__half*>(Ch);
                    __half2 p0 = __floats2half2_rn(v00, v01);
                    __half2 p1 = __floats2half2_rn(v10, v11);
                    *reinterpret_cast<__half2*>(Ho + zC + (size_t)r * ldc + c)       = p0;
                    *reinterpret_cast<__half2*>(Ho + zC + (size_t)(r + 8) * ldc + c) = p1;
                } else {
                    uint32_t h, l;
                    split2(v00, v01, h, l);
                    *reinterpret_cast<uint32_t*>(Ch + zC + (size_t)r * ldc + c) = h;
                    *reinterpret_cast<uint32_t*>(Cl + zC + (size_t)r * ldc + c) = l;
                    split2(v10, v11, h, l);
                    *reinterpret_cast<uint32_t*>(Ch + zC + (size_t)(r + 8) * ldc + c) = h;
                    *reinterpret_cast<uint32_t*>(Cl + zC + (size_t)(r + 8) * ldc + c) = l;
                }
            }
        }
    }
}

// ---------------------------------------------------------------------------
// PV GEMM fp16, 1 product: X_h = E (fp16) @ V' (fp16 single plane).
// ---------------------------------------------------------------------------
#define PV_STAGE 32768
#define PV_SMEM  98304

__global__ __launch_bounds__(256) void pv_gemm(
    const __half* __restrict__ Ag,
    const __half* __restrict__ Bg,
    __half* __restrict__ Co)
{
    extern __shared__ __align__(16) char smem[];
    const uint32_t sbase = (uint32_t)__cvta_generic_to_shared(smem);
    const int tid = threadIdx.x, lane = tid & 31, wid = tid >> 5;
    const int wm = wid >> 2, wn = wid & 3;
    const int rowBase = blockIdx.y * 128;
    const __half* A = Ag + (size_t)blockIdx.z * Ss * Ss;
    const __half* B = Bg + (size_t)blockIdx.z * Ss * HD;
    const size_t zC = (size_t)blockIdx.z * Ss * HD;

    float acc[4][4][4] = {};

    auto copyStage = [&](int st, int k0) {
        uint32_t aOff = sbase + st * PV_STAGE;
        #pragma unroll
        for (int t = 0; t < 4; t++) {
            int idx = tid + t * 256;
            int r = idx >> 3, c = idx & 7;
            cpa(aOff + r * 128 + ((c ^ (r & 7)) << 4), A + (size_t)(rowBase + r) * Ss + (k0 + c * 8));
        }
        uint32_t bOff = aOff + 16384;
        #pragma unroll
        for (int t = 0; t < 4; t++) {
            int idx = tid + t * 256;
            int r = idx >> 4, c = idx & 15;
            cpa(bOff + r * 256 + ((c ^ (r & 7)) << 4), B + (size_t)(k0 + r) * HD + c * 8);
        }
    };

    auto computeStage = [&](int st) {
        uint32_t aP  = sbase + st * PV_STAGE;
        uint32_t bP  = aP + 16384;
        #pragma unroll
        for (int ks = 0; ks < 4; ks++) {
            uint32_t af[4][4];
            uint32_t bfr[4][2];
            #pragma unroll
            for (int mt = 0; mt < 4; mt++) {
                int row = wm * 64 + mt * 16 + (lane & 15);
                int ch = ks * 2 + (lane >> 4);
                ldsm4(af[mt][0], af[mt][1], af[mt][2], af[mt][3],
                      aP + (uint32_t)(row * 128 + ((ch ^ (row & 7)) << 4)));
            }
            #pragma unroll
            for (int i = 0; i < 2; i++) {
                int row = ks * 16 + ((lane >> 3) & 1) * 8 + (lane & 7);
                int ch = wn * 4 + i * 2 + (lane >> 4);
                uint32_t bd = (uint32_t)(row * 256 + ((ch ^ (row & 7)) << 4));
                uint32_t r0, r1, r2, r3;
                ldsm4t(r0, r1, r2, r3, bP + bd);
                bfr[2*i][0] = r0; bfr[2*i][1] = r1; bfr[2*i+1][0] = r2; bfr[2*i+1][1] = r3;
            }
            #pragma unroll
            for (int mt = 0; mt < 4; mt++)
                #pragma unroll
                for (int nt = 0; nt < 4; nt++)
                    mma16816h(acc[mt][nt], af[mt], bfr[nt]);
        }
    };

    const int nk = Ss >> 6;   // 32
    copyStage(0, 0);
    asm volatile("cp.async.commit_group;" ::: "memory");
    copyStage(1, 64);
    asm volatile("cp.async.commit_group;" ::: "memory");
    int st = 0;
    for (int kt = 0; kt < nk; kt++) {
        if (kt + 2 < nk) {
            int pst = st + 2; if (pst >= 3) pst -= 3;
            copyStage(pst, (kt + 2) * 64);
            asm volatile("cp.async.commit_group;" ::: "memory");
            asm volatile("cp.async.wait_group 2;" ::: "memory");
        } else if (kt + 1 < nk) {
            asm volatile("cp.async.wait_group 1;" ::: "memory");
        } else {
            asm volatile("cp.async.wait_group 0;" ::: "memory");
        }
        __syncthreads();
        computeStage(st);
        __syncthreads();
        if (++st == 3) st = 0;
    }

    #pragma unroll
    for (int mt = 0; mt < 4; mt++) {
        #pragma unroll
        for (int nt = 0; nt < 4; nt++) {
            int r = rowBase + wm * 64 + mt * 16 + (lane >> 2);
            int c = wn * 32 + nt * 8 + (lane & 3) * 2;
            __half2 p0 = __floats2half2_rn(acc[mt][nt][0], acc[mt][nt][1]);
            __half2 p1 = __floats2half2_rn(acc[mt][nt][2], acc[mt][nt][3]);
            *reinterpret_cast<__half2*>(Co + zC + (size_t)r * HD + c) = p0;
            *reinterpret_cast<__half2*>(Co + zC + (size_t)(r + 8) * HD + c) = p1;
        }
    }
}

// ---------------------------------------------------------------------------
// V'[k,d] = V[k,d]/Z[k] -> fp16 single plane
// ---------------------------------------------------------------------------
__global__ __launch_bounds__(256) void vscale_kernel(const __half* __restrict__ V16,
                                                     const float* __restrict__ Z,
                                                     __half* __restrict__ Vo)
{
    size_t i = (size_t)blockIdx.x * 256 + threadIdx.x;
    size_t kz = i >> 7;
    float inv = __fdividef(1.0f, Z[kz]);
    Vo[i] = __float2half_rn(__half2float(V16[i]) * inv);
}

// ---------------------------------------------------------------------------
// Launch (single stream, no statics, no events)
// ---------------------------------------------------------------------------
extern "C" void kernel_launch(void* const* d_in, const int* in_sizes, int n_in,
                              void* d_out, int out_size)
{
    const float* query = (const float*)d_in[0];
    const float* key   = (const float*)d_in[1];
    const float* value = (const float*)d_in[2];
    const float* Wq    = (const float*)d_in[3];
    const float* bq    = (const float*)d_in[4];
    const float* Wk    = (const float*)d_in[5];
    const float* bk    = (const float*)d_in[6];
    const float* Wv    = (const float*)d_in[7];
    const float* bv    = (const float*)d_in[8];
    const float* Wo    = (const float*)d_in[9];
    const float* bo    = (const float*)d_in[10];
    float* out = (float*)d_out;

    #define SYM(p, s) do { void* tmp_; cudaGetSymbolAddress(&tmp_, s); p = (decltype(p))tmp_; } while (0)
    bf16 *iqkh, *iqkl, *wqkh, *wqkl, *QKh, *QKl;
    __half *iv16, *Wv16, *Wo16, *V16, *Ep, *Vop, *X16;
    float *bqk, *Mxp, *Zp;
    SYM(iqkh, g_iqk_h); SYM(iqkl, g_iqk_l);
    SYM(wqkh, g_wqk_h); SYM(wqkl, g_wqk_l);
    SYM(bqk, g_bqk);
    SYM(iv16, g_iv16); SYM(Wv16, g_Wv16); SYM(Wo16, g_Wo16);
    SYM(QKh, g_QK_h); SYM(QKl, g_QK_l);
    SYM(V16, g_V16); SYM(Vop, g_Vo); SYM(X16, g_X16);
    SYM(Ep, g_E); SYM(Mxp, g_Mx); SYM(Zp, g_Z);
    #undef SYM
    bf16 *Qh = QKh, *Ql = QKl, *Kh = QKh + NELEM, *Kl = QKl + NELEM;

    const int SMEMB = 1024 + 3 * STG;   // 99328 for all GEMM variants
    cudaFuncSetAttribute(mma_gemm<0, 1, 0, 0>, cudaFuncAttributeMaxDynamicSharedMemorySize, SMEMB);
    cudaFuncSetAttribute(mma_gemm<1, 2, 1, 0>, cudaFuncAttributeMaxDynamicSharedMemorySize, SMEMB);
    cudaFuncSetAttribute(mma_gemm<1, 3, 0, 0>, cudaFuncAttributeMaxDynamicSharedMemorySize, SMEMB);
    cudaFuncSetAttribute(mma_gemm<0, 0, 1, 1>, cudaFuncAttributeMaxDynamicSharedMemorySize, SMEMB);
    cudaFuncSetAttribute(mma_gemm<0, 4, 1, 1>, cudaFuncAttributeMaxDynamicSharedMemorySize, SMEMB);
    cudaFuncSetAttribute(pv_gemm, cudaFuncAttributeMaxDynamicSharedMemorySize, PV_SMEM);

    // 0) Re-init Mx/Z + copy biases into pair buffer (one kernel)
    init_mz<<<(BH * Ss) / 256, 256>>>(Mxp, Zp, bq, bk, bqk);

    // 1) Fused prep
    int n4i = (int)(NELEM / 4), n4w = (int)(WELEM / 4);
    split2_f32<<<2 * n4i / 256, 256>>>((const float4*)query, (const float4*)key,
                                       (uint2*)iqkh, (uint2*)iqkl, n4i);
    split2_f32<<<2 * n4w / 256, 256>>>((const float4*)Wq, (const float4*)Wk,
                                       (uint2*)wqkh, (uint2*)wqkl, n4w);
    cvt3_f16<<<(n4i + 2 * n4w) / 256, 256>>>((const float4*)value, (uint2*)iv16, n4i,
                                             (const float4*)Wv, (uint2*)Wv16, n4w,
                                             (const float4*)Wo, (uint2*)Wo16);

    // 2) Q+K projections batched (bf16x3, grid.z=2) + V projection (fp16 1-product)
    {
        dim3 gridQK(Dd / 128, MROWS / 128, 2);
        mma_gemm<0, 1, 0, 0><<<gridQK, 256, SMEMB>>>(iqkh, iqkl, wqkh, wqkl, bqk,
                                                     nullptr, QKh, QKl,
                                                     nullptr, nullptr, Dd, Dd, Dd, Dd,
                                                     NELEM, WELEM, NELEM);
        dim3 gridV(Dd / 128, MROWS / 128, 1);
        mma_gemm<0, 4, 1, 1><<<gridV, 256, SMEMB>>>((const bf16*)iv16, nullptr,
                                                    (const bf16*)Wv16, nullptr, bv,
                                                    nullptr, (bf16*)V16, nullptr,
                                                    nullptr, nullptr, Dd, Dd, Dd, Dd, 0, 0, 0);
    }

    // 3a) Scores max pass: Mx = colmax(Q_h @ K_h^T)
    {
        dim3 grid(Ss / 128, Ss / 128, BH);
        mma_gemm<1, 2, 1, 0><<<grid, 256, SMEMB>>>(Qh, nullptr, Kh, nullptr, nullptr,
                                                   nullptr, nullptr, nullptr, Mxp, nullptr,
                                                   HD, HD, HD, Ss,
                                                   (size_t)Ss * HD, (size_t)Ss * HD, 0);
    }

    // 3b) Scores full pass (3-product, BK=32) + fused exp + Z
    {
        dim3 grid(Ss / 128, Ss / 128, BH);
        mma_gemm<1, 3, 0, 0><<<grid, 256, SMEMB>>>(Qh, Ql, Kh, Kl, nullptr,
                                                   nullptr, (bf16*)Ep, nullptr, Mxp, Zp,
                                                   HD, HD, HD, Ss,
                                                   (size_t)Ss * HD, (size_t)Ss * HD, (size_t)Ss * Ss);
    }

    // 4) V' = V/Z (fp16)
    vscale_kernel<<<(unsigned)(NELEM / 256), 256>>>(V16, Zp, Vop);

    // 5) PV per head (fp16 1-product)
    {
        dim3 grid(1, Ss / 128, BH);
        pv_gemm<<<grid, 256, PV_SMEM>>>(Ep, Vop, X16);
    }

    // 6) Output projection (fp16 1-product) -> fp32 out
    {
        dim3 grid(Dd / 128, MROWS / 128, 1);
        mma_gemm<0, 0, 1, 1><<<grid, 256, SMEMB>>>((const bf16*)X16, nullptr,
                                                   (const bf16*)Wo16, nullptr, bo,
                                                   out, nullptr, nullptr,
                                                   nullptr, nullptr, Dd, Dd, Dd, Dd, 0, 0, 0);
    }
}